// round 2
// baseline (speedup 1.0000x reference)
#include <cuda_runtime.h>
#include <math.h>

#define NN 50000
#define DD 256
#define EE 800000
#define NCLS 47
#define NLAYER 3

// ---------------- device scratch (no allocations allowed) ----------------
__device__ float g_x[NN * DD];   // current node features
__device__ float g_z[NN * DD];   // scatter accumulator
__device__ float g_p[NN * DD];   // prop / o / post-h1
__device__ float g_h[NN * DD];   // h
__device__ float g_t[NN * DD];   // t
__device__ float g_cnt[NN];      // in-degree -> 1/max(cnt,1)

static __device__ __forceinline__ float4 ld4(const float* p) { return *(const float4*)p; }
static __device__ __forceinline__ void st4(float* p, float4 v) { *(float4*)p = v; }

// ---------------- degree count / invert ----------------
__global__ void count_kernel(const int* __restrict__ dst, float* __restrict__ cnt) {
    int e = blockIdx.x * 256 + threadIdx.x;
    if (e < EE) atomicAdd(&cnt[dst[e]], 1.0f);
}

__global__ void inv_kernel(float* __restrict__ cnt) {
    int i = blockIdx.x * 256 + threadIdx.x;
    if (i < NN) cnt[i] = 1.0f / fmaxf(cnt[i], 1.0f);
}

// ---------------- scatter-add of x[src] rows into z[dst] ----------------
// 4 edges per 256-thread block; 64 threads (float4 each) per edge row.
__global__ void scatter_kernel(const float* __restrict__ x,
                               const int* __restrict__ src,
                               const int* __restrict__ dst,
                               float* __restrict__ z) {
    int e = blockIdx.x * 4 + (threadIdx.x >> 6);
    if (e >= EE) return;
    int s = src[e];
    int d = dst[e];
    int c = (threadIdx.x & 63) * 4;
    float4 v = ld4(x + (size_t)s * DD + c);
    float* zp = z + (size_t)d * DD + c;
    atomicAdd(zp + 0, v.x);
    atomicAdd(zp + 1, v.y);
    atomicAdd(zp + 2, v.z);
    atomicAdd(zp + 3, v.w);
}

// ---------------- SGEMM: [M,K] x [K,256] -> [M,256], fused epilogues ----------------
// BM=128, BN=128, BK=8, 256 threads, 8x8 per-thread tile.
// CONCAT: A is virtual [x | z*inv] (K=512), B is virtual [B ; B2].
// epi: 0 = +bias (+bias2), 1 = gamma*(relu(acc+bias)*bnscale)+beta, 2 = acc+bias+C (residual in-place)
template <bool CONCAT>
__global__ void __launch_bounds__(256, 2)
gemm_kernel(const float* __restrict__ A, const float* __restrict__ A2,
            const float* __restrict__ inv,
            const float* __restrict__ B, const float* __restrict__ B2,
            const float* __restrict__ bias, const float* __restrict__ bias2,
            const float* __restrict__ gamma, const float* __restrict__ beta,
            float bnscale, int epi, float* __restrict__ C, int M) {
    const int K = CONCAT ? 512 : 256;
    __shared__ float As[8][128];
    __shared__ float Bs[8][128];

    int tid = threadIdx.x;
    int tx = tid & 15, ty = tid >> 4;
    int bm0 = blockIdx.x * 128;
    int col0 = blockIdx.y * 128;

    int ar = tid >> 1;          // 0..127 (row in A tile)
    int ak = (tid & 1) * 4;     // 0 or 4
    int gr = bm0 + ar;
    int bk = tid >> 5;          // 0..7 (k row in B tile)
    int bc = (tid & 31) * 4;    // 0..124

    float iv = 1.0f;
    if (CONCAT && gr < M) iv = inv[gr];

    float acc[8][8];
#pragma unroll
    for (int i = 0; i < 8; i++)
#pragma unroll
        for (int j = 0; j < 8; j++) acc[i][j] = 0.0f;

    auto loadA = [&](int k0) -> float4 {
        if (gr >= M) return make_float4(0.f, 0.f, 0.f, 0.f);
        int k = k0 + ak;
        if (CONCAT && k >= 256) {
            float4 v = ld4(A2 + (size_t)gr * 256 + (k - 256));
            v.x *= iv; v.y *= iv; v.z *= iv; v.w *= iv;
            return v;
        }
        return ld4(A + (size_t)gr * 256 + k);
    };
    auto loadB = [&](int k0) -> float4 {
        int k = k0 + bk;
        const float* Bp = (CONCAT && k >= 256) ? (B2 + (size_t)(k - 256) * 256)
                                               : (B + (size_t)k * 256);
        return ld4(Bp + col0 + bc);
    };

    float4 pa = loadA(0);
    float4 pb = loadB(0);

    for (int k0 = 0; k0 < K; k0 += 8) {
        As[ak + 0][ar] = pa.x;
        As[ak + 1][ar] = pa.y;
        As[ak + 2][ar] = pa.z;
        As[ak + 3][ar] = pa.w;
        st4(&Bs[bk][bc], pb);
        __syncthreads();
        if (k0 + 8 < K) { pa = loadA(k0 + 8); pb = loadB(k0 + 8); }
#pragma unroll
        for (int kk = 0; kk < 8; kk++) {
            float4 a0 = ld4(&As[kk][ty * 4]);
            float4 a1 = ld4(&As[kk][64 + ty * 4]);
            float4 b0 = ld4(&Bs[kk][tx * 4]);
            float4 b1 = ld4(&Bs[kk][64 + tx * 4]);
            float am[8] = {a0.x, a0.y, a0.z, a0.w, a1.x, a1.y, a1.z, a1.w};
            float bn[8] = {b0.x, b0.y, b0.z, b0.w, b1.x, b1.y, b1.z, b1.w};
#pragma unroll
            for (int i = 0; i < 8; i++)
#pragma unroll
                for (int j = 0; j < 8; j++) acc[i][j] = fmaf(am[i], bn[j], acc[i][j]);
        }
        __syncthreads();
    }

    // ---- epilogue ----
    int c0 = col0 + tx * 4;
    int c1 = col0 + 64 + tx * 4;
    float4 add0 = ld4(bias + c0);
    float4 add1 = ld4(bias + c1);
    if (bias2) {
        float4 t0 = ld4(bias2 + c0), t1 = ld4(bias2 + c1);
        add0.x += t0.x; add0.y += t0.y; add0.z += t0.z; add0.w += t0.w;
        add1.x += t1.x; add1.y += t1.y; add1.z += t1.z; add1.w += t1.w;
    }
    float4 g0 = make_float4(0, 0, 0, 0), g1 = g0, be0 = g0, be1 = g0;
    if (epi == 1) {
        g0 = ld4(gamma + c0); g1 = ld4(gamma + c1);
        be0 = ld4(beta + c0); be1 = ld4(beta + c1);
    }

#pragma unroll
    for (int mi = 0; mi < 8; mi++) {
        int r = bm0 + ((mi < 4) ? (ty * 4 + mi) : (64 + ty * 4 + mi - 4));
        if (r >= M) continue;
        float4 v0 = make_float4(acc[mi][0] + add0.x, acc[mi][1] + add0.y,
                                acc[mi][2] + add0.z, acc[mi][3] + add0.w);
        float4 v1 = make_float4(acc[mi][4] + add1.x, acc[mi][5] + add1.y,
                                acc[mi][6] + add1.z, acc[mi][7] + add1.w);
        if (epi == 1) {
            v0.x = fmaf(g0.x, fmaxf(v0.x, 0.f) * bnscale, be0.x);
            v0.y = fmaf(g0.y, fmaxf(v0.y, 0.f) * bnscale, be0.y);
            v0.z = fmaf(g0.z, fmaxf(v0.z, 0.f) * bnscale, be0.z);
            v0.w = fmaf(g0.w, fmaxf(v0.w, 0.f) * bnscale, be0.w);
            v1.x = fmaf(g1.x, fmaxf(v1.x, 0.f) * bnscale, be1.x);
            v1.y = fmaf(g1.y, fmaxf(v1.y, 0.f) * bnscale, be1.y);
            v1.z = fmaf(g1.z, fmaxf(v1.z, 0.f) * bnscale, be1.z);
            v1.w = fmaf(g1.w, fmaxf(v1.w, 0.f) * bnscale, be1.w);
        } else if (epi == 2) {
            float4 p0 = ld4(C + (size_t)r * 256 + c0);
            float4 p1 = ld4(C + (size_t)r * 256 + c1);
            v0.x += p0.x; v0.y += p0.y; v0.z += p0.z; v0.w += p0.w;
            v1.x += p1.x; v1.y += p1.y; v1.z += p1.z; v1.w += p1.w;
        }
        st4(C + (size_t)r * 256 + c0, v0);
        st4(C + (size_t)r * 256 + c1, v1);
    }
}

// ---------------- row-wise L2 normalize + relu ----------------
__global__ void norm_relu_kernel(const float* __restrict__ o, float* __restrict__ xout) {
    int w = (blockIdx.x * blockDim.x + threadIdx.x) >> 5;
    int lane = threadIdx.x & 31;
    if (w >= NN) return;
    const float* row = o + (size_t)w * DD;
    float v[8];
    float s = 0.f;
#pragma unroll
    for (int j = 0; j < 8; j++) {
        v[j] = row[lane + j * 32];
        s = fmaf(v[j], v[j], s);
    }
#pragma unroll
    for (int off = 16; off > 0; off >>= 1) s += __shfl_xor_sync(0xffffffffu, s, off);
    float sc = 1.f / fmaxf(sqrtf(s), 1e-12f);
    float* out = xout + (size_t)w * DD;
#pragma unroll
    for (int j = 0; j < 8; j++) out[lane + j * 32] = fmaxf(v[j] * sc, 0.f);
}

// ---------------- head: logits [256->47] + log_softmax ----------------
__global__ void head_kernel(const float* __restrict__ h, const float* __restrict__ W2,
                            const float* __restrict__ b2, float* __restrict__ out) {
    __shared__ float sW[256 * NCLS];
    __shared__ float sb[NCLS];
    int tid = threadIdx.x;
    for (int i = tid; i < 256 * NCLS; i += 256) sW[i] = W2[i];
    if (tid < NCLS) sb[tid] = b2[tid];
    __syncthreads();

    int wid = tid >> 5, lane = tid & 31;
    int r = blockIdx.x * 8 + wid;
    if (r >= NN) return;

    // stage row into registers: lane holds h[r, lane*8 + e]
    const float4* rp = (const float4*)(h + (size_t)r * DD);
    float4 q0 = rp[lane * 2];
    float4 q1 = rp[lane * 2 + 1];
    float hreg[8] = {q0.x, q0.y, q0.z, q0.w, q1.x, q1.y, q1.z, q1.w};

    int c0 = lane;
    int c1 = lane + 32;
    int c1m = (c1 < NCLS) ? c1 : (NCLS - 1);
    float acc0 = sb[c0];
    float acc1 = sb[c1m];
#pragma unroll
    for (int e = 0; e < 8; e++) {
        for (int l = 0; l < 32; l++) {
            float hv = __shfl_sync(0xffffffffu, hreg[e], l);
            int k = l * 8 + e;
            acc0 = fmaf(hv, sW[k * NCLS + c0], acc0);
            acc1 = fmaf(hv, sW[k * NCLS + c1m], acc1);
        }
    }
    // log-softmax over 47 values
    float m = fmaxf(acc0, (c1 < NCLS) ? acc1 : -3.4e38f);
#pragma unroll
    for (int off = 16; off > 0; off >>= 1) m = fmaxf(m, __shfl_xor_sync(0xffffffffu, m, off));
    float es = expf(acc0 - m) + ((c1 < NCLS) ? expf(acc1 - m) : 0.f);
#pragma unroll
    for (int off = 16; off > 0; off >>= 1) es += __shfl_xor_sync(0xffffffffu, es, off);
    float lse = m + logf(es);
    out[(size_t)r * NCLS + c0] = acc0 - lse;
    if (c1 < NCLS) out[(size_t)r * NCLS + c1] = acc1 - lse;
}

// ---------------- host orchestration ----------------
static void launch_gemm(const float* A, const float* B, const float* bias,
                        const float* bias2, const float* gamma, const float* beta,
                        float bnscale, int epi, float* C) {
    dim3 grid((NN + 127) / 128, 2);
    gemm_kernel<false><<<grid, 256>>>(A, nullptr, nullptr, B, nullptr, bias, bias2,
                                      gamma, beta, bnscale, epi, C, NN);
}

static void launch_gemm_concat(const float* A, const float* A2, const float* inv,
                               const float* B, const float* B2, const float* bias,
                               const float* bias2, float* C) {
    dim3 grid((NN + 127) / 128, 2);
    gemm_kernel<true><<<grid, 256>>>(A, A2, inv, B, B2, bias, bias2,
                                     nullptr, nullptr, 0.f, 0, C, NN);
}

extern "C" void kernel_launch(void* const* d_in, const int* in_sizes, int n_in,
                              void* d_out, int out_size) {
    const float* x_in      = (const float*)d_in[0];
    const int* ei          = (const int*)d_in[1];   // int32! (JAX x64 disabled)
    const float* lin_l_W   = (const float*)d_in[2];
    const float* lin_l_b   = (const float*)d_in[3];
    const float* lin_r_W   = (const float*)d_in[4];
    const float* lin_r_b   = (const float*)d_in[5];
    const float* mlp_W1    = (const float*)d_in[6];
    const float* mlp_b1    = (const float*)d_in[7];
    const float* blk_Wa    = (const float*)d_in[8];
    const float* blk_ba    = (const float*)d_in[9];
    const float* blk_gamma = (const float*)d_in[10];
    const float* blk_beta  = (const float*)d_in[11];
    const float* blk_Wb    = (const float*)d_in[12];
    const float* blk_bb    = (const float*)d_in[13];
    const float* mlp_W2    = (const float*)d_in[14];
    const float* mlp_b2    = (const float*)d_in[15];
    const float* post_W1   = (const float*)d_in[16];
    const float* post_b1   = (const float*)d_in[17];
    const float* post_W2   = (const float*)d_in[18];
    const float* post_b2   = (const float*)d_in[19];
    float* out = (float*)d_out;

    float *xp, *zp, *pp, *hp, *tp, *cp;
    cudaGetSymbolAddress((void**)&xp, g_x);
    cudaGetSymbolAddress((void**)&zp, g_z);
    cudaGetSymbolAddress((void**)&pp, g_p);
    cudaGetSymbolAddress((void**)&hp, g_h);
    cudaGetSymbolAddress((void**)&tp, g_t);
    cudaGetSymbolAddress((void**)&cp, g_cnt);

    const float bnscale = rsqrtf(1.0f + 1e-5f);
    const int* src = ei;
    const int* dst = ei + EE;

    // x <- input; degrees
    cudaMemcpyAsync(xp, x_in, (size_t)NN * DD * sizeof(float), cudaMemcpyDeviceToDevice);
    cudaMemsetAsync(cp, 0, NN * sizeof(float));
    count_kernel<<<(EE + 255) / 256, 256>>>(dst, cp);
    inv_kernel<<<(NN + 255) / 256, 256>>>(cp);

    for (int i = 0; i < NLAYER; i++) {
        // scatter-mean accumulator
        cudaMemsetAsync(zp, 0, (size_t)NN * DD * sizeof(float));
        scatter_kernel<<<(EE + 3) / 4, 256>>>(xp, src, dst, zp);

        // prop = x@Wl + bl + (z/cnt)@Wr + br   (fused K=512 GEMM)
        launch_gemm_concat(xp, zp, cp,
                           lin_l_W + (size_t)i * 65536, lin_r_W + (size_t)i * 65536,
                           lin_l_b + (size_t)i * 256, lin_r_b + (size_t)i * 256, pp);

        // h = prop@W1 + b1
        launch_gemm(pp, mlp_W1 + (size_t)i * 65536, mlp_b1 + (size_t)i * 256,
                    nullptr, nullptr, nullptr, 0.f, 0, hp);

        for (int j = 0; j < 2; j++) {
            size_t wo = ((size_t)i * 2 + j) * 65536;
            size_t bo = ((size_t)i * 2 + j) * 256;
            // t = gamma*(relu(h@Wa+ba)*bnscale)+beta
            launch_gemm(hp, blk_Wa + wo, blk_ba + bo, nullptr,
                        blk_gamma + bo, blk_beta + bo, bnscale, 1, tp);
            // h = h + t@Wb + bb
            launch_gemm(tp, blk_Wb + wo, blk_bb + bo, nullptr,
                        nullptr, nullptr, 0.f, 2, hp);
        }

        // o = h@W2 + b2 ; x = relu(normalize(o))
        launch_gemm(hp, mlp_W2 + (size_t)i * 65536, mlp_b2 + (size_t)i * 256,
                    nullptr, nullptr, nullptr, 0.f, 0, pp);
        norm_relu_kernel<<<(NN * 32 + 255) / 256, 256>>>(pp, xp);
    }

    // post MLP + log_softmax
    launch_gemm(xp, post_W1, post_b1, nullptr, nullptr, nullptr, 0.f, 0, pp);
    head_kernel<<<(NN + 7) / 8, 256>>>(pp, post_W2, post_b2, out);
}

// round 4
// speedup vs baseline: 1.4705x; 1.4705x over previous
#include <cuda_runtime.h>
#include <cuda_bf16.h>
#include <math.h>

#define NN 50000
#define DD 256
#define EE 800000
#define NCLS 47
#define NLAYER 3
#define NB ((NN + 127) / 128)          // 391 M-tiles

// SW128 swizzle: XOR 16B-column with row%8 (byte form)
#define SWZ(x) ((x) ^ (((x) >> 3) & 0x70))

// smem byte offsets (dynamic smem)
#define OFF_AHI 0            // 16KB  (128 rows x 64 k x bf16)
#define OFF_ALO 16384        // 16KB
#define OFF_BHI 32768        // 16KB  (128 n x 64 k x bf16)
#define OFF_BLO 49152        // 16KB
#define OFF_BIAS 65536       // 256 f
#define OFF_GAMMA 66560      // 256 f
#define OFF_BETA 67584       // 256 f
#define SMEM_SZ 68608

// ---------------- device scratch ----------------
__device__ float g_x[NN * DD];
__device__ float g_z[NN * DD];
__device__ float g_p[NN * DD];
__device__ float g_h[NN * DD];
__device__ float g_t[NN * DD];
__device__ float g_cnt[NN];
// prepped weights: 100 chunks x 32KB each (hi and lo), swizzled [N][Kchunk] images
__device__ uint4 g_whi4[100 * 2048];
__device__ uint4 g_wlo4[100 * 2048];

static __device__ __forceinline__ float4 ld4(const float* p) { return *(const float4*)p; }
static __device__ __forceinline__ void st4(float* p, float4 v) { *(float4*)p = v; }

static __device__ __forceinline__ unsigned smem_u32(const void* p) {
    unsigned a;
    asm("{ .reg .u64 t; cvta.to.shared.u64 t, %1; cvt.u32.u64 %0, t; }" : "=r"(a) : "l"(p));
    return a;
}
static __device__ __forceinline__ void ldsm4(unsigned r[4], unsigned addr) {
    asm volatile("ldmatrix.sync.aligned.m8n8.x4.shared.b16 {%0,%1,%2,%3}, [%4];"
                 : "=r"(r[0]), "=r"(r[1]), "=r"(r[2]), "=r"(r[3]) : "r"(addr));
}
static __device__ __forceinline__ void mma16816(float d[4], const unsigned a[4],
                                                unsigned b0, unsigned b1) {
    asm volatile(
        "mma.sync.aligned.m16n8k16.row.col.f32.bf16.bf16.f32 "
        "{%0,%1,%2,%3}, {%4,%5,%6,%7}, {%8,%9}, {%0,%1,%2,%3};"
        : "+f"(d[0]), "+f"(d[1]), "+f"(d[2]), "+f"(d[3])
        : "r"(a[0]), "r"(a[1]), "r"(a[2]), "r"(a[3]), "r"(b0), "r"(b1));
}

// ---------------- degree count / invert ----------------
__global__ void count_kernel(const int* __restrict__ dst, float* __restrict__ cnt) {
    int e = blockIdx.x * 256 + threadIdx.x;
    if (e < EE) atomicAdd(&cnt[dst[e]], 1.0f);
}
__global__ void inv_kernel(float* __restrict__ cnt) {
    int i = blockIdx.x * 256 + threadIdx.x;
    if (i < NN) cnt[i] = 1.0f / fmaxf(cnt[i], 1.0f);
}

// ---------------- scatter-add of x[src] rows into z[dst] ----------------
__global__ void scatter_kernel(const float* __restrict__ x, const int* __restrict__ src,
                               const int* __restrict__ dst, float* __restrict__ z) {
    int e = blockIdx.x * 4 + (threadIdx.x >> 6);
    if (e >= EE) return;
    int s = src[e];
    int d = dst[e];
    int c = (threadIdx.x & 63) * 4;
    float4 v = ld4(x + (size_t)s * DD + c);
    float* zp = z + (size_t)d * DD + c;
    atomicAdd(zp + 0, v.x);
    atomicAdd(zp + 1, v.y);
    atomicAdd(zp + 2, v.z);
    atomicAdd(zp + 3, v.w);
}

// ---------------- weight prep ----------------
// W: nmat concatenated [K=256][256] matrices. For matrix t, element (k,n):
// out chunk = chunk_start + t*chunk_stride + (k>>6); within chunk: SWZ(n*128 + (k&63)*2).
__global__ void prep_w(const float* __restrict__ W, int chunk_start, int chunk_stride,
                       unsigned short* __restrict__ dhi, unsigned short* __restrict__ dlo) {
    int idx = blockIdx.x * 256 + threadIdx.x;
    int t = idx >> 16;
    int rem = idx & 65535;
    int n = rem & 255, k = rem >> 8;
    float v = W[(size_t)idx];  // W[t][k][n] flat
    __nv_bfloat16 h = __float2bfloat16(v);
    __nv_bfloat16 l = __float2bfloat16(v - __bfloat162float(h));
    unsigned chunk = chunk_start + t * chunk_stride + (k >> 6);
    unsigned off = chunk * 32768u + SWZ((unsigned)(n * 128 + (k & 63) * 2));
    dhi[off >> 1] = __bfloat16_as_ushort(h);
    dlo[off >> 1] = __bfloat16_as_ushort(l);
}

// ---------------- HMMA GEMM: [M,KTOT] x [KTOT,256] -> [M,256] ----------------
// 3-term bf16 split (hi*hi + hi*lo + lo*hi), fp32 accumulate.
// EPI: 0 = +bias(+bias2)   1 = gamma*(relu(+bias)*bnscale)+beta   2 = +bias + C (residual)
template <int KTOT, int EPI>
__global__ void __launch_bounds__(256, 2)
mma_gemm(const float* __restrict__ A, const float* __restrict__ A2,
         const float* __restrict__ inv, const uint4* __restrict__ Whi,
         const uint4* __restrict__ Wlo, const float* __restrict__ bias,
         const float* __restrict__ bias2, const float* __restrict__ gamma,
         const float* __restrict__ beta, float bnscale, float* __restrict__ C, int M) {
    extern __shared__ char smem[];
    const unsigned sb = smem_u32(smem);
    const int tid = threadIdx.x, wid = tid >> 5, lane = tid & 31;
    const int bm0 = blockIdx.x * 128;
    const int col0 = blockIdx.y * 128;
    constexpr int NCHUNK = KTOT / 64;

    // epilogue params
    {
        float bv = bias[tid];
        if (bias2) bv += bias2[tid];
        ((float*)(smem + OFF_BIAS))[tid] = bv;
        if (EPI == 1) {
            ((float*)(smem + OFF_GAMMA))[tid] = gamma[tid];
            ((float*)(smem + OFF_BETA))[tid] = beta[tid];
        }
    }

    const int wm0 = (wid >> 1) * 32;   // warp M offset in tile
    const int wn0 = (wid & 1) * 64;    // warp N offset in tile
    const int lrow = lane & 15;
    const int lk = (lane >> 4) * 8;

    float acc[2][8][4];
#pragma unroll
    for (int a = 0; a < 2; a++)
#pragma unroll
        for (int b = 0; b < 8; b++)
#pragma unroll
            for (int c = 0; c < 4; c++) acc[a][b][c] = 0.f;

    for (int c = 0; c < NCHUNK; c++) {
        __syncthreads();
        // ---- A producer: LDG fp32, bf16 hi/lo split, swizzled STS ----
#pragma unroll
        for (int i = 0; i < 8; i++) {
            int idx = tid + i * 256;
            int r = idx >> 4, kq = idx & 15;
            int grow = bm0 + r;
            int gk = c * 64 + kq * 4;
            float4 v = make_float4(0.f, 0.f, 0.f, 0.f);
            if (grow < M) {
                if (KTOT == 512 && gk >= 256) {
                    v = ld4(A2 + (size_t)grow * 256 + (gk - 256));
                    float iv = inv[grow];
                    v.x *= iv; v.y *= iv; v.z *= iv; v.w *= iv;
                } else {
                    v = ld4(A + (size_t)grow * 256 + gk);
                }
            }
            unsigned hx = __bfloat16_as_ushort(__float2bfloat16(v.x));
            unsigned hy = __bfloat16_as_ushort(__float2bfloat16(v.y));
            unsigned hz = __bfloat16_as_ushort(__float2bfloat16(v.z));
            unsigned hw = __bfloat16_as_ushort(__float2bfloat16(v.w));
            unsigned lx = __bfloat16_as_ushort(__float2bfloat16(v.x - __bfloat162float(__ushort_as_bfloat16(hx))));
            unsigned ly = __bfloat16_as_ushort(__float2bfloat16(v.y - __bfloat162float(__ushort_as_bfloat16(hy))));
            unsigned lz = __bfloat16_as_ushort(__float2bfloat16(v.z - __bfloat162float(__ushort_as_bfloat16(hz))));
            unsigned lw = __bfloat16_as_ushort(__float2bfloat16(v.w - __bfloat162float(__ushort_as_bfloat16(hw))));
            unsigned off = SWZ((unsigned)(r * 128 + kq * 8));
            *(uint2*)(smem + OFF_AHI + off) = make_uint2(hx | (hy << 16), hz | (hw << 16));
            *(uint2*)(smem + OFF_ALO + off) = make_uint2(lx | (ly << 16), lz | (lw << 16));
        }
        // ---- B producer: copy rows [col0, col0+128) of pre-swizzled chunk image ----
        {
            const uint4* shp = Whi + (size_t)c * 2048 + col0 * 8;
            const uint4* slp = Wlo + (size_t)c * 2048 + col0 * 8;
            uint4* dh = (uint4*)(smem + OFF_BHI);
            uint4* dl = (uint4*)(smem + OFF_BLO);
#pragma unroll
            for (int i = 0; i < 4; i++) {
                dh[tid + i * 256] = shp[tid + i * 256];
                dl[tid + i * 256] = slp[tid + i * 256];
            }
        }
        __syncthreads();
        // ---- consume: 4 k16 steps ----
#pragma unroll
        for (int ks = 0; ks < 4; ks++) {
            const int k0 = ks * 16;
            unsigned ahi[2][4], alo[2][4];
#pragma unroll
            for (int mi = 0; mi < 2; mi++) {
                unsigned off = SWZ((unsigned)((wm0 + mi * 16 + lrow) * 128 + (k0 + lk) * 2));
                ldsm4(ahi[mi], sb + OFF_AHI + off);
                ldsm4(alo[mi], sb + OFF_ALO + off);
            }
#pragma unroll
            for (int h = 0; h < 2; h++) {
                unsigned bhi[2][4], blo[2][4];
#pragma unroll
                for (int nb = 0; nb < 2; nb++) {
                    unsigned off = SWZ((unsigned)((wn0 + (h * 2 + nb) * 16 + lrow) * 128 + (k0 + lk) * 2));
                    ldsm4(bhi[nb], sb + OFF_BHI + off);
                    ldsm4(blo[nb], sb + OFF_BLO + off);
                }
#pragma unroll
                for (int mi = 0; mi < 2; mi++)
#pragma unroll
                    for (int f = 0; f < 4; f++) {
                        int nb = f >> 1, r0 = f & 1;
                        float* d = acc[mi][h * 4 + f];
                        mma16816(d, ahi[mi], bhi[nb][r0], bhi[nb][r0 + 2]);
                        mma16816(d, ahi[mi], blo[nb][r0], blo[nb][r0 + 2]);
                        mma16816(d, alo[mi], bhi[nb][r0], bhi[nb][r0 + 2]);
                    }
            }
        }
    }

    // ---- epilogue: registers -> global ----
    const float* sbias = (const float*)(smem + OFF_BIAS);
    const float* sg = (const float*)(smem + OFF_GAMMA);
    const float* sbt = (const float*)(smem + OFF_BETA);
    const int tr = lane >> 2;
    const int tc = (lane & 3) * 2;
#pragma unroll
    for (int mi = 0; mi < 2; mi++) {
#pragma unroll
        for (int ni = 0; ni < 8; ni++) {
            int cl = wn0 + ni * 8 + tc;          // 0..255 within-tile = bias index via col0+
            int cg = col0 + cl;                   // global col 0..255
            float b0 = sbias[cg], b1 = sbias[cg + 1];
            int ra = bm0 + wm0 + mi * 16 + tr;
            int rb = ra + 8;
            float v0 = acc[mi][ni][0] + b0, v1 = acc[mi][ni][1] + b1;
            float v2 = acc[mi][ni][2] + b0, v3 = acc[mi][ni][3] + b1;
            if (EPI == 1) {
                float ga = sg[cg], gb = sg[cg + 1], ba = sbt[cg], bb = sbt[cg + 1];
                v0 = fmaf(ga, fmaxf(v0, 0.f) * bnscale, ba);
                v1 = fmaf(gb, fmaxf(v1, 0.f) * bnscale, bb);
                v2 = fmaf(ga, fmaxf(v2, 0.f) * bnscale, ba);
                v3 = fmaf(gb, fmaxf(v3, 0.f) * bnscale, bb);
            }
            if (ra < M) {
                float2 v = make_float2(v0, v1);
                if (EPI == 2) {
                    float2 p = *(const float2*)(C + (size_t)ra * 256 + cg);
                    v.x += p.x; v.y += p.y;
                }
                *(float2*)(C + (size_t)ra * 256 + cg) = v;
            }
            if (rb < M) {
                float2 v = make_float2(v2, v3);
                if (EPI == 2) {
                    float2 p = *(const float2*)(C + (size_t)rb * 256 + cg);
                    v.x += p.x; v.y += p.y;
                }
                *(float2*)(C + (size_t)rb * 256 + cg) = v;
            }
        }
    }
}

// ---------------- row-wise L2 normalize + relu ----------------
__global__ void norm_relu_kernel(const float* __restrict__ o, float* __restrict__ xout) {
    int w = (blockIdx.x * blockDim.x + threadIdx.x) >> 5;
    int lane = threadIdx.x & 31;
    if (w >= NN) return;
    const float* row = o + (size_t)w * DD;
    float v[8];
    float s = 0.f;
#pragma unroll
    for (int j = 0; j < 8; j++) {
        v[j] = row[lane + j * 32];
        s = fmaf(v[j], v[j], s);
    }
#pragma unroll
    for (int off = 16; off > 0; off >>= 1) s += __shfl_xor_sync(0xffffffffu, s, off);
    float sc = 1.f / fmaxf(sqrtf(s), 1e-12f);
    float* out = xout + (size_t)w * DD;
#pragma unroll
    for (int j = 0; j < 8; j++) out[lane + j * 32] = fmaxf(v[j] * sc, 0.f);
}

// ---------------- head: logits [256->47] + log_softmax ----------------
__global__ void head_kernel(const float* __restrict__ h, const float* __restrict__ W2,
                            const float* __restrict__ b2, float* __restrict__ out) {
    __shared__ float sW[256 * NCLS];
    __shared__ float sb[NCLS];
    int tid = threadIdx.x;
    for (int i = tid; i < 256 * NCLS; i += 256) sW[i] = W2[i];
    if (tid < NCLS) sb[tid] = b2[tid];
    __syncthreads();

    int wid = tid >> 5, lane = tid & 31;
    int r = blockIdx.x * 8 + wid;
    if (r >= NN) return;

    const float4* rp = (const float4*)(h + (size_t)r * DD);
    float4 q0 = rp[lane * 2];
    float4 q1 = rp[lane * 2 + 1];
    float hreg[8] = {q0.x, q0.y, q0.z, q0.w, q1.x, q1.y, q1.z, q1.w};

    int c0 = lane;
    int c1 = lane + 32;
    int c1m = (c1 < NCLS) ? c1 : (NCLS - 1);
    float acc0 = sb[c0];
    float acc1 = sb[c1m];
#pragma unroll
    for (int e = 0; e < 8; e++) {
        for (int l = 0; l < 32; l++) {
            float hv = __shfl_sync(0xffffffffu, hreg[e], l);
            int k = l * 8 + e;
            acc0 = fmaf(hv, sW[k * NCLS + c0], acc0);
            acc1 = fmaf(hv, sW[k * NCLS + c1m], acc1);
        }
    }
    float m = fmaxf(acc0, (c1 < NCLS) ? acc1 : -3.4e38f);
#pragma unroll
    for (int o = 16; o > 0; o >>= 1) m = fmaxf(m, __shfl_xor_sync(0xffffffffu, m, o));
    float es = expf(acc0 - m) + ((c1 < NCLS) ? expf(acc1 - m) : 0.f);
#pragma unroll
    for (int o = 16; o > 0; o >>= 1) es += __shfl_xor_sync(0xffffffffu, es, o);
    float lse = m + logf(es);
    out[(size_t)r * NCLS + c0] = acc0 - lse;
    if (c1 < NCLS) out[(size_t)r * NCLS + c1] = acc1 - lse;
}

// ---------------- host orchestration ----------------
// chunk layout (4 chunks per 256x256 matrix):
//   cat image (lin_l then lin_r, 8/layer): layer i -> chunk i*8      (0..23)
//   w1:    24 + i*4            (24..35)
//   wa:    36 + (i*2+j)*4      (36..59)
//   wb:    60 + (i*2+j)*4      (60..83)
//   w2:    84 + i*4            (84..95)
//   post:  96                  (96..99)
extern "C" void kernel_launch(void* const* d_in, const int* in_sizes, int n_in,
                              void* d_out, int out_size) {
    const float* x_in      = (const float*)d_in[0];
    const int* ei          = (const int*)d_in[1];   // int32 (JAX x64 disabled)
    const float* lin_l_W   = (const float*)d_in[2];
    const float* lin_l_b   = (const float*)d_in[3];
    const float* lin_r_W   = (const float*)d_in[4];
    const float* lin_r_b   = (const float*)d_in[5];
    const float* mlp_W1    = (const float*)d_in[6];
    const float* mlp_b1    = (const float*)d_in[7];
    const float* blk_Wa    = (const float*)d_in[8];
    const float* blk_ba    = (const float*)d_in[9];
    const float* blk_gamma = (const float*)d_in[10];
    const float* blk_beta  = (const float*)d_in[11];
    const float* blk_Wb    = (const float*)d_in[12];
    const float* blk_bb    = (const float*)d_in[13];
    const float* mlp_W2    = (const float*)d_in[14];
    const float* mlp_b2    = (const float*)d_in[15];
    const float* post_W1   = (const float*)d_in[16];
    const float* post_b1   = (const float*)d_in[17];
    const float* post_W2   = (const float*)d_in[18];
    const float* post_b2   = (const float*)d_in[19];
    float* out = (float*)d_out;

    float *xp, *zp, *pp, *hp, *tp, *cp;
    uint4 *whi, *wlo;
    cudaGetSymbolAddress((void**)&xp, g_x);
    cudaGetSymbolAddress((void**)&zp, g_z);
    cudaGetSymbolAddress((void**)&pp, g_p);
    cudaGetSymbolAddress((void**)&hp, g_h);
    cudaGetSymbolAddress((void**)&tp, g_t);
    cudaGetSymbolAddress((void**)&cp, g_cnt);
    cudaGetSymbolAddress((void**)&whi, g_whi4);
    cudaGetSymbolAddress((void**)&wlo, g_wlo4);
    unsigned short* hiu = (unsigned short*)whi;
    unsigned short* lou = (unsigned short*)wlo;

    cudaFuncSetAttribute(mma_gemm<512, 0>, cudaFuncAttributeMaxDynamicSharedMemorySize, SMEM_SZ);
    cudaFuncSetAttribute(mma_gemm<256, 0>, cudaFuncAttributeMaxDynamicSharedMemorySize, SMEM_SZ);
    cudaFuncSetAttribute(mma_gemm<256, 1>, cudaFuncAttributeMaxDynamicSharedMemorySize, SMEM_SZ);
    cudaFuncSetAttribute(mma_gemm<256, 2>, cudaFuncAttributeMaxDynamicSharedMemorySize, SMEM_SZ);

    const float bnscale = rsqrtf(1.0f + 1e-5f);
    const int* src = ei;
    const int* dst = ei + EE;

    // ---- weight prep (batched: 7 launches) ----
    prep_w<<<3 * 256, 256>>>(lin_l_W, 0, 8, hiu, lou);
    prep_w<<<3 * 256, 256>>>(lin_r_W, 4, 8, hiu, lou);
    prep_w<<<3 * 256, 256>>>(mlp_W1, 24, 4, hiu, lou);
    prep_w<<<6 * 256, 256>>>(blk_Wa, 36, 4, hiu, lou);
    prep_w<<<6 * 256, 256>>>(blk_Wb, 60, 4, hiu, lou);
    prep_w<<<3 * 256, 256>>>(mlp_W2, 84, 4, hiu, lou);
    prep_w<<<1 * 256, 256>>>(post_W1, 96, 4, hiu, lou);

    // ---- degrees ----
    cudaMemcpyAsync(xp, x_in, (size_t)NN * DD * sizeof(float), cudaMemcpyDeviceToDevice);
    cudaMemsetAsync(cp, 0, NN * sizeof(float));
    count_kernel<<<(EE + 255) / 256, 256>>>(dst, cp);
    inv_kernel<<<(NN + 255) / 256, 256>>>(cp);

    dim3 grid(NB, 2);
    for (int i = 0; i < NLAYER; i++) {
        cudaMemsetAsync(zp, 0, (size_t)NN * DD * sizeof(float));
        scatter_kernel<<<(EE + 3) / 4, 256>>>(xp, src, dst, zp);

        // prop = x@Wl + bl + (z/cnt)@Wr + br  (fused K=512)
        mma_gemm<512, 0><<<grid, 256, SMEM_SZ>>>(
            xp, zp, cp, whi + (size_t)(i * 8) * 2048, wlo + (size_t)(i * 8) * 2048,
            lin_l_b + (size_t)i * 256, lin_r_b + (size_t)i * 256, nullptr, nullptr, 0.f, pp, NN);
        // h = prop@W1 + b1
        mma_gemm<256, 0><<<grid, 256, SMEM_SZ>>>(
            pp, nullptr, nullptr, whi + (size_t)(24 + i * 4) * 2048,
            wlo + (size_t)(24 + i * 4) * 2048, mlp_b1 + (size_t)i * 256,
            nullptr, nullptr, nullptr, 0.f, hp, NN);
        for (int j = 0; j < 2; j++) {
            size_t bo = ((size_t)i * 2 + j) * 256;
            int ca = 36 + (i * 2 + j) * 4, cb = 60 + (i * 2 + j) * 4;
            mma_gemm<256, 1><<<grid, 256, SMEM_SZ>>>(
                hp, nullptr, nullptr, whi + (size_t)ca * 2048, wlo + (size_t)ca * 2048,
                blk_ba + bo, nullptr, blk_gamma + bo, blk_beta + bo, bnscale, tp, NN);
            mma_gemm<256, 2><<<grid, 256, SMEM_SZ>>>(
                tp, nullptr, nullptr, whi + (size_t)cb * 2048, wlo + (size_t)cb * 2048,
                blk_bb + bo, nullptr, nullptr, nullptr, 0.f, hp, NN);
        }
        // o = h@W2 + b2 ; x = relu(normalize(o))
        mma_gemm<256, 0><<<grid, 256, SMEM_SZ>>>(
            hp, nullptr, nullptr, whi + (size_t)(84 + i * 4) * 2048,
            wlo + (size_t)(84 + i * 4) * 2048, mlp_b2 + (size_t)i * 256,
            nullptr, nullptr, nullptr, 0.f, pp, NN);
        norm_relu_kernel<<<(NN * 32 + 255) / 256, 256>>>(pp, xp);
    }

    // post MLP + log_softmax
    mma_gemm<256, 0><<<grid, 256, SMEM_SZ>>>(
        xp, nullptr, nullptr, whi + (size_t)96 * 2048, wlo + (size_t)96 * 2048,
        post_b1, nullptr, nullptr, nullptr, 0.f, pp, NN);
    head_kernel<<<(NN + 7) / 8, 256>>>(pp, post_W2, post_b2, out);
}

// round 5
// speedup vs baseline: 1.9078x; 1.2973x over previous
#include <cuda_runtime.h>
#include <cuda_bf16.h>
#include <math.h>

#define NN 50000
#define ROWSP 50048
#define DD 256
#define EE 800000
#define NCLS 47
#define NLAYER 3
#define NB 391

// SW128 swizzle on byte offset within a 128B row block
#define SWZ(x) ((x) ^ (((x) >> 3) & 0x70))

// dynamic smem layout
#define ABUF 32768           // per stage: AHI 16KB @0, ALO 16KB @16384
#define BBASE 65536
#define BBUF 65536           // per stage: BHI 32KB @0, BLO 32KB @32768
#define PBASE 196608         // bias 1KB, gamma 1KB, beta 1KB, rsum 2KB
#define SMEM_SZ 201728

// ---------------- device scratch ----------------
__device__ float g_x[ROWSP * DD];
__device__ float g_z[ROWSP * DD];
__device__ float g_p[ROWSP * DD];
__device__ float g_cnt[NN];
__device__ uint4 g_whi4[100 * 2048];
__device__ uint4 g_wlo4[100 * 2048];
// activation images: [chunk(4)][row(ROWSP)][128B swizzled] as uints
__device__ unsigned g_ximg_hi[4 * ROWSP * 32];
__device__ unsigned g_ximg_lo[4 * ROWSP * 32];
__device__ unsigned g_pimg_hi[4 * ROWSP * 32];
__device__ unsigned g_pimg_lo[4 * ROWSP * 32];
__device__ unsigned g_himg_hi[4 * ROWSP * 32];
__device__ unsigned g_himg_lo[4 * ROWSP * 32];
__device__ unsigned g_timg_hi[4 * ROWSP * 32];
__device__ unsigned g_timg_lo[4 * ROWSP * 32];

static __device__ __forceinline__ float4 ld4(const float* p) { return *(const float4*)p; }

static __device__ __forceinline__ unsigned smem_u32(const void* p) {
    unsigned a;
    asm("{ .reg .u64 t; cvta.to.shared.u64 t, %1; cvt.u32.u64 %0, t; }" : "=r"(a) : "l"(p));
    return a;
}
static __device__ __forceinline__ void ldsm4(unsigned r[4], unsigned addr) {
    asm volatile("ldmatrix.sync.aligned.m8n8.x4.shared.b16 {%0,%1,%2,%3}, [%4];"
                 : "=r"(r[0]), "=r"(r[1]), "=r"(r[2]), "=r"(r[3]) : "r"(addr));
}
static __device__ __forceinline__ void mma16816(float d[4], const unsigned a[4],
                                                unsigned b0, unsigned b1) {
    asm volatile(
        "mma.sync.aligned.m16n8k16.row.col.f32.bf16.bf16.f32 "
        "{%0,%1,%2,%3}, {%4,%5,%6,%7}, {%8,%9}, {%0,%1,%2,%3};"
        : "+f"(d[0]), "+f"(d[1]), "+f"(d[2]), "+f"(d[3])
        : "r"(a[0]), "r"(a[1]), "r"(a[2]), "r"(a[3]), "r"(b0), "r"(b1));
}
#define CPA(dst, src) \
    asm volatile("cp.async.cg.shared.global [%0], [%1], 16;" :: "r"(dst), "l"(src) : "memory")
#define CP_COMMIT() asm volatile("cp.async.commit_group;" ::: "memory")
template <int N>
static __device__ __forceinline__ void cp_wait() {
    asm volatile("cp.async.wait_group %0;" :: "n"(N) : "memory");
}

static __device__ __forceinline__ void bsplit(float v, unsigned& h, unsigned& l) {
    __nv_bfloat16 hb = __float2bfloat16(v);
    h = __bfloat16_as_ushort(hb);
    l = __bfloat16_as_ushort(__float2bfloat16(v - __bfloat162float(hb)));
}
static __device__ __forceinline__ unsigned img_idx(int chunk, int row, int lc) {
    return ((unsigned)chunk * ROWSP + (unsigned)row) * 32u +
           ((((unsigned)(lc * 2)) ^ (((unsigned)row & 7u) << 4)) >> 2);
}
static __device__ __forceinline__ void img_write(unsigned* __restrict__ hi,
                                                 unsigned* __restrict__ lo, int chunk,
                                                 int row, int lc, float v0, float v1) {
    unsigned h0, l0, h1, l1;
    bsplit(v0, h0, l0);
    bsplit(v1, h1, l1);
    unsigned idx = img_idx(chunk, row, lc);
    hi[idx] = h0 | (h1 << 16);
    lo[idx] = l0 | (l1 << 16);
}
static __device__ __forceinline__ float2 img_read(const unsigned* __restrict__ hi,
                                                  const unsigned* __restrict__ lo, int chunk,
                                                  int row, int lc) {
    unsigned idx = img_idx(chunk, row, lc);
    unsigned h = hi[idx], l = lo[idx];
    float x0 = __bfloat162float(__ushort_as_bfloat16((unsigned short)(h & 0xffff))) +
               __bfloat162float(__ushort_as_bfloat16((unsigned short)(l & 0xffff)));
    float x1 = __bfloat162float(__ushort_as_bfloat16((unsigned short)(h >> 16))) +
               __bfloat162float(__ushort_as_bfloat16((unsigned short)(l >> 16)));
    return make_float2(x0, x1);
}

// ---------------- degree count / invert ----------------
__global__ void count_kernel(const int* __restrict__ dst, float* __restrict__ cnt) {
    int e = blockIdx.x * 256 + threadIdx.x;
    if (e < EE) atomicAdd(&cnt[dst[e]], 1.0f);
}
__global__ void inv_kernel(float* __restrict__ cnt) {
    int i = blockIdx.x * 256 + threadIdx.x;
    if (i < NN) cnt[i] = 1.0f / fmaxf(cnt[i], 1.0f);
}

// ---------------- scatter-add with vector reductions ----------------
__global__ void scatter_kernel(const float* __restrict__ x, const int* __restrict__ src,
                               const int* __restrict__ dst, float* __restrict__ z) {
    int e = blockIdx.x * 4 + (threadIdx.x >> 6);
    if (e >= EE) return;
    int s = src[e];
    int d = dst[e];
    int c = (threadIdx.x & 63) * 4;
    float4 v = ld4(x + (size_t)s * DD + c);
    float* zp = z + (size_t)d * DD + c;
    asm volatile("red.global.add.v4.f32 [%0], {%1,%2,%3,%4};"
                 :: "l"(zp), "f"(v.x), "f"(v.y), "f"(v.z), "f"(v.w) : "memory");
}

// ---------------- weight prep (as R4; chunk images 32KB, swizzled) ----------------
__global__ void prep_w(const float* __restrict__ W, int chunk_start, int chunk_stride,
                       unsigned short* __restrict__ dhi, unsigned short* __restrict__ dlo) {
    int idx = blockIdx.x * 256 + threadIdx.x;
    int t = idx >> 16;
    int rem = idx & 65535;
    int n = rem & 255, k = rem >> 8;
    float v = W[(size_t)idx];
    __nv_bfloat16 h = __float2bfloat16(v);
    __nv_bfloat16 l = __float2bfloat16(v - __bfloat162float(h));
    unsigned chunk = chunk_start + t * chunk_stride + (k >> 6);
    unsigned off = chunk * 32768u + SWZ((unsigned)(n * 128 + (k & 63) * 2));
    dhi[off >> 1] = __bfloat16_as_ushort(h);
    dlo[off >> 1] = __bfloat16_as_ushort(l);
}

// ---------------- initial x image ----------------
__global__ void split_img(const float* __restrict__ X, unsigned* __restrict__ hi,
                          unsigned* __restrict__ lo) {
    int idx = blockIdx.x * 256 + threadIdx.x;
    if (idx >= NN * 128) return;
    int row = idx >> 7, p = idx & 127;
    float v0 = X[(size_t)row * 256 + p * 2];
    float v1 = X[(size_t)row * 256 + p * 2 + 1];
    img_write(hi, lo, (p * 2) >> 6, row, (p * 2) & 63, v0, v1);
}

// ---------------- HMMA GEMM: [M,KTOT] x [KTOT,256] -> [M,256] ----------------
// A from bf16 hi/lo images (chunks 0-3); for KTOT=512 chunks 4-7 convert z*inv fp32.
// 3-term split (hi*hi + hi*lo + lo*hi), fp32 accumulate.
// EPI: 0 bias(+bias2); 1 gamma*(relu(+bias)*bnscale)+beta; 2 +bias + residual (Oimg read);
//      3 +bias, row-L2-normalize, relu.
// OMODE bit0: write Oimg (bf16 hi/lo image); bit1: write Of32.
template <int KTOT, int EPI, int OMODE>
__global__ void __launch_bounds__(512, 1)
mma_gemm(const unsigned* __restrict__ Aimg_hi, const unsigned* __restrict__ Aimg_lo,
         const float* __restrict__ A2, const float* __restrict__ inv,
         const uint4* __restrict__ Whi, const uint4* __restrict__ Wlo,
         const float* __restrict__ bias, const float* __restrict__ bias2,
         const float* __restrict__ gamma, const float* __restrict__ beta, float bnscale,
         unsigned* __restrict__ Oimg_hi, unsigned* __restrict__ Oimg_lo,
         float* __restrict__ Of32, int M) {
    extern __shared__ char smem[];
    const unsigned sb = smem_u32(smem);
    const int tid = threadIdx.x, wid = tid >> 5, lane = tid & 31;
    const int bm0 = blockIdx.x * 128;
    constexpr int NCHUNK = KTOT / 64;

    // params
    if (tid < 256) {
        float bv = bias[tid];
        if (EPI == 0 && bias2) bv += bias2[tid];
        ((float*)(smem + PBASE))[tid] = bv;
        if (EPI == 1) {
            ((float*)(smem + PBASE + 1024))[tid] = gamma[tid];
            ((float*)(smem + PBASE + 2048))[tid] = beta[tid];
        }
    }

    const int wm0 = (wid >> 2) * 32;
    const int wn0 = (wid & 3) * 64;
    const int lrow = lane & 15;
    const int lk = (lane >> 4) * 8;

    float acc[2][8][4];
#pragma unroll
    for (int a = 0; a < 2; a++)
#pragma unroll
        for (int b = 0; b < 8; b++)
#pragma unroll
            for (int c = 0; c < 4; c++) acc[a][b][c] = 0.f;

    auto issue = [&](int c, int st) {
        unsigned ab = sb + st * ABUF;
        unsigned bb = sb + BBASE + st * BBUF;
        const char* wh = (const char*)(Whi + (size_t)c * 2048);
        const char* wl = (const char*)(Wlo + (size_t)c * 2048);
#pragma unroll
        for (int i = 0; i < 4; i++) {
            int u = tid + i * 512;
            CPA(bb + u * 16, wh + u * 16);
            CPA(bb + 32768 + u * 16, wl + u * 16);
        }
        if (KTOT == 512 && c >= 4) {
            // convert z*inv -> bf16 hi/lo, swizzled STS
#pragma unroll
            for (int i = 0; i < 4; i++) {
                int q = tid + i * 512;
                int r = q >> 4, kq = q & 15;
                int grow = bm0 + r;
                float4 v = make_float4(0.f, 0.f, 0.f, 0.f);
                if (grow < M) {
                    v = ld4(A2 + (size_t)grow * 256 + (c - 4) * 64 + kq * 4);
                    float iv = inv[grow];
                    v.x *= iv; v.y *= iv; v.z *= iv; v.w *= iv;
                }
                unsigned hx, lx, hy, ly, hz, lz, hw, lw;
                bsplit(v.x, hx, lx); bsplit(v.y, hy, ly);
                bsplit(v.z, hz, lz); bsplit(v.w, hw, lw);
                unsigned off = SWZ((unsigned)(r * 128 + kq * 8));
                *(uint2*)(smem + st * ABUF + off) = make_uint2(hx | (hy << 16), hz | (hw << 16));
                *(uint2*)(smem + st * ABUF + 16384 + off) = make_uint2(lx | (ly << 16), lz | (lw << 16));
            }
        } else {
            const char* ih = (const char*)(Aimg_hi + ((size_t)c * ROWSP + bm0) * 32);
            const char* il = (const char*)(Aimg_lo + ((size_t)c * ROWSP + bm0) * 32);
#pragma unroll
            for (int i = 0; i < 2; i++) {
                int u = tid + i * 512;
                CPA(ab + u * 16, ih + u * 16);
                CPA(ab + 16384 + u * 16, il + u * 16);
            }
        }
    };

    issue(0, 0);
    CP_COMMIT();

    for (int c = 0; c < NCHUNK; c++) {
        int st = c & 1;
        if (c + 1 < NCHUNK) {
            issue(c + 1, st ^ 1);
            CP_COMMIT();
            cp_wait<1>();
        } else {
            cp_wait<0>();
        }
        __syncthreads();
        // consume stage st
        unsigned abase = sb + st * ABUF;
        unsigned bbase = sb + BBASE + st * BBUF;
#pragma unroll
        for (int ks = 0; ks < 4; ks++) {
            const int k0 = ks * 16;
            unsigned ahi[2][4], alo[2][4];
#pragma unroll
            for (int mi = 0; mi < 2; mi++) {
                unsigned off = SWZ((unsigned)((wm0 + mi * 16 + lrow) * 128 + (k0 + lk) * 2));
                ldsm4(ahi[mi], abase + off);
                ldsm4(alo[mi], abase + 16384 + off);
            }
#pragma unroll
            for (int h = 0; h < 2; h++) {
                unsigned bhi[2][4], blo[2][4];
#pragma unroll
                for (int nb = 0; nb < 2; nb++) {
                    unsigned off = SWZ((unsigned)((wn0 + (h * 2 + nb) * 16 + lrow) * 128 + (k0 + lk) * 2));
                    ldsm4(bhi[nb], bbase + off);
                    ldsm4(blo[nb], bbase + 32768 + off);
                }
#pragma unroll
                for (int mi = 0; mi < 2; mi++)
#pragma unroll
                    for (int f = 0; f < 4; f++) {
                        int nb = f >> 1, r0 = f & 1;
                        float* d = acc[mi][h * 4 + f];
                        mma16816(d, ahi[mi], bhi[nb][r0], bhi[nb][r0 + 2]);
                        mma16816(d, ahi[mi], blo[nb][r0], blo[nb][r0 + 2]);
                        mma16816(d, alo[mi], bhi[nb][r0], bhi[nb][r0 + 2]);
                    }
            }
        }
        __syncthreads();
    }

    // ---- epilogue ----
    const float* sbias = (const float*)(smem + PBASE);
    const float* sg = (const float*)(smem + PBASE + 1024);
    const float* sbt = (const float*)(smem + PBASE + 2048);
    float* rsum = (float*)(smem + PBASE + 3072);
    const int tr = lane >> 2;
    const int tc2 = (lane & 3) * 2;
    const int chunkw = wid & 3;

#pragma unroll
    for (int mi = 0; mi < 2; mi++) {
#pragma unroll
        for (int ni = 0; ni < 8; ni++) {
            int cg = wn0 + ni * 8 + tc2;
            float b0 = sbias[cg], b1 = sbias[cg + 1];
            float* d = acc[mi][ni];
            d[0] += b0; d[1] += b1; d[2] += b0; d[3] += b1;
            if (EPI == 1) {
                float ga = sg[cg], gb = sg[cg + 1], ba = sbt[cg], bb = sbt[cg + 1];
                d[0] = fmaf(ga, fmaxf(d[0], 0.f) * bnscale, ba);
                d[1] = fmaf(gb, fmaxf(d[1], 0.f) * bnscale, bb);
                d[2] = fmaf(ga, fmaxf(d[2], 0.f) * bnscale, ba);
                d[3] = fmaf(gb, fmaxf(d[3], 0.f) * bnscale, bb);
            }
            if (EPI == 2) {
                int lc = cg & 63;
                int ra = bm0 + wm0 + mi * 16 + tr;
                float2 oa = img_read(Oimg_hi, Oimg_lo, chunkw, ra, lc);
                float2 ob = img_read(Oimg_hi, Oimg_lo, chunkw, ra + 8, lc);
                d[0] += oa.x; d[1] += oa.y; d[2] += ob.x; d[3] += ob.y;
            }
        }
    }
    if (EPI == 3) {
        float ps[2][2] = {{0.f, 0.f}, {0.f, 0.f}};
#pragma unroll
        for (int mi = 0; mi < 2; mi++)
#pragma unroll
            for (int ni = 0; ni < 8; ni++) {
                float* d = acc[mi][ni];
                ps[mi][0] = fmaf(d[0], d[0], fmaf(d[1], d[1], ps[mi][0]));
                ps[mi][1] = fmaf(d[2], d[2], fmaf(d[3], d[3], ps[mi][1]));
            }
#pragma unroll
        for (int mi = 0; mi < 2; mi++)
#pragma unroll
            for (int q = 0; q < 2; q++) {
                ps[mi][q] += __shfl_xor_sync(0xffffffffu, ps[mi][q], 1);
                ps[mi][q] += __shfl_xor_sync(0xffffffffu, ps[mi][q], 2);
            }
        if ((lane & 3) == 0) {
#pragma unroll
            for (int mi = 0; mi < 2; mi++) {
                rsum[(wm0 + mi * 16 + tr) * 4 + chunkw] = ps[mi][0];
                rsum[(wm0 + mi * 16 + 8 + tr) * 4 + chunkw] = ps[mi][1];
            }
        }
        __syncthreads();
        float sc[2][2];
#pragma unroll
        for (int mi = 0; mi < 2; mi++) {
            int r = wm0 + mi * 16 + tr;
            float s0 = rsum[r * 4] + rsum[r * 4 + 1] + rsum[r * 4 + 2] + rsum[r * 4 + 3];
            int r2 = r + 8;
            float s1 = rsum[r2 * 4] + rsum[r2 * 4 + 1] + rsum[r2 * 4 + 2] + rsum[r2 * 4 + 3];
            sc[mi][0] = 1.f / fmaxf(sqrtf(s0), 1e-12f);
            sc[mi][1] = 1.f / fmaxf(sqrtf(s1), 1e-12f);
        }
#pragma unroll
        for (int mi = 0; mi < 2; mi++)
#pragma unroll
            for (int ni = 0; ni < 8; ni++) {
                float* d = acc[mi][ni];
                d[0] = fmaxf(d[0] * sc[mi][0], 0.f);
                d[1] = fmaxf(d[1] * sc[mi][0], 0.f);
                d[2] = fmaxf(d[2] * sc[mi][1], 0.f);
                d[3] = fmaxf(d[3] * sc[mi][1], 0.f);
            }
    }
    // writes
#pragma unroll
    for (int mi = 0; mi < 2; mi++) {
#pragma unroll
        for (int ni = 0; ni < 8; ni++) {
            int cg = wn0 + ni * 8 + tc2;
            int lc = cg & 63;
            int ra = bm0 + wm0 + mi * 16 + tr;
            int rb = ra + 8;
            float* d = acc[mi][ni];
            if (OMODE & 1) {
                img_write(Oimg_hi, Oimg_lo, chunkw, ra, lc, d[0], d[1]);
                img_write(Oimg_hi, Oimg_lo, chunkw, rb, lc, d[2], d[3]);
            }
            if (OMODE & 2) {
                if (ra < M) *(float2*)(Of32 + (size_t)ra * 256 + cg) = make_float2(d[0], d[1]);
                if (rb < M) *(float2*)(Of32 + (size_t)rb * 256 + cg) = make_float2(d[2], d[3]);
            }
        }
    }
}

// ---------------- head: logits [256->47] + log_softmax ----------------
__global__ void head_kernel(const float* __restrict__ h, const float* __restrict__ W2,
                            const float* __restrict__ b2, float* __restrict__ out) {
    __shared__ float sW[256 * NCLS];
    __shared__ float sb[NCLS];
    int tid = threadIdx.x;
    for (int i = tid; i < 256 * NCLS; i += 256) sW[i] = W2[i];
    if (tid < NCLS) sb[tid] = b2[tid];
    __syncthreads();

    int wid = tid >> 5, lane = tid & 31;
    int r = blockIdx.x * 8 + wid;
    if (r >= NN) return;

    const float4* rp = (const float4*)(h + (size_t)r * DD);
    float4 q0 = rp[lane * 2];
    float4 q1 = rp[lane * 2 + 1];
    float hreg[8] = {q0.x, q0.y, q0.z, q0.w, q1.x, q1.y, q1.z, q1.w};

    int c0 = lane;
    int c1 = lane + 32;
    int c1m = (c1 < NCLS) ? c1 : (NCLS - 1);
    float acc0 = sb[c0];
    float acc1 = sb[c1m];
#pragma unroll
    for (int e = 0; e < 8; e++) {
        for (int l = 0; l < 32; l++) {
            float hv = __shfl_sync(0xffffffffu, hreg[e], l);
            int k = l * 8 + e;
            acc0 = fmaf(hv, sW[k * NCLS + c0], acc0);
            acc1 = fmaf(hv, sW[k * NCLS + c1m], acc1);
        }
    }
    float m = fmaxf(acc0, (c1 < NCLS) ? acc1 : -3.4e38f);
#pragma unroll
    for (int o = 16; o > 0; o >>= 1) m = fmaxf(m, __shfl_xor_sync(0xffffffffu, m, o));
    float es = expf(acc0 - m) + ((c1 < NCLS) ? expf(acc1 - m) : 0.f);
#pragma unroll
    for (int o = 16; o > 0; o >>= 1) es += __shfl_xor_sync(0xffffffffu, es, o);
    float lse = m + logf(es);
    out[(size_t)r * NCLS + c0] = acc0 - lse;
    if (c1 < NCLS) out[(size_t)r * NCLS + c1] = acc1 - lse;
}

// ---------------- host orchestration ----------------
// weight chunk layout: cat (lin_l|lin_r) layer i -> i*8 (0..23); w1: 24+i*4;
// wa: 36+(i*2+j)*4; wb: 60+(i*2+j)*4; w2: 84+i*4; post: 96.
extern "C" void kernel_launch(void* const* d_in, const int* in_sizes, int n_in,
                              void* d_out, int out_size) {
    const float* x_in      = (const float*)d_in[0];
    const int* ei          = (const int*)d_in[1];   // int32 (JAX x64 disabled)
    const float* lin_l_W   = (const float*)d_in[2];
    const float* lin_l_b   = (const float*)d_in[3];
    const float* lin_r_W   = (const float*)d_in[4];
    const float* lin_r_b   = (const float*)d_in[5];
    const float* mlp_W1    = (const float*)d_in[6];
    const float* mlp_b1    = (const float*)d_in[7];
    const float* blk_Wa    = (const float*)d_in[8];
    const float* blk_ba    = (const float*)d_in[9];
    const float* blk_gamma = (const float*)d_in[10];
    const float* blk_beta  = (const float*)d_in[11];
    const float* blk_Wb    = (const float*)d_in[12];
    const float* blk_bb    = (const float*)d_in[13];
    const float* mlp_W2    = (const float*)d_in[14];
    const float* mlp_b2    = (const float*)d_in[15];
    const float* post_W1   = (const float*)d_in[16];
    const float* post_b1   = (const float*)d_in[17];
    const float* post_W2   = (const float*)d_in[18];
    const float* post_b2   = (const float*)d_in[19];
    float* out = (float*)d_out;

    float *xp, *zp, *pp, *cp;
    uint4 *whi, *wlo;
    unsigned *xih, *xil, *pih, *pil, *hih, *hil, *tih, *til;
    cudaGetSymbolAddress((void**)&xp, g_x);
    cudaGetSymbolAddress((void**)&zp, g_z);
    cudaGetSymbolAddress((void**)&pp, g_p);
    cudaGetSymbolAddress((void**)&cp, g_cnt);
    cudaGetSymbolAddress((void**)&whi, g_whi4);
    cudaGetSymbolAddress((void**)&wlo, g_wlo4);
    cudaGetSymbolAddress((void**)&xih, g_ximg_hi);
    cudaGetSymbolAddress((void**)&xil, g_ximg_lo);
    cudaGetSymbolAddress((void**)&pih, g_pimg_hi);
    cudaGetSymbolAddress((void**)&pil, g_pimg_lo);
    cudaGetSymbolAddress((void**)&hih, g_himg_hi);
    cudaGetSymbolAddress((void**)&hil, g_himg_lo);
    cudaGetSymbolAddress((void**)&tih, g_timg_hi);
    cudaGetSymbolAddress((void**)&til, g_timg_lo);
    unsigned short* hiu = (unsigned short*)whi;
    unsigned short* lou = (unsigned short*)wlo;

    cudaFuncSetAttribute(mma_gemm<512, 0, 1>, cudaFuncAttributeMaxDynamicSharedMemorySize, SMEM_SZ);
    cudaFuncSetAttribute(mma_gemm<256, 0, 1>, cudaFuncAttributeMaxDynamicSharedMemorySize, SMEM_SZ);
    cudaFuncSetAttribute(mma_gemm<256, 1, 1>, cudaFuncAttributeMaxDynamicSharedMemorySize, SMEM_SZ);
    cudaFuncSetAttribute(mma_gemm<256, 2, 1>, cudaFuncAttributeMaxDynamicSharedMemorySize, SMEM_SZ);
    cudaFuncSetAttribute(mma_gemm<256, 3, 3>, cudaFuncAttributeMaxDynamicSharedMemorySize, SMEM_SZ);
    cudaFuncSetAttribute(mma_gemm<256, 0, 2>, cudaFuncAttributeMaxDynamicSharedMemorySize, SMEM_SZ);

    const float bnscale = rsqrtf(1.0f + 1e-5f);
    const int* src = ei;
    const int* dst = ei + EE;

    // weight prep
    prep_w<<<3 * 256, 256>>>(lin_l_W, 0, 8, hiu, lou);
    prep_w<<<3 * 256, 256>>>(lin_r_W, 4, 8, hiu, lou);
    prep_w<<<3 * 256, 256>>>(mlp_W1, 24, 4, hiu, lou);
    prep_w<<<6 * 256, 256>>>(blk_Wa, 36, 4, hiu, lou);
    prep_w<<<6 * 256, 256>>>(blk_Wb, 60, 4, hiu, lou);
    prep_w<<<3 * 256, 256>>>(mlp_W2, 84, 4, hiu, lou);
    prep_w<<<1 * 256, 256>>>(post_W1, 96, 4, hiu, lou);

    // x image + degrees
    split_img<<<(NN * 128 + 255) / 256, 256>>>(x_in, xih, xil);
    cudaMemsetAsync(cp, 0, NN * sizeof(float));
    count_kernel<<<(EE + 255) / 256, 256>>>(dst, cp);
    inv_kernel<<<(NN + 255) / 256, 256>>>(cp);

    for (int i = 0; i < NLAYER; i++) {
        const float* x_prev = (i == 0) ? x_in : xp;
        cudaMemsetAsync(zp, 0, (size_t)NN * DD * sizeof(float));
        scatter_kernel<<<(EE + 3) / 4, 256>>>(x_prev, src, dst, zp);

        // prop = x@Wl + bl + (z/cnt)@Wr + br  -> pimg
        mma_gemm<512, 0, 1><<<NB, 512, SMEM_SZ>>>(
            xih, xil, zp, cp, whi + (size_t)(i * 8) * 2048, wlo + (size_t)(i * 8) * 2048,
            lin_l_b + (size_t)i * 256, lin_r_b + (size_t)i * 256, nullptr, nullptr, 0.f,
            pih, pil, nullptr, NN);
        // h = prop@W1 + b1 -> himg
        mma_gemm<256, 0, 1><<<NB, 512, SMEM_SZ>>>(
            pih, pil, nullptr, nullptr, whi + (size_t)(24 + i * 4) * 2048,
            wlo + (size_t)(24 + i * 4) * 2048, mlp_b1 + (size_t)i * 256, nullptr,
            nullptr, nullptr, 0.f, hih, hil, nullptr, NN);
        for (int j = 0; j < 2; j++) {
            size_t bo = ((size_t)i * 2 + j) * 256;
            int ca = 36 + (i * 2 + j) * 4, cb = 60 + (i * 2 + j) * 4;
            // t = gamma*(relu(h@Wa+ba)*bnscale)+beta -> timg
            mma_gemm<256, 1, 1><<<NB, 512, SMEM_SZ>>>(
                hih, hil, nullptr, nullptr, whi + (size_t)ca * 2048, wlo + (size_t)ca * 2048,
                blk_ba + bo, nullptr, blk_gamma + bo, blk_beta + bo, bnscale,
                tih, til, nullptr, NN);
            // h = h + t@Wb + bb -> himg (residual read+write)
            mma_gemm<256, 2, 1><<<NB, 512, SMEM_SZ>>>(
                tih, til, nullptr, nullptr, whi + (size_t)cb * 2048, wlo + (size_t)cb * 2048,
                blk_bb + bo, nullptr, nullptr, nullptr, 0.f, hih, hil, nullptr, NN);
        }
        // x = relu(normalize(h@W2 + b2)) -> ximg + x fp32
        mma_gemm<256, 3, 3><<<NB, 512, SMEM_SZ>>>(
            hih, hil, nullptr, nullptr, whi + (size_t)(84 + i * 4) * 2048,
            wlo + (size_t)(84 + i * 4) * 2048, mlp_b2 + (size_t)i * 256, nullptr,
            nullptr, nullptr, 0.f, xih, xil, xp, NN);
    }

    // post MLP + log_softmax
    mma_gemm<256, 0, 2><<<NB, 512, SMEM_SZ>>>(
        xih, xil, nullptr, nullptr, whi + (size_t)96 * 2048, wlo + (size_t)96 * 2048,
        post_b1, nullptr, nullptr, nullptr, 0.f, nullptr, nullptr, pp, NN);
    head_kernel<<<(NN + 7) / 8, 256>>>(pp, post_W2, post_b2, out);
}

// round 6
// speedup vs baseline: 2.1346x; 1.1189x over previous
#include <cuda_runtime.h>
#include <cuda_bf16.h>
#include <math.h>

#define NN 50000
#define ROWSP 50048
#define DD 256
#define EE 800000
#define NCLS 47
#define NLAYER 3
#define NB 391

#define SWZ(x) ((x) ^ (((x) >> 3) & 0x70))

// ---- old (post) gemm smem layout ----
#define ABUF 32768
#define BBASE 65536
#define BBUF 65536
#define PBASE 196608
#define SMEM_SZ 201728

// ---- fused kernel smem layout ----
#define FS_B 131072
#define FSMEM 229376   // 128KB img + 3x32KB B ring

// ---------------- device scratch ----------------
__device__ float g_x[ROWSP * DD];
__device__ float g_z[ROWSP * DD];
__device__ float g_p[ROWSP * DD];
__device__ uint4 g_whi4[100 * 2048];
__device__ uint4 g_wlo4[100 * 2048];
__device__ unsigned g_ximg_hi[4 * ROWSP * 32];
__device__ unsigned g_ximg_lo[4 * ROWSP * 32];
__device__ unsigned g_himg_hi[4 * ROWSP * 32];
__device__ unsigned g_himg_lo[4 * ROWSP * 32];
__device__ int g_cnti[NN];
__device__ int g_off[NN + 1];
__device__ int g_cur[NN];
__device__ int g_csr[EE];

struct SlotTab { const uint4* p[64]; };

static __device__ __forceinline__ float4 ld4(const float* p) { return *(const float4*)p; }

static __device__ __forceinline__ unsigned smem_u32(const void* p) {
    unsigned a;
    asm("{ .reg .u64 t; cvta.to.shared.u64 t, %1; cvt.u32.u64 %0, t; }" : "=r"(a) : "l"(p));
    return a;
}
static __device__ __forceinline__ void ldsm4(unsigned r[4], unsigned addr) {
    asm volatile("ldmatrix.sync.aligned.m8n8.x4.shared.b16 {%0,%1,%2,%3}, [%4];"
                 : "=r"(r[0]), "=r"(r[1]), "=r"(r[2]), "=r"(r[3]) : "r"(addr));
}
static __device__ __forceinline__ void mma16816(float d[4], const unsigned a[4],
                                                unsigned b0, unsigned b1) {
    asm volatile(
        "mma.sync.aligned.m16n8k16.row.col.f32.bf16.bf16.f32 "
        "{%0,%1,%2,%3}, {%4,%5,%6,%7}, {%8,%9}, {%0,%1,%2,%3};"
        : "+f"(d[0]), "+f"(d[1]), "+f"(d[2]), "+f"(d[3])
        : "r"(a[0]), "r"(a[1]), "r"(a[2]), "r"(a[3]), "r"(b0), "r"(b1));
}
#define CPA(dst, src) \
    asm volatile("cp.async.cg.shared.global [%0], [%1], 16;" :: "r"(dst), "l"(src) : "memory")
#define CP_COMMIT() asm volatile("cp.async.commit_group;" ::: "memory")
template <int N>
static __device__ __forceinline__ void cp_wait() {
    asm volatile("cp.async.wait_group %0;" :: "n"(N) : "memory");
}

static __device__ __forceinline__ void bsplit(float v, unsigned& h, unsigned& l) {
    __nv_bfloat16 hb = __float2bfloat16(v);
    h = __bfloat16_as_ushort(hb);
    l = __bfloat16_as_ushort(__float2bfloat16(v - __bfloat162float(hb)));
}
static __device__ __forceinline__ unsigned img_idx(int chunk, int row, int lc) {
    return ((unsigned)chunk * ROWSP + (unsigned)row) * 32u +
           ((((unsigned)(lc * 2)) ^ (((unsigned)row & 7u) << 4)) >> 2);
}
static __device__ __forceinline__ void img_write(unsigned* __restrict__ hi,
                                                 unsigned* __restrict__ lo, int chunk,
                                                 int row, int lc, float v0, float v1) {
    unsigned h0, l0, h1, l1;
    bsplit(v0, h0, l0);
    bsplit(v1, h1, l1);
    unsigned idx = img_idx(chunk, row, lc);
    hi[idx] = h0 | (h1 << 16);
    lo[idx] = l0 | (l1 << 16);
}
static __device__ __forceinline__ float2 img_read(const unsigned* __restrict__ hi,
                                                  const unsigned* __restrict__ lo, int chunk,
                                                  int row, int lc) {
    unsigned idx = img_idx(chunk, row, lc);
    unsigned h = hi[idx], l = lo[idx];
    float x0 = __bfloat162float(__ushort_as_bfloat16((unsigned short)(h & 0xffff))) +
               __bfloat162float(__ushort_as_bfloat16((unsigned short)(l & 0xffff)));
    float x1 = __bfloat162float(__ushort_as_bfloat16((unsigned short)(h >> 16))) +
               __bfloat162float(__ushort_as_bfloat16((unsigned short)(l >> 16)));
    return make_float2(x0, x1);
}

// ---------------- CSR build ----------------
__global__ void count_int(const int* __restrict__ dst, int* __restrict__ cnt) {
    int e = blockIdx.x * 256 + threadIdx.x;
    if (e < EE) atomicAdd(&cnt[dst[e]], 1);
}
__global__ void scan_kernel(const int* __restrict__ cnt, int* __restrict__ off,
                            int* __restrict__ cur) {
    __shared__ int sdata[1024];
    __shared__ int carry;
    int tid = threadIdx.x;
    if (tid == 0) { carry = 0; off[0] = 0; }
    __syncthreads();
    for (int base = 0; base < NN; base += 1024) {
        int i = base + tid;
        int v = (i < NN) ? cnt[i] : 0;
        sdata[tid] = v;
        __syncthreads();
        for (int o = 1; o < 1024; o <<= 1) {
            int t = (tid >= o) ? sdata[tid - o] : 0;
            __syncthreads();
            sdata[tid] += t;
            __syncthreads();
        }
        int incl = sdata[tid] + carry;
        if (i < NN) { off[i + 1] = incl; cur[i] = incl - v; }
        __syncthreads();
        if (tid == 1023) carry = incl;
        __syncthreads();
    }
}
__global__ void fill_kernel(const int* __restrict__ src, const int* __restrict__ dst,
                            int* __restrict__ cur, int* __restrict__ csr) {
    int e = blockIdx.x * 256 + threadIdx.x;
    if (e < EE) {
        int p = atomicAdd(&cur[dst[e]], 1);
        csr[p] = src[e];
    }
}
// warp per dst: z[d] = mean over in-edges of x[src]
__global__ void gather_kernel(const float* __restrict__ x, const int* __restrict__ off,
                              const int* __restrict__ csr, float* __restrict__ z) {
    int d = blockIdx.x * 8 + (threadIdx.x >> 5);
    if (d >= NN) return;
    int lane = threadIdx.x & 31;
    int b = off[d], e = off[d + 1];
    float a[8] = {0.f, 0.f, 0.f, 0.f, 0.f, 0.f, 0.f, 0.f};
    for (int j = b; j < e; j++) {
        int s = csr[j];
        const float4* row = (const float4*)(x + (size_t)s * DD);
        float4 v0 = row[lane * 2];
        float4 v1 = row[lane * 2 + 1];
        a[0] += v0.x; a[1] += v0.y; a[2] += v0.z; a[3] += v0.w;
        a[4] += v1.x; a[5] += v1.y; a[6] += v1.z; a[7] += v1.w;
    }
    float iv = 1.f / fmaxf((float)(e - b), 1.f);
    float4* zr = (float4*)(z + (size_t)d * DD);
    zr[lane * 2] = make_float4(a[0] * iv, a[1] * iv, a[2] * iv, a[3] * iv);
    zr[lane * 2 + 1] = make_float4(a[4] * iv, a[5] * iv, a[6] * iv, a[7] * iv);
}

// ---------------- weight prep ----------------
__global__ void prep_w(const float* __restrict__ W, int chunk_start, int chunk_stride,
                       unsigned short* __restrict__ dhi, unsigned short* __restrict__ dlo) {
    int idx = blockIdx.x * 256 + threadIdx.x;
    int t = idx >> 16;
    int rem = idx & 65535;
    int n = rem & 255, k = rem >> 8;
    float v = W[(size_t)idx];
    __nv_bfloat16 h = __float2bfloat16(v);
    __nv_bfloat16 l = __float2bfloat16(v - __bfloat162float(h));
    unsigned chunk = chunk_start + t * chunk_stride + (k >> 6);
    unsigned off = chunk * 32768u + SWZ((unsigned)(n * 128 + (k & 63) * 2));
    dhi[off >> 1] = __bfloat16_as_ushort(h);
    dlo[off >> 1] = __bfloat16_as_ushort(l);
}

// ---------------- initial x image ----------------
__global__ void split_img(const float* __restrict__ X, unsigned* __restrict__ hi,
                          unsigned* __restrict__ lo) {
    int idx = blockIdx.x * 256 + threadIdx.x;
    if (idx >= NN * 128) return;
    int row = idx >> 7, p = idx & 127;
    float v0 = X[(size_t)row * 256 + p * 2];
    float v1 = X[(size_t)row * 256 + p * 2 + 1];
    img_write(hi, lo, (p * 2) >> 6, row, (p * 2) & 63, v0, v1);
}

// ---- fused-layer helpers ----
template <bool BHI>
static __device__ __forceinline__ void mma_slot(unsigned abase, unsigned bbase,
                                                float (&acc)[2][8][4], int wm0, int wn0,
                                                int lane) {
    const int lrow = lane & 15;
    const int lk = (lane >> 4) * 8;
#pragma unroll
    for (int ks = 0; ks < 4; ks++) {
        const int k0 = ks * 16;
        unsigned ahi[2][4], alo[2][4];
#pragma unroll
        for (int mi = 0; mi < 2; mi++) {
            unsigned off = SWZ((unsigned)((wm0 + mi * 16 + lrow) * 128 + (k0 + lk) * 2));
            ldsm4(ahi[mi], abase + off);
            if (BHI) ldsm4(alo[mi], abase + 16384 + off);
        }
#pragma unroll
        for (int h = 0; h < 2; h++) {
            unsigned bb[2][4];
#pragma unroll
            for (int nb = 0; nb < 2; nb++) {
                unsigned off = SWZ((unsigned)((wn0 + (h * 2 + nb) * 16 + lrow) * 128 + (k0 + lk) * 2));
                ldsm4(bb[nb], bbase + off);
            }
#pragma unroll
            for (int mi = 0; mi < 2; mi++)
#pragma unroll
                for (int f = 0; f < 4; f++) {
                    int nb = f >> 1, r0 = f & 1;
                    float* d = acc[mi][h * 4 + f];
                    mma16816(d, ahi[mi], bb[nb][r0], bb[nb][r0 + 2]);
                    if (BHI) mma16816(d, alo[mi], bb[nb][r0], bb[nb][r0 + 2]);
                }
        }
    }
}

// ---------------- fused layer kernel ----------------
__global__ void __launch_bounds__(512, 1)
fused_layer(unsigned* __restrict__ ximg_hi, unsigned* __restrict__ ximg_lo,
            const float* __restrict__ z, SlotTab tab,
            const float* __restrict__ bl, const float* __restrict__ br,
            const float* __restrict__ b1,
            const float* __restrict__ ba0, const float* __restrict__ g0,
            const float* __restrict__ be0, const float* __restrict__ bb0,
            const float* __restrict__ ba1, const float* __restrict__ g1,
            const float* __restrict__ be1, const float* __restrict__ bb1,
            const float* __restrict__ b2, float bnscale,
            unsigned* __restrict__ himg_hi, unsigned* __restrict__ himg_lo,
            float* __restrict__ xout) {
    extern __shared__ char smem[];
    const unsigned sb = smem_u32(smem);
    const int tid = threadIdx.x, wid = tid >> 5, lane = tid & 31;
    const int bm0 = blockIdx.x * 128;
    const int wm0 = (wid >> 2) * 32;
    const int wn0 = (wid & 3) * 64;
    const int tr = lane >> 2;
    const int tc2 = (lane & 3) * 2;

    float acc[2][8][4];
#pragma unroll
    for (int a = 0; a < 2; a++)
#pragma unroll
        for (int b = 0; b < 8; b++)
#pragma unroll
            for (int c = 0; c < 4; c++) acc[a][b][c] = 0.f;

    auto zero_acc = [&]() {
#pragma unroll
        for (int a = 0; a < 2; a++)
#pragma unroll
            for (int b = 0; b < 8; b++)
#pragma unroll
                for (int c = 0; c < 4; c++) acc[a][b][c] = 0.f;
    };
    auto issue_slot = [&](int s) {
        if (s >= 64) return;
        const char* src = (const char*)tab.p[s];
        unsigned dstb = sb + FS_B + (unsigned)(s % 3) * 32768u;
#pragma unroll
        for (int i = 0; i < 4; i++) {
            int u = tid + i * 512;
            CPA(dstb + u * 16, src + u * 16);
        }
        CP_COMMIT();
    };
    auto run8 = [&](int s0) {
#pragma unroll 1
        for (int c = 0; c < 4; c++) {
            int s = s0 + c * 2;
            unsigned abase = sb + (unsigned)c * 32768u;
            cp_wait<2>();
            __syncthreads();
            mma_slot<true>(abase, sb + FS_B + (unsigned)(s % 3) * 32768u, acc, wm0, wn0, lane);
            __syncthreads();
            issue_slot(s + 3);
            cp_wait<2>();
            __syncthreads();
            mma_slot<false>(abase, sb + FS_B + (unsigned)((s + 1) % 3) * 32768u, acc, wm0, wn0, lane);
            __syncthreads();
            issue_slot(s + 4);
        }
    };
    auto conv_img = [&]() {   // acc -> smem A image (each warp its own chunk/rows)
        unsigned cb = (unsigned)(wn0 >> 6) * 32768u;
#pragma unroll
        for (int mi = 0; mi < 2; mi++)
#pragma unroll
            for (int ni = 0; ni < 8; ni++) {
                int lc = ni * 8 + tc2;
                float* d = acc[mi][ni];
                unsigned h0, l0, h1, l1;
                bsplit(d[0], h0, l0); bsplit(d[1], h1, l1);
                unsigned off = SWZ((unsigned)((wm0 + mi * 16 + tr) * 128 + lc * 2));
                *(unsigned*)(smem + cb + off) = h0 | (h1 << 16);
                *(unsigned*)(smem + cb + 16384 + off) = l0 | (l1 << 16);
                bsplit(d[2], h0, l0); bsplit(d[3], h1, l1);
                off = SWZ((unsigned)((wm0 + mi * 16 + 8 + tr) * 128 + lc * 2));
                *(unsigned*)(smem + cb + off) = h0 | (h1 << 16);
                *(unsigned*)(smem + cb + 16384 + off) = l0 | (l1 << 16);
            }
    };

    // ---- prologue: A image (ximg chunks 0-3) + first 3 B slots ----
#pragma unroll
    for (int c = 0; c < 4; c++) {
        const char* gh = (const char*)(ximg_hi + ((size_t)c * ROWSP + bm0) * 32);
        const char* gl = (const char*)(ximg_lo + ((size_t)c * ROWSP + bm0) * 32);
        unsigned cb = sb + (unsigned)c * 32768u;
#pragma unroll
        for (int i = 0; i < 2; i++) {
            int u = tid + i * 512;
            CPA(cb + u * 16, gh + u * 16);
            CPA(cb + 16384 + u * 16, gl + u * 16);
        }
    }
    CP_COMMIT();
    issue_slot(0); issue_slot(1); issue_slot(2);

    // ---- stage 1: cat ----
    run8(0);            // x half (K 0..255)
    // convert z (fp32 global) into IMG chunks 0-3
    {
#pragma unroll
        for (int i = 0; i < 16; i++) {
            int q = tid + i * 512;
            int r = q >> 6;           // 0..127
            int k4 = q & 63;          // float4 index in row
            int k = k4 * 4;
            float4 v = ld4(z + (size_t)(bm0 + r) * 256 + k);
            unsigned hx, lx, hy, ly, hz, lz, hw, lw;
            bsplit(v.x, hx, lx); bsplit(v.y, hy, ly);
            bsplit(v.z, hz, lz); bsplit(v.w, hw, lw);
            unsigned cb = (unsigned)(k >> 6) * 32768u;
            unsigned off = SWZ((unsigned)(r * 128 + (k & 63) * 2));
            *(uint2*)(smem + cb + off) = make_uint2(hx | (hy << 16), hz | (hw << 16));
            *(uint2*)(smem + cb + 16384 + off) = make_uint2(lx | (ly << 16), lz | (lw << 16));
        }
        __syncthreads();
    }
    run8(8);            // z half (K 256..511)
    // epi: + bl + br
#pragma unroll
    for (int mi = 0; mi < 2; mi++)
#pragma unroll
        for (int ni = 0; ni < 8; ni++) {
            int cg = wn0 + ni * 8 + tc2;
            float* d = acc[mi][ni];
            float a0 = bl[cg] + br[cg], a1 = bl[cg + 1] + br[cg + 1];
            d[0] += a0; d[1] += a1; d[2] += a0; d[3] += a1;
        }
    conv_img(); zero_acc(); __syncthreads();

    // ---- stage 2: w1 -> h0 (write himg) ----
    run8(16);
#pragma unroll
    for (int mi = 0; mi < 2; mi++)
#pragma unroll
        for (int ni = 0; ni < 8; ni++) {
            int cg = wn0 + ni * 8 + tc2;
            float* d = acc[mi][ni];
            d[0] += b1[cg]; d[1] += b1[cg + 1]; d[2] += b1[cg]; d[3] += b1[cg + 1];
            int ra = bm0 + wm0 + mi * 16 + tr;
            img_write(himg_hi, himg_lo, cg >> 6, ra, cg & 63, d[0], d[1]);
            img_write(himg_hi, himg_lo, cg >> 6, ra + 8, cg & 63, d[2], d[3]);
        }
    conv_img(); zero_acc(); __syncthreads();

    // ---- blocks ----
#pragma unroll 1
    for (int j = 0; j < 2; j++) {
        const float* ba = j ? ba1 : ba0;
        const float* gg = j ? g1 : g0;
        const float* be = j ? be1 : be0;
        const float* bb = j ? bb1 : bb0;
        // wa
        run8(24 + j * 16);
#pragma unroll
        for (int mi = 0; mi < 2; mi++)
#pragma unroll
            for (int ni = 0; ni < 8; ni++) {
                int cg = wn0 + ni * 8 + tc2;
                float* d = acc[mi][ni];
                float ga = gg[cg], gb = gg[cg + 1], ea = be[cg], eb = be[cg + 1];
                float a0 = ba[cg], a1 = ba[cg + 1];
                d[0] = fmaf(ga, fmaxf(d[0] + a0, 0.f) * bnscale, ea);
                d[1] = fmaf(gb, fmaxf(d[1] + a1, 0.f) * bnscale, eb);
                d[2] = fmaf(ga, fmaxf(d[2] + a0, 0.f) * bnscale, ea);
                d[3] = fmaf(gb, fmaxf(d[3] + a1, 0.f) * bnscale, eb);
            }
        conv_img(); zero_acc(); __syncthreads();
        // wb + residual
        run8(32 + j * 16);
#pragma unroll
        for (int mi = 0; mi < 2; mi++)
#pragma unroll
            for (int ni = 0; ni < 8; ni++) {
                int cg = wn0 + ni * 8 + tc2;
                float* d = acc[mi][ni];
                int ra = bm0 + wm0 + mi * 16 + tr;
                float2 ha = img_read(himg_hi, himg_lo, cg >> 6, ra, cg & 63);
                float2 hb = img_read(himg_hi, himg_lo, cg >> 6, ra + 8, cg & 63);
                d[0] += bb[cg] + ha.x; d[1] += bb[cg + 1] + ha.y;
                d[2] += bb[cg] + hb.x; d[3] += bb[cg + 1] + hb.y;
                if (j == 0) {
                    img_write(himg_hi, himg_lo, cg >> 6, ra, cg & 63, d[0], d[1]);
                    img_write(himg_hi, himg_lo, cg >> 6, ra + 8, cg & 63, d[2], d[3]);
                }
            }
        conv_img(); zero_acc(); __syncthreads();
    }

    // ---- stage 7: w2 + normalize + relu -> x ----
    run8(56);
#pragma unroll
    for (int mi = 0; mi < 2; mi++)
#pragma unroll
        for (int ni = 0; ni < 8; ni++) {
            int cg = wn0 + ni * 8 + tc2;
            float* d = acc[mi][ni];
            d[0] += b2[cg]; d[1] += b2[cg + 1]; d[2] += b2[cg]; d[3] += b2[cg + 1];
        }
    {
        float* rsum = (float*)(smem + FS_B);   // B ring is idle now
        float ps[2][2] = {{0.f, 0.f}, {0.f, 0.f}};
#pragma unroll
        for (int mi = 0; mi < 2; mi++)
#pragma unroll
            for (int ni = 0; ni < 8; ni++) {
                float* d = acc[mi][ni];
                ps[mi][0] = fmaf(d[0], d[0], fmaf(d[1], d[1], ps[mi][0]));
                ps[mi][1] = fmaf(d[2], d[2], fmaf(d[3], d[3], ps[mi][1]));
            }
#pragma unroll
        for (int mi = 0; mi < 2; mi++)
#pragma unroll
            for (int q = 0; q < 2; q++) {
                ps[mi][q] += __shfl_xor_sync(0xffffffffu, ps[mi][q], 1);
                ps[mi][q] += __shfl_xor_sync(0xffffffffu, ps[mi][q], 2);
            }
        __syncthreads();
        if ((lane & 3) == 0) {
            int cw = wn0 >> 6;
#pragma unroll
            for (int mi = 0; mi < 2; mi++) {
                rsum[(wm0 + mi * 16 + tr) * 4 + cw] = ps[mi][0];
                rsum[(wm0 + mi * 16 + 8 + tr) * 4 + cw] = ps[mi][1];
            }
        }
        __syncthreads();
#pragma unroll
        for (int mi = 0; mi < 2; mi++) {
            int r0 = wm0 + mi * 16 + tr;
            int r1 = r0 + 8;
            float s0 = rsum[r0 * 4] + rsum[r0 * 4 + 1] + rsum[r0 * 4 + 2] + rsum[r0 * 4 + 3];
            float s1 = rsum[r1 * 4] + rsum[r1 * 4 + 1] + rsum[r1 * 4 + 2] + rsum[r1 * 4 + 3];
            float c0 = 1.f / fmaxf(sqrtf(s0), 1e-12f);
            float c1 = 1.f / fmaxf(sqrtf(s1), 1e-12f);
#pragma unroll
            for (int ni = 0; ni < 8; ni++) {
                float* d = acc[mi][ni];
                d[0] = fmaxf(d[0] * c0, 0.f); d[1] = fmaxf(d[1] * c0, 0.f);
                d[2] = fmaxf(d[2] * c1, 0.f); d[3] = fmaxf(d[3] * c1, 0.f);
            }
        }
    }
    // write x fp32 + ximg (in place; rows disjoint across CTAs)
#pragma unroll
    for (int mi = 0; mi < 2; mi++)
#pragma unroll
        for (int ni = 0; ni < 8; ni++) {
            int cg = wn0 + ni * 8 + tc2;
            int ra = bm0 + wm0 + mi * 16 + tr;
            int rb = ra + 8;
            float* d = acc[mi][ni];
            img_write(ximg_hi, ximg_lo, cg >> 6, ra, cg & 63, d[0], d[1]);
            img_write(ximg_hi, ximg_lo, cg >> 6, rb, cg & 63, d[2], d[3]);
            *(float2*)(xout + (size_t)ra * 256 + cg) = make_float2(d[0], d[1]);
            *(float2*)(xout + (size_t)rb * 256 + cg) = make_float2(d[2], d[3]);
        }
}

// ---------------- standalone GEMM (post layer) — from R5 ----------------
template <int KTOT, int EPI, int OMODE>
__global__ void __launch_bounds__(512, 1)
mma_gemm(const unsigned* __restrict__ Aimg_hi, const unsigned* __restrict__ Aimg_lo,
         const uint4* __restrict__ Whi, const uint4* __restrict__ Wlo,
         const float* __restrict__ bias, float* __restrict__ Of32, int M) {
    extern __shared__ char smem[];
    const unsigned sb = smem_u32(smem);
    const int tid = threadIdx.x, wid = tid >> 5, lane = tid & 31;
    const int bm0 = blockIdx.x * 128;
    constexpr int NCHUNK = KTOT / 64;

    if (tid < 256) ((float*)(smem + PBASE))[tid] = bias[tid];

    const int wm0 = (wid >> 2) * 32;
    const int wn0 = (wid & 3) * 64;
    const int lrow = lane & 15;
    const int lk = (lane >> 4) * 8;

    float acc[2][8][4];
#pragma unroll
    for (int a = 0; a < 2; a++)
#pragma unroll
        for (int b = 0; b < 8; b++)
#pragma unroll
            for (int c = 0; c < 4; c++) acc[a][b][c] = 0.f;

    auto issue = [&](int c, int st) {
        unsigned ab = sb + st * ABUF;
        unsigned bb = sb + BBASE + st * BBUF;
        const char* wh = (const char*)(Whi + (size_t)c * 2048);
        const char* wl = (const char*)(Wlo + (size_t)c * 2048);
#pragma unroll
        for (int i = 0; i < 4; i++) {
            int u = tid + i * 512;
            CPA(bb + u * 16, wh + u * 16);
            CPA(bb + 32768 + u * 16, wl + u * 16);
        }
        const char* ih = (const char*)(Aimg_hi + ((size_t)c * ROWSP + bm0) * 32);
        const char* il = (const char*)(Aimg_lo + ((size_t)c * ROWSP + bm0) * 32);
#pragma unroll
        for (int i = 0; i < 2; i++) {
            int u = tid + i * 512;
            CPA(ab + u * 16, ih + u * 16);
            CPA(ab + 16384 + u * 16, il + u * 16);
        }
    };

    issue(0, 0);
    CP_COMMIT();
    for (int c = 0; c < NCHUNK; c++) {
        int st = c & 1;
        if (c + 1 < NCHUNK) { issue(c + 1, st ^ 1); CP_COMMIT(); cp_wait<1>(); }
        else cp_wait<0>();
        __syncthreads();
        unsigned abase = sb + st * ABUF;
        unsigned bbase = sb + BBASE + st * BBUF;
#pragma unroll
        for (int ks = 0; ks < 4; ks++) {
            const int k0 = ks * 16;
            unsigned ahi[2][4], alo[2][4];
#pragma unroll
            for (int mi = 0; mi < 2; mi++) {
                unsigned off = SWZ((unsigned)((wm0 + mi * 16 + lrow) * 128 + (k0 + lk) * 2));
                ldsm4(ahi[mi], abase + off);
                ldsm4(alo[mi], abase + 16384 + off);
            }
#pragma unroll
            for (int h = 0; h < 2; h++) {
                unsigned bhi[2][4], blo[2][4];
#pragma unroll
                for (int nb = 0; nb < 2; nb++) {
                    unsigned off = SWZ((unsigned)((wn0 + (h * 2 + nb) * 16 + lrow) * 128 + (k0 + lk) * 2));
                    ldsm4(bhi[nb], bbase + off);
                    ldsm4(blo[nb], bbase + 32768 + off);
                }
#pragma unroll
                for (int mi = 0; mi < 2; mi++)
#pragma unroll
                    for (int f = 0; f < 4; f++) {
                        int nb = f >> 1, r0 = f & 1;
                        float* d = acc[mi][h * 4 + f];
                        mma16816(d, ahi[mi], bhi[nb][r0], bhi[nb][r0 + 2]);
                        mma16816(d, ahi[mi], blo[nb][r0], blo[nb][r0 + 2]);
                        mma16816(d, alo[mi], bhi[nb][r0], bhi[nb][r0 + 2]);
                    }
            }
        }
        __syncthreads();
    }

    const float* sbias = (const float*)(smem + PBASE);
    const int tr = lane >> 2;
    const int tc2 = (lane & 3) * 2;
#pragma unroll
    for (int mi = 0; mi < 2; mi++)
#pragma unroll
        for (int ni = 0; ni < 8; ni++) {
            int cg = wn0 + ni * 8 + tc2;
            int ra = bm0 + wm0 + mi * 16 + tr;
            int rb = ra + 8;
            float* d = acc[mi][ni];
            float v0 = d[0] + sbias[cg], v1 = d[1] + sbias[cg + 1];
            float v2 = d[2] + sbias[cg], v3 = d[3] + sbias[cg + 1];
            if (ra < M) *(float2*)(Of32 + (size_t)ra * 256 + cg) = make_float2(v0, v1);
            if (rb < M) *(float2*)(Of32 + (size_t)rb * 256 + cg) = make_float2(v2, v3);
        }
}

// ---------------- head ----------------
__global__ void head_kernel(const float* __restrict__ h, const float* __restrict__ W2,
                            const float* __restrict__ b2, float* __restrict__ out) {
    __shared__ float sW[256 * NCLS];
    __shared__ float sb[NCLS];
    int tid = threadIdx.x;
    for (int i = tid; i < 256 * NCLS; i += 256) sW[i] = W2[i];
    if (tid < NCLS) sb[tid] = b2[tid];
    __syncthreads();

    int wid = tid >> 5, lane = tid & 31;
    int r = blockIdx.x * 8 + wid;
    if (r >= NN) return;

    const float4* rp = (const float4*)(h + (size_t)r * DD);
    float4 q0 = rp[lane * 2];
    float4 q1 = rp[lane * 2 + 1];
    float hreg[8] = {q0.x, q0.y, q0.z, q0.w, q1.x, q1.y, q1.z, q1.w};

    int c0 = lane;
    int c1 = lane + 32;
    int c1m = (c1 < NCLS) ? c1 : (NCLS - 1);
    float acc0 = sb[c0];
    float acc1 = sb[c1m];
#pragma unroll
    for (int e = 0; e < 8; e++) {
        for (int l = 0; l < 32; l++) {
            float hv = __shfl_sync(0xffffffffu, hreg[e], l);
            int k = l * 8 + e;
            acc0 = fmaf(hv, sW[k * NCLS + c0], acc0);
            acc1 = fmaf(hv, sW[k * NCLS + c1m], acc1);
        }
    }
    float m = fmaxf(acc0, (c1 < NCLS) ? acc1 : -3.4e38f);
#pragma unroll
    for (int o = 16; o > 0; o >>= 1) m = fmaxf(m, __shfl_xor_sync(0xffffffffu, m, o));
    float es = expf(acc0 - m) + ((c1 < NCLS) ? expf(acc1 - m) : 0.f);
#pragma unroll
    for (int o = 16; o > 0; o >>= 1) es += __shfl_xor_sync(0xffffffffu, es, o);
    float lse = m + logf(es);
    out[(size_t)r * NCLS + c0] = acc0 - lse;
    if (c1 < NCLS) out[(size_t)r * NCLS + c1] = acc1 - lse;
}

// ---------------- host orchestration ----------------
extern "C" void kernel_launch(void* const* d_in, const int* in_sizes, int n_in,
                              void* d_out, int out_size) {
    const float* x_in      = (const float*)d_in[0];
    const int* ei          = (const int*)d_in[1];
    const float* lin_l_W   = (const float*)d_in[2];
    const float* lin_l_b   = (const float*)d_in[3];
    const float* lin_r_W   = (const float*)d_in[4];
    const float* lin_r_b   = (const float*)d_in[5];
    const float* mlp_W1    = (const float*)d_in[6];
    const float* mlp_b1    = (const float*)d_in[7];
    const float* blk_Wa    = (const float*)d_in[8];
    const float* blk_ba    = (const float*)d_in[9];
    const float* blk_gamma = (const float*)d_in[10];
    const float* blk_beta  = (const float*)d_in[11];
    const float* blk_Wb    = (const float*)d_in[12];
    const float* blk_bb    = (const float*)d_in[13];
    const float* mlp_W2    = (const float*)d_in[14];
    const float* mlp_b2    = (const float*)d_in[15];
    const float* post_W1   = (const float*)d_in[16];
    const float* post_b1   = (const float*)d_in[17];
    const float* post_W2   = (const float*)d_in[18];
    const float* post_b2   = (const float*)d_in[19];
    float* out = (float*)d_out;

    float *xp, *zp, *pp;
    uint4 *whi, *wlo;
    unsigned *xih, *xil, *hih, *hil;
    int *cnti, *offp, *curp, *csrp;
    cudaGetSymbolAddress((void**)&xp, g_x);
    cudaGetSymbolAddress((void**)&zp, g_z);
    cudaGetSymbolAddress((void**)&pp, g_p);
    cudaGetSymbolAddress((void**)&whi, g_whi4);
    cudaGetSymbolAddress((void**)&wlo, g_wlo4);
    cudaGetSymbolAddress((void**)&xih, g_ximg_hi);
    cudaGetSymbolAddress((void**)&xil, g_ximg_lo);
    cudaGetSymbolAddress((void**)&hih, g_himg_hi);
    cudaGetSymbolAddress((void**)&hil, g_himg_lo);
    cudaGetSymbolAddress((void**)&cnti, g_cnti);
    cudaGetSymbolAddress((void**)&offp, g_off);
    cudaGetSymbolAddress((void**)&curp, g_cur);
    cudaGetSymbolAddress((void**)&csrp, g_csr);
    unsigned short* hiu = (unsigned short*)whi;
    unsigned short* lou = (unsigned short*)wlo;

    cudaFuncSetAttribute(fused_layer, cudaFuncAttributeMaxDynamicSharedMemorySize, FSMEM);
    cudaFuncSetAttribute(mma_gemm<256, 0, 2>, cudaFuncAttributeMaxDynamicSharedMemorySize, SMEM_SZ);

    const float bnscale = rsqrtf(1.0f + 1e-5f);
    const int* src = ei;
    const int* dst = ei + EE;

    // weight prep
    prep_w<<<3 * 256, 256>>>(lin_l_W, 0, 8, hiu, lou);
    prep_w<<<3 * 256, 256>>>(lin_r_W, 4, 8, hiu, lou);
    prep_w<<<3 * 256, 256>>>(mlp_W1, 24, 4, hiu, lou);
    prep_w<<<6 * 256, 256>>>(blk_Wa, 36, 4, hiu, lou);
    prep_w<<<6 * 256, 256>>>(blk_Wb, 60, 4, hiu, lou);
    prep_w<<<3 * 256, 256>>>(mlp_W2, 84, 4, hiu, lou);
    prep_w<<<1 * 256, 256>>>(post_W1, 96, 4, hiu, lou);

    // x image + CSR build
    split_img<<<(NN * 128 + 255) / 256, 256>>>(x_in, xih, xil);
    cudaMemsetAsync(cnti, 0, NN * sizeof(int));
    count_int<<<(EE + 255) / 256, 256>>>(dst, cnti);
    scan_kernel<<<1, 1024>>>(cnti, offp, curp);
    fill_kernel<<<(EE + 255) / 256, 256>>>(src, dst, curp, csrp);

    for (int i = 0; i < NLAYER; i++) {
        const float* x_prev = (i == 0) ? x_in : xp;
        gather_kernel<<<(NN + 7) / 8, 256>>>(x_prev, offp, csrp, zp);

        SlotTab tab;
        int s = 0;
        auto push = [&](int base, int n) {
            for (int c = 0; c < n; c++) {
                tab.p[s++] = whi + (size_t)(base + c) * 2048;
                tab.p[s++] = wlo + (size_t)(base + c) * 2048;
            }
        };
        push(i * 8, 8);                 // cat (lin_l 0-3, lin_r 4-7)
        push(24 + i * 4, 4);            // w1
        push(36 + (2 * i) * 4, 4);      // wa0
        push(60 + (2 * i) * 4, 4);      // wb0
        push(36 + (2 * i + 1) * 4, 4);  // wa1
        push(60 + (2 * i + 1) * 4, 4);  // wb1
        push(84 + i * 4, 4);            // w2

        size_t bo0 = ((size_t)i * 2) * 256, bo1 = ((size_t)i * 2 + 1) * 256;
        fused_layer<<<NB, 512, FSMEM>>>(
            xih, xil, zp, tab,
            lin_l_b + (size_t)i * 256, lin_r_b + (size_t)i * 256,
            mlp_b1 + (size_t)i * 256,
            blk_ba + bo0, blk_gamma + bo0, blk_beta + bo0, blk_bb + bo0,
            blk_ba + bo1, blk_gamma + bo1, blk_beta + bo1, blk_bb + bo1,
            mlp_b2 + (size_t)i * 256, bnscale,
            hih, hil, xp);
    }

    // post MLP + log_softmax
    mma_gemm<256, 0, 2><<<NB, 512, SMEM_SZ>>>(
        xih, xil, whi + (size_t)96 * 2048, wlo + (size_t)96 * 2048, post_b1, pp, NN);
    head_kernel<<<(NN + 7) / 8, 256>>>(pp, post_W2, post_b2, out);
}

// round 7
// speedup vs baseline: 2.2227x; 1.0412x over previous
#include <cuda_runtime.h>
#include <cuda_bf16.h>
#include <math.h>

#define NN 50000
#define ROWSP 50048
#define DD 256
#define EE 800000
#define NCLS 47
#define NLAYER 3
#define NB 391

#define SWZ(x) ((x) ^ (((x) >> 3) & 0x70))

// ---- standalone (post) gemm smem layout ----
#define ABUF 32768
#define BBASE 65536
#define BBUF 65536
#define PBASE 196608
#define SMEM_SZ 201728

// ---- fused kernel smem layout ----
#define FS_B 131072
#define FSMEM 229376   // 128KB A-image + 3x32KB B ring

// ---------------- device scratch ----------------
__device__ float g_p[ROWSP * DD];
__device__ uint4 g_whi4[100 * 2048];
__device__ uint4 g_wlo4[100 * 2048];
__device__ unsigned g_ximg_hi[4 * ROWSP * 32];
__device__ unsigned g_ximg_lo[4 * ROWSP * 32];
__device__ unsigned g_zimg_hi[4 * ROWSP * 32];
__device__ unsigned g_zimg_lo[4 * ROWSP * 32];
__device__ unsigned g_himg_hi[4 * ROWSP * 32];
__device__ unsigned g_himg_lo[4 * ROWSP * 32];
__device__ int g_cnti[NN];
__device__ int g_off[NN + 1];
__device__ int g_cur[NN];
__device__ int g_csr[EE];

struct SlotTab { const uint4* p[64]; };

static __device__ __forceinline__ unsigned smem_u32(const void* p) {
    unsigned a;
    asm("{ .reg .u64 t; cvta.to.shared.u64 t, %1; cvt.u32.u64 %0, t; }" : "=r"(a) : "l"(p));
    return a;
}
static __device__ __forceinline__ void ldsm4(unsigned r[4], unsigned addr) {
    asm volatile("ldmatrix.sync.aligned.m8n8.x4.shared.b16 {%0,%1,%2,%3}, [%4];"
                 : "=r"(r[0]), "=r"(r[1]), "=r"(r[2]), "=r"(r[3]) : "r"(addr));
}
static __device__ __forceinline__ void mma16816(float d[4], const unsigned a[4],
                                                unsigned b0, unsigned b1) {
    asm volatile(
        "mma.sync.aligned.m16n8k16.row.col.f32.bf16.bf16.f32 "
        "{%0,%1,%2,%3}, {%4,%5,%6,%7}, {%8,%9}, {%0,%1,%2,%3};"
        : "+f"(d[0]), "+f"(d[1]), "+f"(d[2]), "+f"(d[3])
        : "r"(a[0]), "r"(a[1]), "r"(a[2]), "r"(a[3]), "r"(b0), "r"(b1));
}
#define CPA(dst, src) \
    asm volatile("cp.async.cg.shared.global [%0], [%1], 16;" :: "r"(dst), "l"(src) : "memory")
#define CP_COMMIT() asm volatile("cp.async.commit_group;" ::: "memory")
template <int N>
static __device__ __forceinline__ void cp_wait() {
    asm volatile("cp.async.wait_group %0;" :: "n"(N) : "memory");
}

static __device__ __forceinline__ void bsplit(float v, unsigned& h, unsigned& l) {
    __nv_bfloat16 hb = __float2bfloat16(v);
    h = __bfloat16_as_ushort(hb);
    l = __bfloat16_as_ushort(__float2bfloat16(v - __bfloat162float(hb)));
}
static __device__ __forceinline__ unsigned img_idx(int chunk, int row, int lc) {
    return ((unsigned)chunk * ROWSP + (unsigned)row) * 32u +
           ((((unsigned)(lc * 2)) ^ (((unsigned)row & 7u) << 4)) >> 2);
}
static __device__ __forceinline__ void img_write(unsigned* __restrict__ hi,
                                                 unsigned* __restrict__ lo, int chunk,
                                                 int row, int lc, float v0, float v1) {
    unsigned h0, l0, h1, l1;
    bsplit(v0, h0, l0);
    bsplit(v1, h1, l1);
    unsigned idx = img_idx(chunk, row, lc);
    hi[idx] = h0 | (h1 << 16);
    lo[idx] = l0 | (l1 << 16);
}
static __device__ __forceinline__ float2 img_read(const unsigned* __restrict__ hi,
                                                  const unsigned* __restrict__ lo, int chunk,
                                                  int row, int lc) {
    unsigned idx = img_idx(chunk, row, lc);
    unsigned h = hi[idx], l = lo[idx];
    float x0 = __bfloat162float(__ushort_as_bfloat16((unsigned short)(h & 0xffff))) +
               __bfloat162float(__ushort_as_bfloat16((unsigned short)(l & 0xffff)));
    float x1 = __bfloat162float(__ushort_as_bfloat16((unsigned short)(h >> 16))) +
               __bfloat162float(__ushort_as_bfloat16((unsigned short)(l >> 16)));
    return make_float2(x0, x1);
}

// ---------------- setup: weight prep + x image + cnti zero (ONE launch) ----------------
__global__ void setup_kernel(const float* __restrict__ linl, const float* __restrict__ linr,
                             const float* __restrict__ w1, const float* __restrict__ wa,
                             const float* __restrict__ wb, const float* __restrict__ w2,
                             const float* __restrict__ post, const float* __restrict__ X,
                             unsigned short* __restrict__ dhi, unsigned short* __restrict__ dlo,
                             unsigned* __restrict__ xih, unsigned* __restrict__ xil,
                             int* __restrict__ cnti) {
    int b = blockIdx.x;
    if (b < 6400) {
        int idx = b * 256 + threadIdx.x;
        int m = idx >> 16;
        int rem = idx & 65535;
        int n = rem & 255, k = rem >> 8;
        const float* W;
        int chunk;
        if (m < 3)       { W = linl + (size_t)m * 65536;       chunk = 0  + m * 8 + (k >> 6); }
        else if (m < 6)  { W = linr + (size_t)(m - 3) * 65536; chunk = 4  + (m - 3) * 8 + (k >> 6); }
        else if (m < 9)  { W = w1 + (size_t)(m - 6) * 65536;   chunk = 24 + (m - 6) * 4 + (k >> 6); }
        else if (m < 15) { W = wa + (size_t)(m - 9) * 65536;   chunk = 36 + (m - 9) * 4 + (k >> 6); }
        else if (m < 21) { W = wb + (size_t)(m - 15) * 65536;  chunk = 60 + (m - 15) * 4 + (k >> 6); }
        else if (m < 24) { W = w2 + (size_t)(m - 21) * 65536;  chunk = 84 + (m - 21) * 4 + (k >> 6); }
        else             { W = post;                           chunk = 96 + (k >> 6); }
        float v = W[(size_t)k * 256 + n];
        unsigned h, l;
        bsplit(v, h, l);
        unsigned off = (unsigned)chunk * 32768u + SWZ((unsigned)(n * 128 + (k & 63) * 2));
        dhi[off >> 1] = (unsigned short)h;
        dlo[off >> 1] = (unsigned short)l;
    } else if (b < 31400) {
        int idx = (b - 6400) * 256 + threadIdx.x;   // < NN*128 exactly
        int row = idx >> 7, p = idx & 127;
        float v0 = X[(size_t)row * 256 + p * 2];
        float v1 = X[(size_t)row * 256 + p * 2 + 1];
        img_write(xih, xil, (p * 2) >> 6, row, (p * 2) & 63, v0, v1);
    } else {
        int i = (b - 31400) * 256 + threadIdx.x;
        if (i < NN) cnti[i] = 0;
    }
}

// ---------------- CSR build ----------------
__global__ void count_int(const int* __restrict__ dst, int* __restrict__ cnt) {
    int e = blockIdx.x * 256 + threadIdx.x;
    if (e < EE) atomicAdd(&cnt[dst[e]], 1);
}
__global__ void scan_kernel(const int* __restrict__ cnt, int* __restrict__ off,
                            int* __restrict__ cur) {
    __shared__ int sdata[1024];
    __shared__ int carry;
    int tid = threadIdx.x;
    if (tid == 0) { carry = 0; off[0] = 0; }
    __syncthreads();
    for (int base = 0; base < NN; base += 1024) {
        int i = base + tid;
        int v = (i < NN) ? cnt[i] : 0;
        sdata[tid] = v;
        __syncthreads();
        for (int o = 1; o < 1024; o <<= 1) {
            int t = (tid >= o) ? sdata[tid - o] : 0;
            __syncthreads();
            sdata[tid] += t;
            __syncthreads();
        }
        int incl = sdata[tid] + carry;
        if (i < NN) { off[i + 1] = incl; cur[i] = incl - v; }
        __syncthreads();
        if (tid == 1023) carry = incl;
        __syncthreads();
    }
}
__global__ void fill_kernel(const int* __restrict__ src, const int* __restrict__ dst,
                            int* __restrict__ cur, int* __restrict__ csr) {
    int e = blockIdx.x * 256 + threadIdx.x;
    if (e < EE) {
        int p = atomicAdd(&cur[dst[e]], 1);
        csr[p] = src[e];
    }
}

// ---------------- gather: zimg[d] = mean over in-edges of ximg[src] ----------------
// warp per (node, 64-col chunk); reads hi/lo images, writes z image.
__global__ void gather_img(const unsigned* __restrict__ xih, const unsigned* __restrict__ xil,
                           const int* __restrict__ off, const int* __restrict__ csr,
                           unsigned* __restrict__ zih, unsigned* __restrict__ zil) {
    int w = (blockIdx.x * 256 + threadIdx.x) >> 5;
    int d = w >> 2, c = w & 3;
    if (d >= NN) return;
    int lane = threadIdx.x & 31;
    int lc = lane * 2;
    int b = off[d], e = off[d + 1];
    float s0 = 0.f, s1 = 0.f;
    int j = b;
    for (; j + 1 < e; j += 2) {
        int r0 = csr[j], r1 = csr[j + 1];
        float2 v0 = img_read(xih, xil, c, r0, lc);
        float2 v1 = img_read(xih, xil, c, r1, lc);
        s0 += v0.x + v1.x;
        s1 += v0.y + v1.y;
    }
    if (j < e) {
        float2 v = img_read(xih, xil, c, csr[j], lc);
        s0 += v.x;
        s1 += v.y;
    }
    float iv = 1.f / fmaxf((float)(e - b), 1.f);
    img_write(zih, zil, c, d, lc, s0 * iv, s1 * iv);
}

// ---- fused-layer helpers ----
template <bool BHI>
static __device__ __forceinline__ void mma_slot(unsigned abase, unsigned bbase,
                                                float (&acc)[2][8][4], int wm0, int wn0,
                                                int lane) {
    const int lrow = lane & 15;
    const int lk = (lane >> 4) * 8;
#pragma unroll
    for (int ks = 0; ks < 4; ks++) {
        const int k0 = ks * 16;
        unsigned ahi[2][4], alo[2][4];
#pragma unroll
        for (int mi = 0; mi < 2; mi++) {
            unsigned off = SWZ((unsigned)((wm0 + mi * 16 + lrow) * 128 + (k0 + lk) * 2));
            ldsm4(ahi[mi], abase + off);
            if (BHI) ldsm4(alo[mi], abase + 16384 + off);
        }
#pragma unroll
        for (int h = 0; h < 2; h++) {
            unsigned bb[2][4];
#pragma unroll
            for (int nb = 0; nb < 2; nb++) {
                unsigned off = SWZ((unsigned)((wn0 + (h * 2 + nb) * 16 + lrow) * 128 + (k0 + lk) * 2));
                ldsm4(bb[nb], bbase + off);
            }
#pragma unroll
            for (int mi = 0; mi < 2; mi++)
#pragma unroll
                for (int f = 0; f < 4; f++) {
                    int nb = f >> 1, r0 = f & 1;
                    float* d = acc[mi][h * 4 + f];
                    mma16816(d, ahi[mi], bb[nb][r0], bb[nb][r0 + 2]);
                    if (BHI) mma16816(d, alo[mi], bb[nb][r0], bb[nb][r0 + 2]);
                }
        }
    }
}

// ---------------- fused layer kernel ----------------
__global__ void __launch_bounds__(512, 1)
fused_layer(unsigned* __restrict__ ximg_hi, unsigned* __restrict__ ximg_lo,
            const unsigned* __restrict__ zimg_hi, const unsigned* __restrict__ zimg_lo,
            SlotTab tab,
            const float* __restrict__ bl, const float* __restrict__ br,
            const float* __restrict__ b1,
            const float* __restrict__ ba0, const float* __restrict__ g0,
            const float* __restrict__ be0, const float* __restrict__ bb0,
            const float* __restrict__ ba1, const float* __restrict__ g1,
            const float* __restrict__ be1, const float* __restrict__ bb1,
            const float* __restrict__ b2, float bnscale,
            unsigned* __restrict__ himg_hi, unsigned* __restrict__ himg_lo) {
    extern __shared__ char smem[];
    const unsigned sb = smem_u32(smem);
    const int tid = threadIdx.x, wid = tid >> 5, lane = tid & 31;
    const int bm0 = blockIdx.x * 128;
    const int wm0 = (wid >> 2) * 32;
    const int wn0 = (wid & 3) * 64;
    const int tr = lane >> 2;
    const int tc2 = (lane & 3) * 2;

    float acc[2][8][4];
    auto zero_acc = [&]() {
#pragma unroll
        for (int a = 0; a < 2; a++)
#pragma unroll
            for (int b = 0; b < 8; b++)
#pragma unroll
                for (int c = 0; c < 4; c++) acc[a][b][c] = 0.f;
    };
    zero_acc();

    auto issue_B = [&](int s) {   // no commit
        if (s >= 64) return;
        const char* src = (const char*)tab.p[s];
        unsigned dstb = sb + FS_B + (unsigned)(s % 3) * 32768u;
#pragma unroll
        for (int i = 0; i < 4; i++) {
            int u = tid + i * 512;
            CPA(dstb + u * 16, src + u * 16);
        }
    };
    auto issue_z = [&](int c) {   // zimg chunk c -> A chunk c (no commit)
        const char* gh = (const char*)(zimg_hi + ((size_t)c * ROWSP + bm0) * 32);
        const char* gl = (const char*)(zimg_lo + ((size_t)c * ROWSP + bm0) * 32);
        unsigned cb = sb + (unsigned)c * 32768u;
#pragma unroll
        for (int i = 0; i < 2; i++) {
            int u = tid + i * 512;
            CPA(cb + u * 16, gh + u * 16);
            CPA(cb + 16384 + u * 16, gl + u * 16);
        }
    };
    auto run_stage = [&](int s0, bool loadz) {
#pragma unroll 1
        for (int c = 0; c < 4; c++) {
            int s = s0 + c * 2;
            unsigned abase = sb + (unsigned)c * 32768u;
            cp_wait<2>();
            __syncthreads();
            mma_slot<true>(abase, sb + FS_B + (unsigned)(s % 3) * 32768u, acc, wm0, wn0, lane);
            __syncthreads();
            issue_B(s + 3);
            CP_COMMIT();
            cp_wait<2>();
            __syncthreads();
            mma_slot<false>(abase, sb + FS_B + (unsigned)((s + 1) % 3) * 32768u, acc, wm0, wn0, lane);
            __syncthreads();
            issue_B(s + 4);
            if (loadz) issue_z(c);
            CP_COMMIT();
        }
    };
    auto conv_img = [&]() {   // acc -> smem A image
        unsigned cb = (unsigned)(wn0 >> 6) * 32768u;
#pragma unroll
        for (int mi = 0; mi < 2; mi++)
#pragma unroll
            for (int ni = 0; ni < 8; ni++) {
                int lc = ni * 8 + tc2;
                float* d = acc[mi][ni];
                unsigned h0, l0, h1, l1;
                bsplit(d[0], h0, l0); bsplit(d[1], h1, l1);
                unsigned off = SWZ((unsigned)((wm0 + mi * 16 + tr) * 128 + lc * 2));
                *(unsigned*)(smem + cb + off) = h0 | (h1 << 16);
                *(unsigned*)(smem + cb + 16384 + off) = l0 | (l1 << 16);
                bsplit(d[2], h0, l0); bsplit(d[3], h1, l1);
                off = SWZ((unsigned)((wm0 + mi * 16 + 8 + tr) * 128 + lc * 2));
                *(unsigned*)(smem + cb + off) = h0 | (h1 << 16);
                *(unsigned*)(smem + cb + 16384 + off) = l0 | (l1 << 16);
            }
    };

    // ---- prologue: x image chunks + first 3 B slots ----
#pragma unroll
    for (int c = 0; c < 4; c++) {
        const char* gh = (const char*)(ximg_hi + ((size_t)c * ROWSP + bm0) * 32);
        const char* gl = (const char*)(ximg_lo + ((size_t)c * ROWSP + bm0) * 32);
        unsigned cb = sb + (unsigned)c * 32768u;
#pragma unroll
        for (int i = 0; i < 2; i++) {
            int u = tid + i * 512;
            CPA(cb + u * 16, gh + u * 16);
            CPA(cb + 16384 + u * 16, gl + u * 16);
        }
    }
    CP_COMMIT();
    issue_B(0); CP_COMMIT();
    issue_B(1); CP_COMMIT();
    issue_B(2); CP_COMMIT();

    // ---- stage 1: cat (x half; z prefetched into A chunks as they free) ----
    run_stage(0, true);
    run_stage(8, false);   // z half
#pragma unroll
    for (int mi = 0; mi < 2; mi++)
#pragma unroll
        for (int ni = 0; ni < 8; ni++) {
            int cg = wn0 + ni * 8 + tc2;
            float* d = acc[mi][ni];
            float a0 = bl[cg] + br[cg], a1 = bl[cg + 1] + br[cg + 1];
            d[0] += a0; d[1] += a1; d[2] += a0; d[3] += a1;
        }
    conv_img(); zero_acc(); __syncthreads();

    // ---- stage 2: w1 -> h0 (write himg) ----
    run_stage(16, false);
#pragma unroll
    for (int mi = 0; mi < 2; mi++)
#pragma unroll
        for (int ni = 0; ni < 8; ni++) {
            int cg = wn0 + ni * 8 + tc2;
            float* d = acc[mi][ni];
            d[0] += b1[cg]; d[1] += b1[cg + 1]; d[2] += b1[cg]; d[3] += b1[cg + 1];
            int ra = bm0 + wm0 + mi * 16 + tr;
            img_write(himg_hi, himg_lo, cg >> 6, ra, cg & 63, d[0], d[1]);
            img_write(himg_hi, himg_lo, cg >> 6, ra + 8, cg & 63, d[2], d[3]);
        }
    conv_img(); zero_acc(); __syncthreads();

    // ---- blocks ----
#pragma unroll 1
    for (int j = 0; j < 2; j++) {
        const float* ba = j ? ba1 : ba0;
        const float* gg = j ? g1 : g0;
        const float* be = j ? be1 : be0;
        const float* bb = j ? bb1 : bb0;
        run_stage(24 + j * 16, false);
#pragma unroll
        for (int mi = 0; mi < 2; mi++)
#pragma unroll
            for (int ni = 0; ni < 8; ni++) {
                int cg = wn0 + ni * 8 + tc2;
                float* d = acc[mi][ni];
                float ga = gg[cg], gb = gg[cg + 1], ea = be[cg], eb = be[cg + 1];
                float a0 = ba[cg], a1 = ba[cg + 1];
                d[0] = fmaf(ga, fmaxf(d[0] + a0, 0.f) * bnscale, ea);
                d[1] = fmaf(gb, fmaxf(d[1] + a1, 0.f) * bnscale, eb);
                d[2] = fmaf(ga, fmaxf(d[2] + a0, 0.f) * bnscale, ea);
                d[3] = fmaf(gb, fmaxf(d[3] + a1, 0.f) * bnscale, eb);
            }
        conv_img(); zero_acc(); __syncthreads();
        run_stage(32 + j * 16, false);
#pragma unroll
        for (int mi = 0; mi < 2; mi++)
#pragma unroll
            for (int ni = 0; ni < 8; ni++) {
                int cg = wn0 + ni * 8 + tc2;
                float* d = acc[mi][ni];
                int ra = bm0 + wm0 + mi * 16 + tr;
                float2 ha = img_read(himg_hi, himg_lo, cg >> 6, ra, cg & 63);
                float2 hb = img_read(himg_hi, himg_lo, cg >> 6, ra + 8, cg & 63);
                d[0] += bb[cg] + ha.x; d[1] += bb[cg + 1] + ha.y;
                d[2] += bb[cg] + hb.x; d[3] += bb[cg + 1] + hb.y;
                if (j == 0) {
                    img_write(himg_hi, himg_lo, cg >> 6, ra, cg & 63, d[0], d[1]);
                    img_write(himg_hi, himg_lo, cg >> 6, ra + 8, cg & 63, d[2], d[3]);
                }
            }
        conv_img(); zero_acc(); __syncthreads();
    }

    // ---- stage 7: w2 + normalize + relu -> ximg ----
    run_stage(56, false);
#pragma unroll
    for (int mi = 0; mi < 2; mi++)
#pragma unroll
        for (int ni = 0; ni < 8; ni++) {
            int cg = wn0 + ni * 8 + tc2;
            float* d = acc[mi][ni];
            d[0] += b2[cg]; d[1] += b2[cg + 1]; d[2] += b2[cg]; d[3] += b2[cg + 1];
        }
    {
        float* rsum = (float*)(smem + FS_B);
        float ps[2][2] = {{0.f, 0.f}, {0.f, 0.f}};
#pragma unroll
        for (int mi = 0; mi < 2; mi++)
#pragma unroll
            for (int ni = 0; ni < 8; ni++) {
                float* d = acc[mi][ni];
                ps[mi][0] = fmaf(d[0], d[0], fmaf(d[1], d[1], ps[mi][0]));
                ps[mi][1] = fmaf(d[2], d[2], fmaf(d[3], d[3], ps[mi][1]));
            }
#pragma unroll
        for (int mi = 0; mi < 2; mi++)
#pragma unroll
            for (int q = 0; q < 2; q++) {
                ps[mi][q] += __shfl_xor_sync(0xffffffffu, ps[mi][q], 1);
                ps[mi][q] += __shfl_xor_sync(0xffffffffu, ps[mi][q], 2);
            }
        __syncthreads();
        if ((lane & 3) == 0) {
            int cw = wn0 >> 6;
#pragma unroll
            for (int mi = 0; mi < 2; mi++) {
                rsum[(wm0 + mi * 16 + tr) * 4 + cw] = ps[mi][0];
                rsum[(wm0 + mi * 16 + 8 + tr) * 4 + cw] = ps[mi][1];
            }
        }
        __syncthreads();
#pragma unroll
        for (int mi = 0; mi < 2; mi++) {
            int r0 = wm0 + mi * 16 + tr;
            int r1 = r0 + 8;
            float s0 = rsum[r0 * 4] + rsum[r0 * 4 + 1] + rsum[r0 * 4 + 2] + rsum[r0 * 4 + 3];
            float s1 = rsum[r1 * 4] + rsum[r1 * 4 + 1] + rsum[r1 * 4 + 2] + rsum[r1 * 4 + 3];
            float c0 = 1.f / fmaxf(sqrtf(s0), 1e-12f);
            float c1 = 1.f / fmaxf(sqrtf(s1), 1e-12f);
#pragma unroll
            for (int ni = 0; ni < 8; ni++) {
                float* d = acc[mi][ni];
                d[0] = fmaxf(d[0] * c0, 0.f); d[1] = fmaxf(d[1] * c0, 0.f);
                d[2] = fmaxf(d[2] * c1, 0.f); d[3] = fmaxf(d[3] * c1, 0.f);
            }
        }
    }
#pragma unroll
    for (int mi = 0; mi < 2; mi++)
#pragma unroll
        for (int ni = 0; ni < 8; ni++) {
            int cg = wn0 + ni * 8 + tc2;
            int ra = bm0 + wm0 + mi * 16 + tr;
            float* d = acc[mi][ni];
            img_write(ximg_hi, ximg_lo, cg >> 6, ra, cg & 63, d[0], d[1]);
            img_write(ximg_hi, ximg_lo, cg >> 6, ra + 8, cg & 63, d[2], d[3]);
        }
}

// ---------------- standalone GEMM (post layer) ----------------
__global__ void __launch_bounds__(512, 1)
mma_gemm(const unsigned* __restrict__ Aimg_hi, const unsigned* __restrict__ Aimg_lo,
         const uint4* __restrict__ Whi, const uint4* __restrict__ Wlo,
         const float* __restrict__ bias, float* __restrict__ Of32, int M) {
    extern __shared__ char smem[];
    const unsigned sb = smem_u32(smem);
    const int tid = threadIdx.x, wid = tid >> 5, lane = tid & 31;
    const int bm0 = blockIdx.x * 128;

    if (tid < 256) ((float*)(smem + PBASE))[tid] = bias[tid];

    const int wm0 = (wid >> 2) * 32;
    const int wn0 = (wid & 3) * 64;
    const int lrow = lane & 15;
    const int lk = (lane >> 4) * 8;

    float acc[2][8][4];
#pragma unroll
    for (int a = 0; a < 2; a++)
#pragma unroll
        for (int b = 0; b < 8; b++)
#pragma unroll
            for (int c = 0; c < 4; c++) acc[a][b][c] = 0.f;

    auto issue = [&](int c, int st) {
        unsigned ab = sb + st * ABUF;
        unsigned bb = sb + BBASE + st * BBUF;
        const char* wh = (const char*)(Whi + (size_t)c * 2048);
        const char* wl = (const char*)(Wlo + (size_t)c * 2048);
#pragma unroll
        for (int i = 0; i < 4; i++) {
            int u = tid + i * 512;
            CPA(bb + u * 16, wh + u * 16);
            CPA(bb + 32768 + u * 16, wl + u * 16);
        }
        const char* ih = (const char*)(Aimg_hi + ((size_t)c * ROWSP + bm0) * 32);
        const char* il = (const char*)(Aimg_lo + ((size_t)c * ROWSP + bm0) * 32);
#pragma unroll
        for (int i = 0; i < 2; i++) {
            int u = tid + i * 512;
            CPA(ab + u * 16, ih + u * 16);
            CPA(ab + 16384 + u * 16, il + u * 16);
        }
    };

    issue(0, 0);
    CP_COMMIT();
    for (int c = 0; c < 4; c++) {
        int st = c & 1;
        if (c + 1 < 4) { issue(c + 1, st ^ 1); CP_COMMIT(); cp_wait<1>(); }
        else cp_wait<0>();
        __syncthreads();
        unsigned abase = sb + st * ABUF;
        unsigned bbase = sb + BBASE + st * BBUF;
#pragma unroll
        for (int ks = 0; ks < 4; ks++) {
            const int k0 = ks * 16;
            unsigned ahi[2][4], alo[2][4];
#pragma unroll
            for (int mi = 0; mi < 2; mi++) {
                unsigned off = SWZ((unsigned)((wm0 + mi * 16 + lrow) * 128 + (k0 + lk) * 2));
                ldsm4(ahi[mi], abase + off);
                ldsm4(alo[mi], abase + 16384 + off);
            }
#pragma unroll
            for (int h = 0; h < 2; h++) {
                unsigned bhi[2][4], blo[2][4];
#pragma unroll
                for (int nb = 0; nb < 2; nb++) {
                    unsigned off = SWZ((unsigned)((wn0 + (h * 2 + nb) * 16 + lrow) * 128 + (k0 + lk) * 2));
                    ldsm4(bhi[nb], bbase + off);
                    ldsm4(blo[nb], bbase + 32768 + off);
                }
#pragma unroll
                for (int mi = 0; mi < 2; mi++)
#pragma unroll
                    for (int f = 0; f < 4; f++) {
                        int nb = f >> 1, r0 = f & 1;
                        float* d = acc[mi][h * 4 + f];
                        mma16816(d, ahi[mi], bhi[nb][r0], bhi[nb][r0 + 2]);
                        mma16816(d, ahi[mi], blo[nb][r0], blo[nb][r0 + 2]);
                        mma16816(d, alo[mi], bhi[nb][r0], bhi[nb][r0 + 2]);
                    }
            }
        }
        __syncthreads();
    }

    const float* sbias = (const float*)(smem + PBASE);
    const int tr = lane >> 2;
    const int tc2 = (lane & 3) * 2;
#pragma unroll
    for (int mi = 0; mi < 2; mi++)
#pragma unroll
        for (int ni = 0; ni < 8; ni++) {
            int cg = wn0 + ni * 8 + tc2;
            int ra = bm0 + wm0 + mi * 16 + tr;
            int rb = ra + 8;
            float* d = acc[mi][ni];
            float v0 = d[0] + sbias[cg], v1 = d[1] + sbias[cg + 1];
            float v2 = d[2] + sbias[cg], v3 = d[3] + sbias[cg + 1];
            if (ra < M) *(float2*)(Of32 + (size_t)ra * 256 + cg) = make_float2(v0, v1);
            if (rb < M) *(float2*)(Of32 + (size_t)rb * 256 + cg) = make_float2(v2, v3);
        }
}

// ---------------- head ----------------
__global__ void head_kernel(const float* __restrict__ h, const float* __restrict__ W2,
                            const float* __restrict__ b2, float* __restrict__ out) {
    __shared__ float sW[256 * NCLS];
    __shared__ float sb[NCLS];
    int tid = threadIdx.x;
    for (int i = tid; i < 256 * NCLS; i += 256) sW[i] = W2[i];
    if (tid < NCLS) sb[tid] = b2[tid];
    __syncthreads();

    int wid = tid >> 5, lane = tid & 31;
    int r = blockIdx.x * 8 + wid;
    if (r >= NN) return;

    const float4* rp = (const float4*)(h + (size_t)r * DD);
    float4 q0 = rp[lane * 2];
    float4 q1 = rp[lane * 2 + 1];
    float hreg[8] = {q0.x, q0.y, q0.z, q0.w, q1.x, q1.y, q1.z, q1.w};

    int c0 = lane;
    int c1 = lane + 32;
    int c1m = (c1 < NCLS) ? c1 : (NCLS - 1);
    float acc0 = sb[c0];
    float acc1 = sb[c1m];
#pragma unroll
    for (int e = 0; e < 8; e++) {
        for (int l = 0; l < 32; l++) {
            float hv = __shfl_sync(0xffffffffu, hreg[e], l);
            int k = l * 8 + e;
            acc0 = fmaf(hv, sW[k * NCLS + c0], acc0);
            acc1 = fmaf(hv, sW[k * NCLS + c1m], acc1);
        }
    }
    float m = fmaxf(acc0, (c1 < NCLS) ? acc1 : -3.4e38f);
#pragma unroll
    for (int o = 16; o > 0; o >>= 1) m = fmaxf(m, __shfl_xor_sync(0xffffffffu, m, o));
    float es = expf(acc0 - m) + ((c1 < NCLS) ? expf(acc1 - m) : 0.f);
#pragma unroll
    for (int o = 16; o > 0; o >>= 1) es += __shfl_xor_sync(0xffffffffu, es, o);
    float lse = m + logf(es);
    out[(size_t)r * NCLS + c0] = acc0 - lse;
    if (c1 < NCLS) out[(size_t)r * NCLS + c1] = acc1 - lse;
}

// ---------------- host orchestration ----------------
extern "C" void kernel_launch(void* const* d_in, const int* in_sizes, int n_in,
                              void* d_out, int out_size) {
    const float* x_in      = (const float*)d_in[0];
    const int* ei          = (const int*)d_in[1];
    const float* lin_l_W   = (const float*)d_in[2];
    const float* lin_l_b   = (const float*)d_in[3];
    const float* lin_r_W   = (const float*)d_in[4];
    const float* lin_r_b   = (const float*)d_in[5];
    const float* mlp_W1    = (const float*)d_in[6];
    const float* mlp_b1    = (const float*)d_in[7];
    const float* blk_Wa    = (const float*)d_in[8];
    const float* blk_ba    = (const float*)d_in[9];
    const float* blk_gamma = (const float*)d_in[10];
    const float* blk_beta  = (const float*)d_in[11];
    const float* blk_Wb    = (const float*)d_in[12];
    const float* blk_bb    = (const float*)d_in[13];
    const float* mlp_W2    = (const float*)d_in[14];
    const float* mlp_b2    = (const float*)d_in[15];
    const float* post_W1   = (const float*)d_in[16];
    const float* post_b1   = (const float*)d_in[17];
    const float* post_W2   = (const float*)d_in[18];
    const float* post_b2   = (const float*)d_in[19];
    float* out = (float*)d_out;

    float* pp;
    uint4 *whi, *wlo;
    unsigned *xih, *xil, *zih, *zil, *hih, *hil;
    int *cnti, *offp, *curp, *csrp;
    cudaGetSymbolAddress((void**)&pp, g_p);
    cudaGetSymbolAddress((void**)&whi, g_whi4);
    cudaGetSymbolAddress((void**)&wlo, g_wlo4);
    cudaGetSymbolAddress((void**)&xih, g_ximg_hi);
    cudaGetSymbolAddress((void**)&xil, g_ximg_lo);
    cudaGetSymbolAddress((void**)&zih, g_zimg_hi);
    cudaGetSymbolAddress((void**)&zil, g_zimg_lo);
    cudaGetSymbolAddress((void**)&hih, g_himg_hi);
    cudaGetSymbolAddress((void**)&hil, g_himg_lo);
    cudaGetSymbolAddress((void**)&cnti, g_cnti);
    cudaGetSymbolAddress((void**)&offp, g_off);
    cudaGetSymbolAddress((void**)&curp, g_cur);
    cudaGetSymbolAddress((void**)&csrp, g_csr);

    cudaFuncSetAttribute(fused_layer, cudaFuncAttributeMaxDynamicSharedMemorySize, FSMEM);
    cudaFuncSetAttribute(mma_gemm, cudaFuncAttributeMaxDynamicSharedMemorySize, SMEM_SZ);

    const float bnscale = rsqrtf(1.0f + 1e-5f);
    const int* src = ei;
    const int* dst = ei + EE;

    // 1: setup (weights + x image + cnti zero)
    setup_kernel<<<31596, 256>>>(lin_l_W, lin_r_W, mlp_W1, blk_Wa, blk_Wb, mlp_W2, post_W1,
                                 x_in, (unsigned short*)whi, (unsigned short*)wlo,
                                 xih, xil, cnti);
    // 2-4: CSR
    count_int<<<(EE + 255) / 256, 256>>>(dst, cnti);
    scan_kernel<<<1, 1024>>>(cnti, offp, curp);
    fill_kernel<<<(EE + 255) / 256, 256>>>(src, dst, curp, csrp);

    for (int i = 0; i < NLAYER; i++) {
        // 5 (+9k+5): gather
        gather_img<<<(NN + 1) / 2, 256>>>(xih, xil, offp, csrp, zih, zil);

        SlotTab tab;
        int s = 0;
        auto push = [&](int base, int n) {
            for (int c = 0; c < n; c++) {
                tab.p[s++] = whi + (size_t)(base + c) * 2048;
                tab.p[s++] = wlo + (size_t)(base + c) * 2048;
            }
        };
        push(i * 8, 8);
        push(24 + i * 4, 4);
        push(36 + (2 * i) * 4, 4);
        push(60 + (2 * i) * 4, 4);
        push(36 + (2 * i + 1) * 4, 4);
        push(60 + (2 * i + 1) * 4, 4);
        push(84 + i * 4, 4);

        size_t bo0 = ((size_t)i * 2) * 256, bo1 = ((size_t)i * 2 + 1) * 256;
        // 6 (+9k+6): fused layer  <-- profiled launch (s=5, c=1)
        fused_layer<<<NB, 512, FSMEM>>>(
            xih, xil, zih, zil, tab,
            lin_l_b + (size_t)i * 256, lin_r_b + (size_t)i * 256,
            mlp_b1 + (size_t)i * 256,
            blk_ba + bo0, blk_gamma + bo0, blk_beta + bo0, blk_bb + bo0,
            blk_ba + bo1, blk_gamma + bo1, blk_beta + bo1, blk_bb + bo1,
            mlp_b2 + (size_t)i * 256, bnscale,
            hih, hil);
    }

    mma_gemm<<<NB, 512, SMEM_SZ>>>(xih, xil, whi + (size_t)96 * 2048,
                                   wlo + (size_t)96 * 2048, post_b1, pp, NN);
    head_kernel<<<(NN + 7) / 8, 256>>>(pp, post_W2, post_b2, out);
}

// round 8
// speedup vs baseline: 2.7628x; 1.2430x over previous
#include <cuda_runtime.h>
#include <cuda_bf16.h>
#include <math.h>

#define NN 50000
#define ROWSP 50048
#define DD 256
#define EE 800000
#define NCLS 47
#define NLAYER 3
#define NB 391
#define CSRB 148

#define SWZ(x) ((x) ^ (((x) >> 3) & 0x70))

// ---- standalone (post) gemm smem layout ----
#define ABUF 32768
#define BBASE 65536
#define BBUF 65536
#define PBASE 196608
#define SMEM_SZ 201728

// ---- fused kernel smem layout ----
#define FS_B 131072
#define FSMEM 229376   // 128KB A-image + 3x32KB B ring

// ---------------- device scratch ----------------
__device__ float g_p[ROWSP * DD];
__device__ uint4 g_whi4[100 * 2048];
__device__ uint4 g_wlo4[100 * 2048];
__device__ unsigned g_ximg_hi[4 * ROWSP * 32];
__device__ unsigned g_ximg_lo[4 * ROWSP * 32];
__device__ unsigned g_zimg_hi[4 * ROWSP * 32];
__device__ unsigned g_zimg_lo[4 * ROWSP * 32];
__device__ unsigned g_himg_hi[4 * ROWSP * 32];
__device__ unsigned g_himg_lo[4 * ROWSP * 32];
__device__ int g_cnti[NN];          // static zero-init; self-zeroed each run
__device__ int g_off[NN + 1];
__device__ int g_cur[NN];
__device__ int g_csr[EE];
__device__ int g_partial[CSRB];
__device__ int g_pscan[CSRB];
__device__ unsigned g_bar;

struct SlotTab { const uint4* p[48]; };

static __device__ __forceinline__ unsigned smem_u32(const void* p) {
    unsigned a;
    asm("{ .reg .u64 t; cvta.to.shared.u64 t, %1; cvt.u32.u64 %0, t; }" : "=r"(a) : "l"(p));
    return a;
}
static __device__ __forceinline__ void ldsm4(unsigned r[4], unsigned addr) {
    asm volatile("ldmatrix.sync.aligned.m8n8.x4.shared.b16 {%0,%1,%2,%3}, [%4];"
                 : "=r"(r[0]), "=r"(r[1]), "=r"(r[2]), "=r"(r[3]) : "r"(addr));
}
static __device__ __forceinline__ void mma16816(float d[4], const unsigned a[4],
                                                unsigned b0, unsigned b1) {
    asm volatile(
        "mma.sync.aligned.m16n8k16.row.col.f32.bf16.bf16.f32 "
        "{%0,%1,%2,%3}, {%4,%5,%6,%7}, {%8,%9}, {%0,%1,%2,%3};"
        : "+f"(d[0]), "+f"(d[1]), "+f"(d[2]), "+f"(d[3])
        : "r"(a[0]), "r"(a[1]), "r"(a[2]), "r"(a[3]), "r"(b0), "r"(b1));
}
#define CPA(dst, src) \
    asm volatile("cp.async.cg.shared.global [%0], [%1], 16;" :: "r"(dst), "l"(src) : "memory")
#define CP_COMMIT() asm volatile("cp.async.commit_group;" ::: "memory")
template <int N>
static __device__ __forceinline__ void cp_wait() {
    asm volatile("cp.async.wait_group %0;" :: "n"(N) : "memory");
}

static __device__ __forceinline__ void bsplit(float v, unsigned& h, unsigned& l) {
    __nv_bfloat16 hb = __float2bfloat16(v);
    h = __bfloat16_as_ushort(hb);
    l = __bfloat16_as_ushort(__float2bfloat16(v - __bfloat162float(hb)));
}
static __device__ __forceinline__ unsigned img_idx(int chunk, int row, int lc) {
    return ((unsigned)chunk * ROWSP + (unsigned)row) * 32u +
           ((((unsigned)(lc * 2)) ^ (((unsigned)row & 7u) << 4)) >> 2);
}
static __device__ __forceinline__ void img_write(unsigned* __restrict__ hi,
                                                 unsigned* __restrict__ lo, int chunk,
                                                 int row, int lc, float v0, float v1) {
    unsigned h0, l0, h1, l1;
    bsplit(v0, h0, l0);
    bsplit(v1, h1, l1);
    unsigned idx = img_idx(chunk, row, lc);
    hi[idx] = h0 | (h1 << 16);
    lo[idx] = l0 | (l1 << 16);
}
static __device__ __forceinline__ float2 img_read(const unsigned* __restrict__ hi,
                                                  const unsigned* __restrict__ lo, int chunk,
                                                  int row, int lc) {
    unsigned idx = img_idx(chunk, row, lc);
    unsigned h = hi[idx], l = lo[idx];
    float x0 = __bfloat162float(__ushort_as_bfloat16((unsigned short)(h & 0xffff))) +
               __bfloat162float(__ushort_as_bfloat16((unsigned short)(l & 0xffff)));
    float x1 = __bfloat162float(__ushort_as_bfloat16((unsigned short)(h >> 16))) +
               __bfloat162float(__ushort_as_bfloat16((unsigned short)(l >> 16)));
    return make_float2(x0, x1);
}

// ---------------- setup: weight prep + x image (ONE launch) ----------------
__global__ void setup_kernel(const float* __restrict__ linl, const float* __restrict__ linr,
                             const float* __restrict__ w1, const float* __restrict__ wa,
                             const float* __restrict__ wb, const float* __restrict__ w2,
                             const float* __restrict__ post, const float* __restrict__ X,
                             unsigned short* __restrict__ dhi, unsigned short* __restrict__ dlo,
                             unsigned* __restrict__ xih, unsigned* __restrict__ xil) {
    int b = blockIdx.x;
    if (b < 6400) {
        int idx = b * 256 + threadIdx.x;
        int m = idx >> 16;
        int rem = idx & 65535;
        int n = rem & 255, k = rem >> 8;
        const float* W;
        int chunk;
        if (m < 3)       { W = linl + (size_t)m * 65536;       chunk = 0  + m * 8 + (k >> 6); }
        else if (m < 6)  { W = linr + (size_t)(m - 3) * 65536; chunk = 4  + (m - 3) * 8 + (k >> 6); }
        else if (m < 9)  { W = w1 + (size_t)(m - 6) * 65536;   chunk = 24 + (m - 6) * 4 + (k >> 6); }
        else if (m < 15) { W = wa + (size_t)(m - 9) * 65536;   chunk = 36 + (m - 9) * 4 + (k >> 6); }
        else if (m < 21) { W = wb + (size_t)(m - 15) * 65536;  chunk = 60 + (m - 15) * 4 + (k >> 6); }
        else if (m < 24) { W = w2 + (size_t)(m - 21) * 65536;  chunk = 84 + (m - 21) * 4 + (k >> 6); }
        else             { W = post;                           chunk = 96 + (k >> 6); }
        float v = W[(size_t)k * 256 + n];
        unsigned h, l;
        bsplit(v, h, l);
        unsigned off = (unsigned)chunk * 32768u + SWZ((unsigned)(n * 128 + (k & 63) * 2));
        dhi[off >> 1] = (unsigned short)h;
        dlo[off >> 1] = (unsigned short)l;
    } else {
        int idx = (b - 6400) * 256 + threadIdx.x;   // < NN*128 exactly
        int row = idx >> 7, p = idx & 127;
        float v0 = X[(size_t)row * 256 + p * 2];
        float v1 = X[(size_t)row * 256 + p * 2 + 1];
        img_write(xih, xil, (p * 2) >> 6, row, (p * 2) & 63, v0, v1);
    }
}

// ---------------- single-kernel CSR build (persistent grid + sw barrier) ----------------
static __device__ __forceinline__ void gridbar() {
    __syncthreads();
    __threadfence();
    if (threadIdx.x == 0) {
        unsigned arr = atomicAdd(&g_bar, 1u);
        unsigned target = (arr / CSRB + 1u) * CSRB;
        while (*(volatile unsigned*)&g_bar < target) { }
    }
    __syncthreads();
}

__global__ void csr_kernel(const int* __restrict__ src, const int* __restrict__ dst,
                           int* __restrict__ cnt, int* __restrict__ off,
                           int* __restrict__ cur, int* __restrict__ csr) {
    __shared__ int sdata[256];
    const int b = blockIdx.x, t = threadIdx.x;
    // P1: count
    for (int e = b * 256 + t; e < EE; e += CSRB * 256)
        atomicAdd(&cnt[dst[e]], 1);
    gridbar();
    // P2: scan (2 nodes per thread), self-zero cnt
    int n0 = (b * 256 + t) * 2;
    int c0 = (n0 < NN) ? cnt[n0] : 0;
    int c1 = (n0 + 1 < NN) ? cnt[n0 + 1] : 0;
    if (n0 < NN) cnt[n0] = 0;
    if (n0 + 1 < NN) cnt[n0 + 1] = 0;
    int ts = c0 + c1;
    sdata[t] = ts;
    __syncthreads();
#pragma unroll
    for (int o = 1; o < 256; o <<= 1) {
        int v = (t >= o) ? sdata[t - o] : 0;
        __syncthreads();
        sdata[t] += v;
        __syncthreads();
    }
    int bexcl = sdata[t] - ts;
    if (t == 255) g_partial[b] = sdata[t];
    gridbar();
    if (b == 0) {
        int v = (t < CSRB) ? g_partial[t] : 0;
        sdata[t] = v;
        __syncthreads();
#pragma unroll
        for (int o = 1; o < 256; o <<= 1) {
            int w = (t >= o) ? sdata[t - o] : 0;
            __syncthreads();
            sdata[t] += w;
            __syncthreads();
        }
        if (t < CSRB) g_pscan[t] = sdata[t] - v;
        if (t == 0) off[0] = 0;
    }
    gridbar();
    int base = g_pscan[b] + bexcl;
    if (n0 < NN) {
        cur[n0] = base;
        off[n0 + 1] = base + c0;
        if (n0 + 1 < NN) {
            cur[n0 + 1] = base + c0;
            if (n0 + 2 <= NN) off[n0 + 2] = base + c0 + c1;
        }
    }
    gridbar();
    // P3: fill
    for (int e = b * 256 + t; e < EE; e += CSRB * 256) {
        int p = atomicAdd(&cur[dst[e]], 1);
        csr[p] = src[e];
    }
}

// ---------------- gather: zimg[d] = mean over in-edges of ximg[src] ----------------
__global__ void gather_img(const unsigned* __restrict__ xih, const unsigned* __restrict__ xil,
                           const int* __restrict__ off, const int* __restrict__ csr,
                           unsigned* __restrict__ zih, unsigned* __restrict__ zil) {
    int w = (blockIdx.x * 256 + threadIdx.x) >> 5;
    int d = w >> 2, c = w & 3;
    if (d >= NN) return;
    int lane = threadIdx.x & 31;
    int lc = lane * 2;
    int b = off[d], e = off[d + 1];
    float s0 = 0.f, s1 = 0.f;
    int j = b;
    for (; j + 1 < e; j += 2) {
        int r0 = csr[j], r1 = csr[j + 1];
        float2 v0 = img_read(xih, xil, c, r0, lc);
        float2 v1 = img_read(xih, xil, c, r1, lc);
        s0 += v0.x + v1.x;
        s1 += v0.y + v1.y;
    }
    if (j < e) {
        float2 v = img_read(xih, xil, c, csr[j], lc);
        s0 += v.x;
        s1 += v.y;
    }
    float iv = 1.f / fmaxf((float)(e - b), 1.f);
    img_write(zih, zil, c, d, lc, s0 * iv, s1 * iv);
}

// ---- fused-layer helpers ----
template <bool ALO>
static __device__ __forceinline__ void mma_slot(unsigned abase, unsigned bbase,
                                                float (&acc)[2][8][4], int wm0, int wn0,
                                                int lane) {
    const int lrow = lane & 15;
    const int lk = (lane >> 4) * 8;
#pragma unroll
    for (int ks = 0; ks < 4; ks++) {
        const int k0 = ks * 16;
        unsigned ahi[2][4], alo[2][4];
#pragma unroll
        for (int mi = 0; mi < 2; mi++) {
            unsigned off = SWZ((unsigned)((wm0 + mi * 16 + lrow) * 128 + (k0 + lk) * 2));
            ldsm4(ahi[mi], abase + off);
            if (ALO) ldsm4(alo[mi], abase + 16384 + off);
        }
#pragma unroll
        for (int h = 0; h < 2; h++) {
            unsigned bb[2][4];
#pragma unroll
            for (int nb = 0; nb < 2; nb++) {
                unsigned off = SWZ((unsigned)((wn0 + (h * 2 + nb) * 16 + lrow) * 128 + (k0 + lk) * 2));
                ldsm4(bb[nb], bbase + off);
            }
#pragma unroll
            for (int mi = 0; mi < 2; mi++)
#pragma unroll
                for (int f = 0; f < 4; f++) {
                    int nb = f >> 1, r0 = f & 1;
                    float* d = acc[mi][h * 4 + f];
                    mma16816(d, ahi[mi], bb[nb][r0], bb[nb][r0 + 2]);
                    if (ALO) mma16816(d, alo[mi], bb[nb][r0], bb[nb][r0 + 2]);
                }
        }
    }
}

// ---------------- fused layer kernel ----------------
__global__ void __launch_bounds__(512, 1)
fused_layer(unsigned* __restrict__ ximg_hi, unsigned* __restrict__ ximg_lo,
            const unsigned* __restrict__ zimg_hi, const unsigned* __restrict__ zimg_lo,
            SlotTab tab,
            const float* __restrict__ bl, const float* __restrict__ br,
            const float* __restrict__ b1,
            const float* __restrict__ ba0, const float* __restrict__ g0,
            const float* __restrict__ be0, const float* __restrict__ bb0,
            const float* __restrict__ ba1, const float* __restrict__ g1,
            const float* __restrict__ be1, const float* __restrict__ bb1,
            const float* __restrict__ b2, float bnscale,
            unsigned* __restrict__ himg_hi, unsigned* __restrict__ himg_lo) {
    extern __shared__ char smem[];
    const unsigned sb = smem_u32(smem);
    const int tid = threadIdx.x, wid = tid >> 5, lane = tid & 31;
    const int bm0 = blockIdx.x * 128;
    const int wm0 = (wid >> 2) * 32;
    const int wn0 = (wid & 3) * 64;
    const int tr = lane >> 2;
    const int tc2 = (lane & 3) * 2;

    float acc[2][8][4];
    auto zero_acc = [&]() {
#pragma unroll
        for (int a = 0; a < 2; a++)
#pragma unroll
            for (int b = 0; b < 8; b++)
#pragma unroll
                for (int c = 0; c < 4; c++) acc[a][b][c] = 0.f;
    };
    zero_acc();

    auto issue_B = [&](int s) {   // no commit
        if (s >= 48) return;
        const char* src = (const char*)tab.p[s];
        unsigned dstb = sb + FS_B + (unsigned)(s % 3) * 32768u;
#pragma unroll
        for (int i = 0; i < 4; i++) {
            int u = tid + i * 512;
            CPA(dstb + u * 16, src + u * 16);
        }
    };
    auto issue_z = [&](int c) {
        const char* gh = (const char*)(zimg_hi + ((size_t)c * ROWSP + bm0) * 32);
        const char* gl = (const char*)(zimg_lo + ((size_t)c * ROWSP + bm0) * 32);
        unsigned cb = sb + (unsigned)c * 32768u;
#pragma unroll
        for (int i = 0; i < 2; i++) {
            int u = tid + i * 512;
            CPA(cb + u * 16, gh + u * 16);
            CPA(cb + 16384 + u * 16, gl + u * 16);
        }
    };
    // 3-term stage: 8 slots (hi,lo per chunk)
    auto run3 = [&](int s0, bool loadz) {
#pragma unroll 1
        for (int c = 0; c < 4; c++) {
            int s = s0 + c * 2;
            unsigned abase = sb + (unsigned)c * 32768u;
            cp_wait<2>();
            __syncthreads();
            mma_slot<true>(abase, sb + FS_B + (unsigned)(s % 3) * 32768u, acc, wm0, wn0, lane);
            __syncthreads();
            issue_B(s + 3);
            CP_COMMIT();
            cp_wait<2>();
            __syncthreads();
            mma_slot<false>(abase, sb + FS_B + (unsigned)((s + 1) % 3) * 32768u, acc, wm0, wn0, lane);
            __syncthreads();
            issue_B(s + 4);
            if (loadz) issue_z(c);
            CP_COMMIT();
        }
    };
    // 1-term stage (pure bf16): 4 slots (hi per chunk)
    auto run1 = [&](int s0) {
#pragma unroll 1
        for (int c = 0; c < 4; c++) {
            int s = s0 + c;
            unsigned abase = sb + (unsigned)c * 32768u;
            cp_wait<2>();
            __syncthreads();
            mma_slot<false>(abase, sb + FS_B + (unsigned)(s % 3) * 32768u, acc, wm0, wn0, lane);
            __syncthreads();
            issue_B(s + 3);
            CP_COMMIT();
        }
    };
    auto conv_img = [&](bool lo) {   // acc -> smem A image
        unsigned cb = (unsigned)(wn0 >> 6) * 32768u;
#pragma unroll
        for (int mi = 0; mi < 2; mi++)
#pragma unroll
            for (int ni = 0; ni < 8; ni++) {
                int lc = ni * 8 + tc2;
                float* d = acc[mi][ni];
                unsigned h0, l0, h1, l1;
                bsplit(d[0], h0, l0); bsplit(d[1], h1, l1);
                unsigned off = SWZ((unsigned)((wm0 + mi * 16 + tr) * 128 + lc * 2));
                *(unsigned*)(smem + cb + off) = h0 | (h1 << 16);
                if (lo) *(unsigned*)(smem + cb + 16384 + off) = l0 | (l1 << 16);
                bsplit(d[2], h0, l0); bsplit(d[3], h1, l1);
                off = SWZ((unsigned)((wm0 + mi * 16 + 8 + tr) * 128 + lc * 2));
                *(unsigned*)(smem + cb + off) = h0 | (h1 << 16);
                if (lo) *(unsigned*)(smem + cb + 16384 + off) = l0 | (l1 << 16);
            }
    };

    // ---- prologue ----
#pragma unroll
    for (int c = 0; c < 4; c++) {
        const char* gh = (const char*)(ximg_hi + ((size_t)c * ROWSP + bm0) * 32);
        const char* gl = (const char*)(ximg_lo + ((size_t)c * ROWSP + bm0) * 32);
        unsigned cb = sb + (unsigned)c * 32768u;
#pragma unroll
        for (int i = 0; i < 2; i++) {
            int u = tid + i * 512;
            CPA(cb + u * 16, gh + u * 16);
            CPA(cb + 16384 + u * 16, gl + u * 16);
        }
    }
    CP_COMMIT();
    issue_B(0); CP_COMMIT();
    issue_B(1); CP_COMMIT();
    issue_B(2); CP_COMMIT();

    // ---- cat: slots 0-7 (x), 8-15 (z) ----
    run3(0, true);
    run3(8, false);
#pragma unroll
    for (int mi = 0; mi < 2; mi++)
#pragma unroll
        for (int ni = 0; ni < 8; ni++) {
            int cg = wn0 + ni * 8 + tc2;
            float* d = acc[mi][ni];
            float a0 = bl[cg] + br[cg], a1 = bl[cg + 1] + br[cg + 1];
            d[0] += a0; d[1] += a1; d[2] += a0; d[3] += a1;
        }
    conv_img(true); zero_acc(); __syncthreads();

    // ---- w1: slots 16-23 ----
    run3(16, false);
#pragma unroll
    for (int mi = 0; mi < 2; mi++)
#pragma unroll
        for (int ni = 0; ni < 8; ni++) {
            int cg = wn0 + ni * 8 + tc2;
            float* d = acc[mi][ni];
            d[0] += b1[cg]; d[1] += b1[cg + 1]; d[2] += b1[cg]; d[3] += b1[cg + 1];
            int ra = bm0 + wm0 + mi * 16 + tr;
            img_write(himg_hi, himg_lo, cg >> 6, ra, cg & 63, d[0], d[1]);
            img_write(himg_hi, himg_lo, cg >> 6, ra + 8, cg & 63, d[2], d[3]);
        }
    conv_img(false); zero_acc(); __syncthreads();

    // ---- blocks (1-term): wa j: 24+j*8, wb j: 28+j*8 ----
#pragma unroll 1
    for (int j = 0; j < 2; j++) {
        const float* ba = j ? ba1 : ba0;
        const float* gg = j ? g1 : g0;
        const float* be = j ? be1 : be0;
        const float* bb = j ? bb1 : bb0;
        run1(24 + j * 8);
#pragma unroll
        for (int mi = 0; mi < 2; mi++)
#pragma unroll
            for (int ni = 0; ni < 8; ni++) {
                int cg = wn0 + ni * 8 + tc2;
                float* d = acc[mi][ni];
                float ga = gg[cg], gb = gg[cg + 1], ea = be[cg], eb = be[cg + 1];
                float a0 = ba[cg], a1 = ba[cg + 1];
                d[0] = fmaf(ga, fmaxf(d[0] + a0, 0.f) * bnscale, ea);
                d[1] = fmaf(gb, fmaxf(d[1] + a1, 0.f) * bnscale, eb);
                d[2] = fmaf(ga, fmaxf(d[2] + a0, 0.f) * bnscale, ea);
                d[3] = fmaf(gb, fmaxf(d[3] + a1, 0.f) * bnscale, eb);
            }
        conv_img(false); zero_acc(); __syncthreads();
        run1(28 + j * 8);
#pragma unroll
        for (int mi = 0; mi < 2; mi++)
#pragma unroll
            for (int ni = 0; ni < 8; ni++) {
                int cg = wn0 + ni * 8 + tc2;
                float* d = acc[mi][ni];
                int ra = bm0 + wm0 + mi * 16 + tr;
                float2 ha = img_read(himg_hi, himg_lo, cg >> 6, ra, cg & 63);
                float2 hb = img_read(himg_hi, himg_lo, cg >> 6, ra + 8, cg & 63);
                d[0] += bb[cg] + ha.x; d[1] += bb[cg + 1] + ha.y;
                d[2] += bb[cg] + hb.x; d[3] += bb[cg + 1] + hb.y;
                if (j == 0) {
                    img_write(himg_hi, himg_lo, cg >> 6, ra, cg & 63, d[0], d[1]);
                    img_write(himg_hi, himg_lo, cg >> 6, ra + 8, cg & 63, d[2], d[3]);
                }
            }
        conv_img(j == 1); zero_acc(); __syncthreads();
    }

    // ---- w2: slots 40-47, normalize + relu -> ximg ----
    run3(40, false);
#pragma unroll
    for (int mi = 0; mi < 2; mi++)
#pragma unroll
        for (int ni = 0; ni < 8; ni++) {
            int cg = wn0 + ni * 8 + tc2;
            float* d = acc[mi][ni];
            d[0] += b2[cg]; d[1] += b2[cg + 1]; d[2] += b2[cg]; d[3] += b2[cg + 1];
        }
    {
        float* rsum = (float*)(smem + FS_B);
        float ps[2][2] = {{0.f, 0.f}, {0.f, 0.f}};
#pragma unroll
        for (int mi = 0; mi < 2; mi++)
#pragma unroll
            for (int ni = 0; ni < 8; ni++) {
                float* d = acc[mi][ni];
                ps[mi][0] = fmaf(d[0], d[0], fmaf(d[1], d[1], ps[mi][0]));
                ps[mi][1] = fmaf(d[2], d[2], fmaf(d[3], d[3], ps[mi][1]));
            }
#pragma unroll
        for (int mi = 0; mi < 2; mi++)
#pragma unroll
            for (int q = 0; q < 2; q++) {
                ps[mi][q] += __shfl_xor_sync(0xffffffffu, ps[mi][q], 1);
                ps[mi][q] += __shfl_xor_sync(0xffffffffu, ps[mi][q], 2);
            }
        __syncthreads();
        if ((lane & 3) == 0) {
            int cw = wn0 >> 6;
#pragma unroll
            for (int mi = 0; mi < 2; mi++) {
                rsum[(wm0 + mi * 16 + tr) * 4 + cw] = ps[mi][0];
                rsum[(wm0 + mi * 16 + 8 + tr) * 4 + cw] = ps[mi][1];
            }
        }
        __syncthreads();
#pragma unroll
        for (int mi = 0; mi < 2; mi++) {
            int r0 = wm0 + mi * 16 + tr;
            int r1 = r0 + 8;
            float s0 = rsum[r0 * 4] + rsum[r0 * 4 + 1] + rsum[r0 * 4 + 2] + rsum[r0 * 4 + 3];
            float s1 = rsum[r1 * 4] + rsum[r1 * 4 + 1] + rsum[r1 * 4 + 2] + rsum[r1 * 4 + 3];
            float c0 = 1.f / fmaxf(sqrtf(s0), 1e-12f);
            float c1 = 1.f / fmaxf(sqrtf(s1), 1e-12f);
#pragma unroll
            for (int ni = 0; ni < 8; ni++) {
                float* d = acc[mi][ni];
                d[0] = fmaxf(d[0] * c0, 0.f); d[1] = fmaxf(d[1] * c0, 0.f);
                d[2] = fmaxf(d[2] * c1, 0.f); d[3] = fmaxf(d[3] * c1, 0.f);
            }
        }
    }
#pragma unroll
    for (int mi = 0; mi < 2; mi++)
#pragma unroll
        for (int ni = 0; ni < 8; ni++) {
            int cg = wn0 + ni * 8 + tc2;
            int ra = bm0 + wm0 + mi * 16 + tr;
            float* d = acc[mi][ni];
            img_write(ximg_hi, ximg_lo, cg >> 6, ra, cg & 63, d[0], d[1]);
            img_write(ximg_hi, ximg_lo, cg >> 6, ra + 8, cg & 63, d[2], d[3]);
        }
}

// ---------------- standalone GEMM (post layer, 3-term) ----------------
__global__ void __launch_bounds__(512, 1)
mma_gemm(const unsigned* __restrict__ Aimg_hi, const unsigned* __restrict__ Aimg_lo,
         const uint4* __restrict__ Whi, const uint4* __restrict__ Wlo,
         const float* __restrict__ bias, float* __restrict__ Of32, int M) {
    extern __shared__ char smem[];
    const unsigned sb = smem_u32(smem);
    const int tid = threadIdx.x, wid = tid >> 5, lane = tid & 31;
    const int bm0 = blockIdx.x * 128;

    if (tid < 256) ((float*)(smem + PBASE))[tid] = bias[tid];

    const int wm0 = (wid >> 2) * 32;
    const int wn0 = (wid & 3) * 64;
    const int lrow = lane & 15;
    const int lk = (lane >> 4) * 8;

    float acc[2][8][4];
#pragma unroll
    for (int a = 0; a < 2; a++)
#pragma unroll
        for (int b = 0; b < 8; b++)
#pragma unroll
            for (int c = 0; c < 4; c++) acc[a][b][c] = 0.f;

    auto issue = [&](int c, int st) {
        unsigned ab = sb + st * ABUF;
        unsigned bb = sb + BBASE + st * BBUF;
        const char* wh = (const char*)(Whi + (size_t)c * 2048);
        const char* wl = (const char*)(Wlo + (size_t)c * 2048);
#pragma unroll
        for (int i = 0; i < 4; i++) {
            int u = tid + i * 512;
            CPA(bb + u * 16, wh + u * 16);
            CPA(bb + 32768 + u * 16, wl + u * 16);
        }
        const char* ih = (const char*)(Aimg_hi + ((size_t)c * ROWSP + bm0) * 32);
        const char* il = (const char*)(Aimg_lo + ((size_t)c * ROWSP + bm0) * 32);
#pragma unroll
        for (int i = 0; i < 2; i++) {
            int u = tid + i * 512;
            CPA(ab + u * 16, ih + u * 16);
            CPA(ab + 16384 + u * 16, il + u * 16);
        }
    };

    issue(0, 0);
    CP_COMMIT();
    for (int c = 0; c < 4; c++) {
        int st = c & 1;
        if (c + 1 < 4) { issue(c + 1, st ^ 1); CP_COMMIT(); cp_wait<1>(); }
        else cp_wait<0>();
        __syncthreads();
        unsigned abase = sb + st * ABUF;
        unsigned bbase = sb + BBASE + st * BBUF;
#pragma unroll
        for (int ks = 0; ks < 4; ks++) {
            const int k0 = ks * 16;
            unsigned ahi[2][4], alo[2][4];
#pragma unroll
            for (int mi = 0; mi < 2; mi++) {
                unsigned off = SWZ((unsigned)((wm0 + mi * 16 + lrow) * 128 + (k0 + lk) * 2));
                ldsm4(ahi[mi], abase + off);
                ldsm4(alo[mi], abase + 16384 + off);
            }
#pragma unroll
            for (int h = 0; h < 2; h++) {
                unsigned bhi[2][4], blo[2][4];
#pragma unroll
                for (int nb = 0; nb < 2; nb++) {
                    unsigned off = SWZ((unsigned)((wn0 + (h * 2 + nb) * 16 + lrow) * 128 + (k0 + lk) * 2));
                    ldsm4(bhi[nb], bbase + off);
                    ldsm4(blo[nb], bbase + 32768 + off);
                }
#pragma unroll
                for (int mi = 0; mi < 2; mi++)
#pragma unroll
                    for (int f = 0; f < 4; f++) {
                        int nb = f >> 1, r0 = f & 1;
                        float* d = acc[mi][h * 4 + f];
                        mma16816(d, ahi[mi], bhi[nb][r0], bhi[nb][r0 + 2]);
                        mma16816(d, ahi[mi], blo[nb][r0], blo[nb][r0 + 2]);
                        mma16816(d, alo[mi], bhi[nb][r0], bhi[nb][r0 + 2]);
                    }
            }
        }
        __syncthreads();
    }

    const float* sbias = (const float*)(smem + PBASE);
    const int tr = lane >> 2;
    const int tc2 = (lane & 3) * 2;
#pragma unroll
    for (int mi = 0; mi < 2; mi++)
#pragma unroll
        for (int ni = 0; ni < 8; ni++) {
            int cg = wn0 + ni * 8 + tc2;
            int ra = bm0 + wm0 + mi * 16 + tr;
            int rb = ra + 8;
            float* d = acc[mi][ni];
            float v0 = d[0] + sbias[cg], v1 = d[1] + sbias[cg + 1];
            float v2 = d[2] + sbias[cg], v3 = d[3] + sbias[cg + 1];
            if (ra < M) *(float2*)(Of32 + (size_t)ra * 256 + cg) = make_float2(v0, v1);
            if (rb < M) *(float2*)(Of32 + (size_t)rb * 256 + cg) = make_float2(v2, v3);
        }
}

// ---------------- head ----------------
__global__ void head_kernel(const float* __restrict__ h, const float* __restrict__ W2,
                            const float* __restrict__ b2, float* __restrict__ out) {
    __shared__ float sW[256 * NCLS];
    __shared__ float sb[NCLS];
    int tid = threadIdx.x;
    for (int i = tid; i < 256 * NCLS; i += 256) sW[i] = W2[i];
    if (tid < NCLS) sb[tid] = b2[tid];
    __syncthreads();

    int wid = tid >> 5, lane = tid & 31;
    int r = blockIdx.x * 8 + wid;
    if (r >= NN) return;

    const float4* rp = (const float4*)(h + (size_t)r * DD);
    float4 q0 = rp[lane * 2];
    float4 q1 = rp[lane * 2 + 1];
    float hreg[8] = {q0.x, q0.y, q0.z, q0.w, q1.x, q1.y, q1.z, q1.w};

    int c0 = lane;
    int c1 = lane + 32;
    int c1m = (c1 < NCLS) ? c1 : (NCLS - 1);
    float acc0 = sb[c0];
    float acc1 = sb[c1m];
#pragma unroll
    for (int e = 0; e < 8; e++) {
        for (int l = 0; l < 32; l++) {
            float hv = __shfl_sync(0xffffffffu, hreg[e], l);
            int k = l * 8 + e;
            acc0 = fmaf(hv, sW[k * NCLS + c0], acc0);
            acc1 = fmaf(hv, sW[k * NCLS + c1m], acc1);
        }
    }
    float m = fmaxf(acc0, (c1 < NCLS) ? acc1 : -3.4e38f);
#pragma unroll
    for (int o = 16; o > 0; o >>= 1) m = fmaxf(m, __shfl_xor_sync(0xffffffffu, m, o));
    float es = expf(acc0 - m) + ((c1 < NCLS) ? expf(acc1 - m) : 0.f);
#pragma unroll
    for (int o = 16; o > 0; o >>= 1) es += __shfl_xor_sync(0xffffffffu, es, o);
    float lse = m + logf(es);
    out[(size_t)r * NCLS + c0] = acc0 - lse;
    if (c1 < NCLS) out[(size_t)r * NCLS + c1] = acc1 - lse;
}

// ---------------- host orchestration ----------------
extern "C" void kernel_launch(void* const* d_in, const int* in_sizes, int n_in,
                              void* d_out, int out_size) {
    const float* x_in      = (const float*)d_in[0];
    const int* ei          = (const int*)d_in[1];
    const float* lin_l_W   = (const float*)d_in[2];
    const float* lin_l_b   = (const float*)d_in[3];
    const float* lin_r_W   = (const float*)d_in[4];
    const float* lin_r_b   = (const float*)d_in[5];
    const float* mlp_W1    = (const float*)d_in[6];
    const float* mlp_b1    = (const float*)d_in[7];
    const float* blk_Wa    = (const float*)d_in[8];
    const float* blk_ba    = (const float*)d_in[9];
    const float* blk_gamma = (const float*)d_in[10];
    const float* blk_beta  = (const float*)d_in[11];
    const float* blk_Wb    = (const float*)d_in[12];
    const float* blk_bb    = (const float*)d_in[13];
    const float* mlp_W2    = (const float*)d_in[14];
    const float* mlp_b2    = (const float*)d_in[15];
    const float* post_W1   = (const float*)d_in[16];
    const float* post_b1   = (const float*)d_in[17];
    const float* post_W2   = (const float*)d_in[18];
    const float* post_b2   = (const float*)d_in[19];
    float* out = (float*)d_out;

    float* pp;
    uint4 *whi, *wlo;
    unsigned *xih, *xil, *zih, *zil, *hih, *hil;
    int *cnti, *offp, *curp, *csrp;
    cudaGetSymbolAddress((void**)&pp, g_p);
    cudaGetSymbolAddress((void**)&whi, g_whi4);
    cudaGetSymbolAddress((void**)&wlo, g_wlo4);
    cudaGetSymbolAddress((void**)&xih, g_ximg_hi);
    cudaGetSymbolAddress((void**)&xil, g_ximg_lo);
    cudaGetSymbolAddress((void**)&zih, g_zimg_hi);
    cudaGetSymbolAddress((void**)&zil, g_zimg_lo);
    cudaGetSymbolAddress((void**)&hih, g_himg_hi);
    cudaGetSymbolAddress((void**)&hil, g_himg_lo);
    cudaGetSymbolAddress((void**)&cnti, g_cnti);
    cudaGetSymbolAddress((void**)&offp, g_off);
    cudaGetSymbolAddress((void**)&curp, g_cur);
    cudaGetSymbolAddress((void**)&csrp, g_csr);

    cudaFuncSetAttribute(fused_layer, cudaFuncAttributeMaxDynamicSharedMemorySize, FSMEM);
    cudaFuncSetAttribute(mma_gemm, cudaFuncAttributeMaxDynamicSharedMemorySize, SMEM_SZ);

    const float bnscale = rsqrtf(1.0f + 1e-5f);
    const int* src = ei;
    const int* dst = ei + EE;

    // 1: setup (weights + x image)
    setup_kernel<<<31400, 256>>>(lin_l_W, lin_r_W, mlp_W1, blk_Wa, blk_Wb, mlp_W2, post_W1,
                                 x_in, (unsigned short*)whi, (unsigned short*)wlo, xih, xil);
    // 2: CSR (count+scan+fill, one persistent kernel)
    csr_kernel<<<CSRB, 256>>>(src, dst, cnti, offp, curp, csrp);

    for (int i = 0; i < NLAYER; i++) {
        // 3: gather
        gather_img<<<(NN + 1) / 2, 256>>>(xih, xil, offp, csrp, zih, zil);

        SlotTab tab;
        int s = 0;
        auto push2 = [&](int base, int n) {
            for (int c = 0; c < n; c++) {
                tab.p[s++] = whi + (size_t)(base + c) * 2048;
                tab.p[s++] = wlo + (size_t)(base + c) * 2048;
            }
        };
        auto push1 = [&](int base, int n) {
            for (int c = 0; c < n; c++) tab.p[s++] = whi + (size_t)(base + c) * 2048;
        };
        push2(i * 8, 4);                 // cat x-half (lin_l)      slots 0-7
        push2(i * 8 + 4, 4);             // cat z-half (lin_r)      slots 8-15
        push2(24 + i * 4, 4);            // w1                      slots 16-23
        push1(36 + (2 * i) * 4, 4);      // wa0 (1-term)            slots 24-27
        push1(60 + (2 * i) * 4, 4);      // wb0                    slots 28-31
        push1(36 + (2 * i + 1) * 4, 4);  // wa1                    slots 32-35
        push1(60 + (2 * i + 1) * 4, 4);  // wb1                    slots 36-39
        push2(84 + i * 4, 4);            // w2                      slots 40-47

        size_t bo0 = ((size_t)i * 2) * 256, bo1 = ((size_t)i * 2 + 1) * 256;
        // 4: fused layer  <-- profiled launch
        fused_layer<<<NB, 512, FSMEM>>>(
            xih, xil, zih, zil, tab,
            lin_l_b + (size_t)i * 256, lin_r_b + (size_t)i * 256,
            mlp_b1 + (size_t)i * 256,
            blk_ba + bo0, blk_gamma + bo0, blk_beta + bo0, blk_bb + bo0,
            blk_ba + bo1, blk_gamma + bo1, blk_beta + bo1, blk_bb + bo1,
            mlp_b2 + (size_t)i * 256, bnscale,
            hih, hil);
    }

    mma_gemm<<<NB, 512, SMEM_SZ>>>(xih, xil, whi + (size_t)96 * 2048,
                                   wlo + (size_t)96 * 2048, post_b1, pp, NN);
    head_kernel<<<(NN + 7) / 8, 256>>>(pp, post_W2, post_b2, out);
}

// round 9
// speedup vs baseline: 3.3173x; 1.2007x over previous
#include <cuda_runtime.h>
#include <cuda_bf16.h>
#include <math.h>

#define NN 50000
#define ROWSP 50048
#define DD 256
#define EE 800000
#define NCLS 47
#define NLAYER 3
#define NB 391
#define CSRB 148

#define SWZ(x) ((x) ^ (((x) >> 3) & 0x70))

// ---- standalone (post) gemm smem layout ----
#define ABUF 32768
#define BBASE 65536
#define BBUF 65536
#define PBASE 196608
#define SMEM_SZ 201728

// ---- fused kernel smem layout ----
#define FS_B 131072
#define FSMEM 229376   // 128KB A-image + 3x32KB B ring

// ---------------- device scratch ----------------
__device__ float g_p[ROWSP * DD];
__device__ uint4 g_whi4[100 * 2048];
__device__ uint4 g_wlo4[100 * 2048];
__device__ unsigned g_ximg_hi[4 * ROWSP * 32];
__device__ unsigned g_ximg_lo[4 * ROWSP * 32];
__device__ unsigned g_zimg_hi[4 * ROWSP * 32];
__device__ unsigned g_zimg_lo[4 * ROWSP * 32];
__device__ unsigned g_himg_hi[4 * ROWSP * 32];
__device__ unsigned g_himg_lo[4 * ROWSP * 32];
__device__ int g_cnti[NN];          // static zero-init; self-zeroed each run
__device__ int g_off[NN + 1];
__device__ int g_cur[NN];
__device__ int g_csr[EE];
__device__ int g_partial[CSRB];
__device__ int g_pscan[CSRB];
__device__ unsigned g_bar;

struct SlotTab { const uint4* p[36]; };

static __device__ __forceinline__ unsigned smem_u32(const void* p) {
    unsigned a;
    asm("{ .reg .u64 t; cvta.to.shared.u64 t, %1; cvt.u32.u64 %0, t; }" : "=r"(a) : "l"(p));
    return a;
}
static __device__ __forceinline__ void ldsm4(unsigned r[4], unsigned addr) {
    asm volatile("ldmatrix.sync.aligned.m8n8.x4.shared.b16 {%0,%1,%2,%3}, [%4];"
                 : "=r"(r[0]), "=r"(r[1]), "=r"(r[2]), "=r"(r[3]) : "r"(addr));
}
static __device__ __forceinline__ void mma16816(float d[4], const unsigned a[4],
                                                unsigned b0, unsigned b1) {
    asm volatile(
        "mma.sync.aligned.m16n8k16.row.col.f32.bf16.bf16.f32 "
        "{%0,%1,%2,%3}, {%4,%5,%6,%7}, {%8,%9}, {%0,%1,%2,%3};"
        : "+f"(d[0]), "+f"(d[1]), "+f"(d[2]), "+f"(d[3])
        : "r"(a[0]), "r"(a[1]), "r"(a[2]), "r"(a[3]), "r"(b0), "r"(b1));
}
#define CPA(dst, src) \
    asm volatile("cp.async.cg.shared.global [%0], [%1], 16;" :: "r"(dst), "l"(src) : "memory")
#define CP_COMMIT() asm volatile("cp.async.commit_group;" ::: "memory")
template <int N>
static __device__ __forceinline__ void cp_wait() {
    asm volatile("cp.async.wait_group %0;" :: "n"(N) : "memory");
}

static __device__ __forceinline__ void bsplit(float v, unsigned& h, unsigned& l) {
    __nv_bfloat16 hb = __float2bfloat16(v);
    h = __bfloat16_as_ushort(hb);
    l = __bfloat16_as_ushort(__float2bfloat16(v - __bfloat162float(hb)));
}
static __device__ __forceinline__ unsigned img_idx(int chunk, int row, int lc) {
    return ((unsigned)chunk * ROWSP + (unsigned)row) * 32u +
           ((((unsigned)(lc * 2)) ^ (((unsigned)row & 7u) << 4)) >> 2);
}
static __device__ __forceinline__ void img_write(unsigned* __restrict__ hi,
                                                 unsigned* __restrict__ lo, int chunk,
                                                 int row, int lc, float v0, float v1) {
    unsigned h0, l0, h1, l1;
    bsplit(v0, h0, l0);
    bsplit(v1, h1, l1);
    unsigned idx = img_idx(chunk, row, lc);
    hi[idx] = h0 | (h1 << 16);
    lo[idx] = l0 | (l1 << 16);
}
static __device__ __forceinline__ float2 img_read(const unsigned* __restrict__ hi,
                                                  const unsigned* __restrict__ lo, int chunk,
                                                  int row, int lc) {
    unsigned idx = img_idx(chunk, row, lc);
    unsigned h = hi[idx], l = lo[idx];
    float x0 = __bfloat162float(__ushort_as_bfloat16((unsigned short)(h & 0xffff))) +
               __bfloat162float(__ushort_as_bfloat16((unsigned short)(l & 0xffff)));
    float x1 = __bfloat162float(__ushort_as_bfloat16((unsigned short)(h >> 16))) +
               __bfloat162float(__ushort_as_bfloat16((unsigned short)(l >> 16)));
    return make_float2(x0, x1);
}

// ---------------- setup: weight prep + x image (ONE launch) ----------------
__global__ void setup_kernel(const float* __restrict__ linl, const float* __restrict__ linr,
                             const float* __restrict__ w1, const float* __restrict__ wa,
                             const float* __restrict__ wb, const float* __restrict__ w2,
                             const float* __restrict__ post, const float* __restrict__ X,
                             unsigned short* __restrict__ dhi, unsigned short* __restrict__ dlo,
                             unsigned* __restrict__ xih, unsigned* __restrict__ xil) {
    int b = blockIdx.x;
    if (b < 6400) {
        int idx = b * 256 + threadIdx.x;
        int m = idx >> 16;
        int rem = idx & 65535;
        int n = rem & 255, k = rem >> 8;
        const float* W;
        int chunk;
        if (m < 3)       { W = linl + (size_t)m * 65536;       chunk = 0  + m * 8 + (k >> 6); }
        else if (m < 6)  { W = linr + (size_t)(m - 3) * 65536; chunk = 4  + (m - 3) * 8 + (k >> 6); }
        else if (m < 9)  { W = w1 + (size_t)(m - 6) * 65536;   chunk = 24 + (m - 6) * 4 + (k >> 6); }
        else if (m < 15) { W = wa + (size_t)(m - 9) * 65536;   chunk = 36 + (m - 9) * 4 + (k >> 6); }
        else if (m < 21) { W = wb + (size_t)(m - 15) * 65536;  chunk = 60 + (m - 15) * 4 + (k >> 6); }
        else if (m < 24) { W = w2 + (size_t)(m - 21) * 65536;  chunk = 84 + (m - 21) * 4 + (k >> 6); }
        else             { W = post;                           chunk = 96 + (k >> 6); }
        float v = W[(size_t)k * 256 + n];
        unsigned h, l;
        bsplit(v, h, l);
        unsigned off = (unsigned)chunk * 32768u + SWZ((unsigned)(n * 128 + (k & 63) * 2));
        dhi[off >> 1] = (unsigned short)h;
        dlo[off >> 1] = (unsigned short)l;
    } else {
        int idx = (b - 6400) * 256 + threadIdx.x;   // < NN*128 exactly
        int row = idx >> 7, p = idx & 127;
        float v0 = X[(size_t)row * 256 + p * 2];
        float v1 = X[(size_t)row * 256 + p * 2 + 1];
        img_write(xih, xil, (p * 2) >> 6, row, (p * 2) & 63, v0, v1);
    }
}

// ---------------- single-kernel CSR build (persistent grid + sw barrier) ----------------
static __device__ __forceinline__ void gridbar() {
    __syncthreads();
    __threadfence();
    if (threadIdx.x == 0) {
        unsigned arr = atomicAdd(&g_bar, 1u);
        unsigned target = (arr / CSRB + 1u) * CSRB;
        while (*(volatile unsigned*)&g_bar < target) { }
    }
    __syncthreads();
}

__global__ void csr_kernel(const int* __restrict__ src, const int* __restrict__ dst,
                           int* __restrict__ cnt, int* __restrict__ off,
                           int* __restrict__ cur, int* __restrict__ csr) {
    __shared__ int sdata[256];
    const int b = blockIdx.x, t = threadIdx.x;
    for (int e = b * 256 + t; e < EE; e += CSRB * 256)
        atomicAdd(&cnt[dst[e]], 1);
    gridbar();
    int n0 = (b * 256 + t) * 2;
    int c0 = (n0 < NN) ? cnt[n0] : 0;
    int c1 = (n0 + 1 < NN) ? cnt[n0 + 1] : 0;
    if (n0 < NN) cnt[n0] = 0;
    if (n0 + 1 < NN) cnt[n0 + 1] = 0;
    int ts = c0 + c1;
    sdata[t] = ts;
    __syncthreads();
#pragma unroll
    for (int o = 1; o < 256; o <<= 1) {
        int v = (t >= o) ? sdata[t - o] : 0;
        __syncthreads();
        sdata[t] += v;
        __syncthreads();
    }
    int bexcl = sdata[t] - ts;
    if (t == 255) g_partial[b] = sdata[t];
    gridbar();
    if (b == 0) {
        int v = (t < CSRB) ? g_partial[t] : 0;
        sdata[t] = v;
        __syncthreads();
#pragma unroll
        for (int o = 1; o < 256; o <<= 1) {
            int w = (t >= o) ? sdata[t - o] : 0;
            __syncthreads();
            sdata[t] += w;
            __syncthreads();
        }
        if (t < CSRB) g_pscan[t] = sdata[t] - v;
        if (t == 0) off[0] = 0;
    }
    gridbar();
    int base = g_pscan[b] + bexcl;
    if (n0 < NN) {
        cur[n0] = base;
        off[n0 + 1] = base + c0;
        if (n0 + 1 < NN) {
            cur[n0 + 1] = base + c0;
            if (n0 + 2 <= NN) off[n0 + 2] = base + c0 + c1;
        }
    }
    gridbar();
    for (int e = b * 256 + t; e < EE; e += CSRB * 256) {
        int p = atomicAdd(&cur[dst[e]], 1);
        csr[p] = src[e];
    }
}

// ---------------- gather: zimg[d] = mean over in-edges of ximg[src] ----------------
__global__ void gather_img(const unsigned* __restrict__ xih, const unsigned* __restrict__ xil,
                           const int* __restrict__ off, const int* __restrict__ csr,
                           unsigned* __restrict__ zih, unsigned* __restrict__ zil) {
    int w = (blockIdx.x * 256 + threadIdx.x) >> 5;
    int d = w >> 2, c = w & 3;
    if (d >= NN) return;
    int lane = threadIdx.x & 31;
    int lc = lane * 2;
    int b = off[d], e = off[d + 1];
    float s0 = 0.f, s1 = 0.f;
    int j = b;
    for (; j + 1 < e; j += 2) {
        int r0 = csr[j], r1 = csr[j + 1];
        float2 v0 = img_read(xih, xil, c, r0, lc);
        float2 v1 = img_read(xih, xil, c, r1, lc);
        s0 += v0.x + v1.x;
        s1 += v0.y + v1.y;
    }
    if (j < e) {
        float2 v = img_read(xih, xil, c, csr[j], lc);
        s0 += v.x;
        s1 += v.y;
    }
    float iv = 1.f / fmaxf((float)(e - b), 1.f);
    img_write(zih, zil, c, d, lc, s0 * iv, s1 * iv);
}

// ---- fused-layer helpers ----
template <bool ALO>
static __device__ __forceinline__ void mma_slot(unsigned abase, unsigned bbase,
                                                float (&acc)[2][8][4], int wm0, int wn0,
                                                int lane) {
    const int lrow = lane & 15;
    const int lk = (lane >> 4) * 8;
#pragma unroll
    for (int ks = 0; ks < 4; ks++) {
        const int k0 = ks * 16;
        unsigned ahi[2][4], alo[2][4];
#pragma unroll
        for (int mi = 0; mi < 2; mi++) {
            unsigned off = SWZ((unsigned)((wm0 + mi * 16 + lrow) * 128 + (k0 + lk) * 2));
            ldsm4(ahi[mi], abase + off);
            if (ALO) ldsm4(alo[mi], abase + 16384 + off);
        }
#pragma unroll
        for (int h = 0; h < 2; h++) {
            unsigned bb[2][4];
#pragma unroll
            for (int nb = 0; nb < 2; nb++) {
                unsigned off = SWZ((unsigned)((wn0 + (h * 2 + nb) * 16 + lrow) * 128 + (k0 + lk) * 2));
                ldsm4(bb[nb], bbase + off);
            }
#pragma unroll
            for (int mi = 0; mi < 2; mi++)
#pragma unroll
                for (int f = 0; f < 4; f++) {
                    int nb = f >> 1, r0 = f & 1;
                    float* d = acc[mi][h * 4 + f];
                    mma16816(d, ahi[mi], bb[nb][r0], bb[nb][r0 + 2]);
                    if (ALO) mma16816(d, alo[mi], bb[nb][r0], bb[nb][r0 + 2]);
                }
        }
    }
}

// ---------------- fused layer kernel ----------------
// Stage slot map (36 B-slots, strict consume order, ring of 3, prefetch depth 3):
//   cat-x 0-3 (1-term), cat-z 4-7 (1-term), w1 8-11 (1-term),
//   wa0 12-15, wb0 16-19, wa1 20-23, wb1 24-27 (1-term),
//   w2 28-35 (3-term; hi,lo interleaved)
__global__ void __launch_bounds__(512, 1)
fused_layer(unsigned* __restrict__ ximg_hi, unsigned* __restrict__ ximg_lo,
            const unsigned* __restrict__ zimg_hi, SlotTab tab,
            const float* __restrict__ bl, const float* __restrict__ br,
            const float* __restrict__ b1,
            const float* __restrict__ ba0, const float* __restrict__ g0,
            const float* __restrict__ be0, const float* __restrict__ bb0,
            const float* __restrict__ ba1, const float* __restrict__ g1,
            const float* __restrict__ be1, const float* __restrict__ bb1,
            const float* __restrict__ b2, float bnscale,
            unsigned* __restrict__ himg_hi, unsigned* __restrict__ himg_lo) {
    extern __shared__ char smem[];
    const unsigned sb = smem_u32(smem);
    const int tid = threadIdx.x, wid = tid >> 5, lane = tid & 31;
    const int bm0 = blockIdx.x * 128;
    const int wm0 = (wid >> 2) * 32;
    const int wn0 = (wid & 3) * 64;
    const int tr = lane >> 2;
    const int tc2 = (lane & 3) * 2;

    float acc[2][8][4];
    auto zero_acc = [&]() {
#pragma unroll
        for (int a = 0; a < 2; a++)
#pragma unroll
            for (int b = 0; b < 8; b++)
#pragma unroll
                for (int c = 0; c < 4; c++) acc[a][b][c] = 0.f;
    };
    zero_acc();

    auto issue_B = [&](int s) {   // no commit
        if (s >= 36) return;
        const char* src = (const char*)tab.p[s];
        unsigned dstb = sb + FS_B + (unsigned)(s % 3) * 32768u;
#pragma unroll
        for (int i = 0; i < 4; i++) {
            int u = tid + i * 512;
            CPA(dstb + u * 16, src + u * 16);
        }
    };
    auto issue_z = [&](int c) {   // hi only (z consumed 1-term)
        const char* gh = (const char*)(zimg_hi + ((size_t)c * ROWSP + bm0) * 32);
        unsigned cb = sb + (unsigned)c * 32768u;
#pragma unroll
        for (int i = 0; i < 2; i++) {
            int u = tid + i * 512;
            CPA(cb + u * 16, gh + u * 16);
        }
    };
    // 1-term stage: 4 slots, one per A chunk
    auto run1 = [&](int s0, bool loadz) {
#pragma unroll 1
        for (int c = 0; c < 4; c++) {
            int s = s0 + c;
            unsigned abase = sb + (unsigned)c * 32768u;
            cp_wait<2>();
            __syncthreads();
            mma_slot<false>(abase, sb + FS_B + (unsigned)(s % 3) * 32768u, acc, wm0, wn0, lane);
            __syncthreads();
            issue_B(s + 3);
            if (loadz) issue_z(c);
            CP_COMMIT();
        }
    };
    // 3-term stage: 8 slots (hi,lo per chunk)
    auto run3 = [&](int s0) {
#pragma unroll 1
        for (int c = 0; c < 4; c++) {
            int s = s0 + c * 2;
            unsigned abase = sb + (unsigned)c * 32768u;
            cp_wait<2>();
            __syncthreads();
            mma_slot<true>(abase, sb + FS_B + (unsigned)(s % 3) * 32768u, acc, wm0, wn0, lane);
            __syncthreads();
            issue_B(s + 3);
            CP_COMMIT();
            cp_wait<2>();
            __syncthreads();
            mma_slot<false>(abase, sb + FS_B + (unsigned)((s + 1) % 3) * 32768u, acc, wm0, wn0, lane);
            __syncthreads();
            issue_B(s + 4);
            CP_COMMIT();
        }
    };
    auto conv_img = [&](bool lo) {   // acc -> smem A image
        unsigned cb = (unsigned)(wn0 >> 6) * 32768u;
#pragma unroll
        for (int mi = 0; mi < 2; mi++)
#pragma unroll
            for (int ni = 0; ni < 8; ni++) {
                int lc = ni * 8 + tc2;
                float* d = acc[mi][ni];
                unsigned h0, l0, h1, l1;
                bsplit(d[0], h0, l0); bsplit(d[1], h1, l1);
                unsigned off = SWZ((unsigned)((wm0 + mi * 16 + tr) * 128 + lc * 2));
                *(unsigned*)(smem + cb + off) = h0 | (h1 << 16);
                if (lo) *(unsigned*)(smem + cb + 16384 + off) = l0 | (l1 << 16);
                bsplit(d[2], h0, l0); bsplit(d[3], h1, l1);
                off = SWZ((unsigned)((wm0 + mi * 16 + 8 + tr) * 128 + lc * 2));
                *(unsigned*)(smem + cb + off) = h0 | (h1 << 16);
                if (lo) *(unsigned*)(smem + cb + 16384 + off) = l0 | (l1 << 16);
            }
    };

    // ---- prologue: x image (hi only; cat is 1-term) + first 3 B slots ----
#pragma unroll
    for (int c = 0; c < 4; c++) {
        const char* gh = (const char*)(ximg_hi + ((size_t)c * ROWSP + bm0) * 32);
        unsigned cb = sb + (unsigned)c * 32768u;
#pragma unroll
        for (int i = 0; i < 2; i++) {
            int u = tid + i * 512;
            CPA(cb + u * 16, gh + u * 16);
        }
    }
    CP_COMMIT();
    issue_B(0); CP_COMMIT();
    issue_B(1); CP_COMMIT();
    issue_B(2); CP_COMMIT();

    // ---- cat: x half slots 0-3 (z prefetch), z half slots 4-7 ----
    run1(0, true);
    run1(4, false);
#pragma unroll
    for (int mi = 0; mi < 2; mi++)
#pragma unroll
        for (int ni = 0; ni < 8; ni++) {
            int cg = wn0 + ni * 8 + tc2;
            float* d = acc[mi][ni];
            float a0 = bl[cg] + br[cg], a1 = bl[cg + 1] + br[cg + 1];
            d[0] += a0; d[1] += a1; d[2] += a0; d[3] += a1;
        }
    conv_img(false); zero_acc(); __syncthreads();

    // ---- w1: slots 8-11 -> h0 (write himg) ----
    run1(8, false);
#pragma unroll
    for (int mi = 0; mi < 2; mi++)
#pragma unroll
        for (int ni = 0; ni < 8; ni++) {
            int cg = wn0 + ni * 8 + tc2;
            float* d = acc[mi][ni];
            d[0] += b1[cg]; d[1] += b1[cg + 1]; d[2] += b1[cg]; d[3] += b1[cg + 1];
            int ra = bm0 + wm0 + mi * 16 + tr;
            img_write(himg_hi, himg_lo, cg >> 6, ra, cg & 63, d[0], d[1]);
            img_write(himg_hi, himg_lo, cg >> 6, ra + 8, cg & 63, d[2], d[3]);
        }
    conv_img(false); zero_acc(); __syncthreads();

    // ---- blocks (1-term): wa j: 12+8j, wb j: 16+8j ----
#pragma unroll 1
    for (int j = 0; j < 2; j++) {
        const float* ba = j ? ba1 : ba0;
        const float* gg = j ? g1 : g0;
        const float* be = j ? be1 : be0;
        const float* bb = j ? bb1 : bb0;
        run1(12 + j * 8, false);
#pragma unroll
        for (int mi = 0; mi < 2; mi++)
#pragma unroll
            for (int ni = 0; ni < 8; ni++) {
                int cg = wn0 + ni * 8 + tc2;
                float* d = acc[mi][ni];
                float ga = gg[cg], gb = gg[cg + 1], ea = be[cg], eb = be[cg + 1];
                float a0 = ba[cg], a1 = ba[cg + 1];
                d[0] = fmaf(ga, fmaxf(d[0] + a0, 0.f) * bnscale, ea);
                d[1] = fmaf(gb, fmaxf(d[1] + a1, 0.f) * bnscale, eb);
                d[2] = fmaf(ga, fmaxf(d[2] + a0, 0.f) * bnscale, ea);
                d[3] = fmaf(gb, fmaxf(d[3] + a1, 0.f) * bnscale, eb);
            }
        conv_img(false); zero_acc(); __syncthreads();
        run1(16 + j * 8, false);
#pragma unroll
        for (int mi = 0; mi < 2; mi++)
#pragma unroll
            for (int ni = 0; ni < 8; ni++) {
                int cg = wn0 + ni * 8 + tc2;
                float* d = acc[mi][ni];
                int ra = bm0 + wm0 + mi * 16 + tr;
                float2 ha = img_read(himg_hi, himg_lo, cg >> 6, ra, cg & 63);
                float2 hb = img_read(himg_hi, himg_lo, cg >> 6, ra + 8, cg & 63);
                d[0] += bb[cg] + ha.x; d[1] += bb[cg + 1] + ha.y;
                d[2] += bb[cg] + hb.x; d[3] += bb[cg + 1] + hb.y;
                if (j == 0) {
                    img_write(himg_hi, himg_lo, cg >> 6, ra, cg & 63, d[0], d[1]);
                    img_write(himg_hi, himg_lo, cg >> 6, ra + 8, cg & 63, d[2], d[3]);
                }
            }
        conv_img(j == 1); zero_acc(); __syncthreads();
    }

    // ---- w2 (3-term): slots 28-35, normalize + relu -> ximg ----
    run3(28);
#pragma unroll
    for (int mi = 0; mi < 2; mi++)
#pragma unroll
        for (int ni = 0; ni < 8; ni++) {
            int cg = wn0 + ni * 8 + tc2;
            float* d = acc[mi][ni];
            d[0] += b2[cg]; d[1] += b2[cg + 1]; d[2] += b2[cg]; d[3] += b2[cg + 1];
        }
    {
        float* rsum = (float*)(smem + FS_B);
        float ps[2][2] = {{0.f, 0.f}, {0.f, 0.f}};
#pragma unroll
        for (int mi = 0; mi < 2; mi++)
#pragma unroll
            for (int ni = 0; ni < 8; ni++) {
                float* d = acc[mi][ni];
                ps[mi][0] = fmaf(d[0], d[0], fmaf(d[1], d[1], ps[mi][0]));
                ps[mi][1] = fmaf(d[2], d[2], fmaf(d[3], d[3], ps[mi][1]));
            }
#pragma unroll
        for (int mi = 0; mi < 2; mi++)
#pragma unroll
            for (int q = 0; q < 2; q++) {
                ps[mi][q] += __shfl_xor_sync(0xffffffffu, ps[mi][q], 1);
                ps[mi][q] += __shfl_xor_sync(0xffffffffu, ps[mi][q], 2);
            }
        __syncthreads();
        if ((lane & 3) == 0) {
            int cw = wn0 >> 6;
#pragma unroll
            for (int mi = 0; mi < 2; mi++) {
                rsum[(wm0 + mi * 16 + tr) * 4 + cw] = ps[mi][0];
                rsum[(wm0 + mi * 16 + 8 + tr) * 4 + cw] = ps[mi][1];
            }
        }
        __syncthreads();
#pragma unroll
        for (int mi = 0; mi < 2; mi++) {
            int r0 = wm0 + mi * 16 + tr;
            int r1 = r0 + 8;
            float s0 = rsum[r0 * 4] + rsum[r0 * 4 + 1] + rsum[r0 * 4 + 2] + rsum[r0 * 4 + 3];
            float s1 = rsum[r1 * 4] + rsum[r1 * 4 + 1] + rsum[r1 * 4 + 2] + rsum[r1 * 4 + 3];
            float c0 = 1.f / fmaxf(sqrtf(s0), 1e-12f);
            float c1 = 1.f / fmaxf(sqrtf(s1), 1e-12f);
#pragma unroll
            for (int ni = 0; ni < 8; ni++) {
                float* d = acc[mi][ni];
                d[0] = fmaxf(d[0] * c0, 0.f); d[1] = fmaxf(d[1] * c0, 0.f);
                d[2] = fmaxf(d[2] * c1, 0.f); d[3] = fmaxf(d[3] * c1, 0.f);
            }
        }
    }
#pragma unroll
    for (int mi = 0; mi < 2; mi++)
#pragma unroll
        for (int ni = 0; ni < 8; ni++) {
            int cg = wn0 + ni * 8 + tc2;
            int ra = bm0 + wm0 + mi * 16 + tr;
            float* d = acc[mi][ni];
            img_write(ximg_hi, ximg_lo, cg >> 6, ra, cg & 63, d[0], d[1]);
            img_write(ximg_hi, ximg_lo, cg >> 6, ra + 8, cg & 63, d[2], d[3]);
        }
}

// ---------------- standalone GEMM (post layer, 3-term) ----------------
__global__ void __launch_bounds__(512, 1)
mma_gemm(const unsigned* __restrict__ Aimg_hi, const unsigned* __restrict__ Aimg_lo,
         const uint4* __restrict__ Whi, const uint4* __restrict__ Wlo,
         const float* __restrict__ bias, float* __restrict__ Of32, int M) {
    extern __shared__ char smem[];
    const unsigned sb = smem_u32(smem);
    const int tid = threadIdx.x, wid = tid >> 5, lane = tid & 31;
    const int bm0 = blockIdx.x * 128;

    if (tid < 256) ((float*)(smem + PBASE))[tid] = bias[tid];

    const int wm0 = (wid >> 2) * 32;
    const int wn0 = (wid & 3) * 64;
    const int lrow = lane & 15;
    const int lk = (lane >> 4) * 8;

    float acc[2][8][4];
#pragma unroll
    for (int a = 0; a < 2; a++)
#pragma unroll
        for (int b = 0; b < 8; b++)
#pragma unroll
            for (int c = 0; c < 4; c++) acc[a][b][c] = 0.f;

    auto issue = [&](int c, int st) {
        unsigned ab = sb + st * ABUF;
        unsigned bb = sb + BBASE + st * BBUF;
        const char* wh = (const char*)(Whi + (size_t)c * 2048);
        const char* wl = (const char*)(Wlo + (size_t)c * 2048);
#pragma unroll
        for (int i = 0; i < 4; i++) {
            int u = tid + i * 512;
            CPA(bb + u * 16, wh + u * 16);
            CPA(bb + 32768 + u * 16, wl + u * 16);
        }
        const char* ih = (const char*)(Aimg_hi + ((size_t)c * ROWSP + bm0) * 32);
        const char* il = (const char*)(Aimg_lo + ((size_t)c * ROWSP + bm0) * 32);
#pragma unroll
        for (int i = 0; i < 2; i++) {
            int u = tid + i * 512;
            CPA(ab + u * 16, ih + u * 16);
            CPA(ab + 16384 + u * 16, il + u * 16);
        }
    };

    issue(0, 0);
    CP_COMMIT();
    for (int c = 0; c < 4; c++) {
        int st = c & 1;
        if (c + 1 < 4) { issue(c + 1, st ^ 1); CP_COMMIT(); cp_wait<1>(); }
        else cp_wait<0>();
        __syncthreads();
        unsigned abase = sb + st * ABUF;
        unsigned bbase = sb + BBASE + st * BBUF;
#pragma unroll
        for (int ks = 0; ks < 4; ks++) {
            const int k0 = ks * 16;
            unsigned ahi[2][4], alo[2][4];
#pragma unroll
            for (int mi = 0; mi < 2; mi++) {
                unsigned off = SWZ((unsigned)((wm0 + mi * 16 + lrow) * 128 + (k0 + lk) * 2));
                ldsm4(ahi[mi], abase + off);
                ldsm4(alo[mi], abase + 16384 + off);
            }
#pragma unroll
            for (int h = 0; h < 2; h++) {
                unsigned bhi[2][4], blo[2][4];
#pragma unroll
                for (int nb = 0; nb < 2; nb++) {
                    unsigned off = SWZ((unsigned)((wn0 + (h * 2 + nb) * 16 + lrow) * 128 + (k0 + lk) * 2));
                    ldsm4(bhi[nb], bbase + off);
                    ldsm4(blo[nb], bbase + 32768 + off);
                }
#pragma unroll
                for (int mi = 0; mi < 2; mi++)
#pragma unroll
                    for (int f = 0; f < 4; f++) {
                        int nb = f >> 1, r0 = f & 1;
                        float* d = acc[mi][h * 4 + f];
                        mma16816(d, ahi[mi], bhi[nb][r0], bhi[nb][r0 + 2]);
                        mma16816(d, ahi[mi], blo[nb][r0], blo[nb][r0 + 2]);
                        mma16816(d, alo[mi], bhi[nb][r0], bhi[nb][r0 + 2]);
                    }
            }
        }
        __syncthreads();
    }

    const float* sbias = (const float*)(smem + PBASE);
    const int tr = lane >> 2;
    const int tc2 = (lane & 3) * 2;
#pragma unroll
    for (int mi = 0; mi < 2; mi++)
#pragma unroll
        for (int ni = 0; ni < 8; ni++) {
            int cg = wn0 + ni * 8 + tc2;
            int ra = bm0 + wm0 + mi * 16 + tr;
            int rb = ra + 8;
            float* d = acc[mi][ni];
            float v0 = d[0] + sbias[cg], v1 = d[1] + sbias[cg + 1];
            float v2 = d[2] + sbias[cg], v3 = d[3] + sbias[cg + 1];
            if (ra < M) *(float2*)(Of32 + (size_t)ra * 256 + cg) = make_float2(v0, v1);
            if (rb < M) *(float2*)(Of32 + (size_t)rb * 256 + cg) = make_float2(v2, v3);
        }
}

// ---------------- head ----------------
__global__ void head_kernel(const float* __restrict__ h, const float* __restrict__ W2,
                            const float* __restrict__ b2, float* __restrict__ out) {
    __shared__ float sW[256 * NCLS];
    __shared__ float sb[NCLS];
    int tid = threadIdx.x;
    for (int i = tid; i < 256 * NCLS; i += 256) sW[i] = W2[i];
    if (tid < NCLS) sb[tid] = b2[tid];
    __syncthreads();

    int wid = tid >> 5, lane = tid & 31;
    int r = blockIdx.x * 8 + wid;
    if (r >= NN) return;

    const float4* rp = (const float4*)(h + (size_t)r * DD);
    float4 q0 = rp[lane * 2];
    float4 q1 = rp[lane * 2 + 1];
    float hreg[8] = {q0.x, q0.y, q0.z, q0.w, q1.x, q1.y, q1.z, q1.w};

    int c0 = lane;
    int c1 = lane + 32;
    int c1m = (c1 < NCLS) ? c1 : (NCLS - 1);
    float acc0 = sb[c0];
    float acc1 = sb[c1m];
#pragma unroll
    for (int e = 0; e < 8; e++) {
        for (int l = 0; l < 32; l++) {
            float hv = __shfl_sync(0xffffffffu, hreg[e], l);
            int k = l * 8 + e;
            acc0 = fmaf(hv, sW[k * NCLS + c0], acc0);
            acc1 = fmaf(hv, sW[k * NCLS + c1m], acc1);
        }
    }
    float m = fmaxf(acc0, (c1 < NCLS) ? acc1 : -3.4e38f);
#pragma unroll
    for (int o = 16; o > 0; o >>= 1) m = fmaxf(m, __shfl_xor_sync(0xffffffffu, m, o));
    float es = expf(acc0 - m) + ((c1 < NCLS) ? expf(acc1 - m) : 0.f);
#pragma unroll
    for (int o = 16; o > 0; o >>= 1) es += __shfl_xor_sync(0xffffffffu, es, o);
    float lse = m + logf(es);
    out[(size_t)r * NCLS + c0] = acc0 - lse;
    if (c1 < NCLS) out[(size_t)r * NCLS + c1] = acc1 - lse;
}

// ---------------- host orchestration ----------------
extern "C" void kernel_launch(void* const* d_in, const int* in_sizes, int n_in,
                              void* d_out, int out_size) {
    const float* x_in      = (const float*)d_in[0];
    const int* ei          = (const int*)d_in[1];
    const float* lin_l_W   = (const float*)d_in[2];
    const float* lin_l_b   = (const float*)d_in[3];
    const float* lin_r_W   = (const float*)d_in[4];
    const float* lin_r_b   = (const float*)d_in[5];
    const float* mlp_W1    = (const float*)d_in[6];
    const float* mlp_b1    = (const float*)d_in[7];
    const float* blk_Wa    = (const float*)d_in[8];
    const float* blk_ba    = (const float*)d_in[9];
    const float* blk_gamma = (const float*)d_in[10];
    const float* blk_beta  = (const float*)d_in[11];
    const float* blk_Wb    = (const float*)d_in[12];
    const float* blk_bb    = (const float*)d_in[13];
    const float* mlp_W2    = (const float*)d_in[14];
    const float* mlp_b2    = (const float*)d_in[15];
    const float* post_W1   = (const float*)d_in[16];
    const float* post_b1   = (const float*)d_in[17];
    const float* post_W2   = (const float*)d_in[18];
    const float* post_b2   = (const float*)d_in[19];
    float* out = (float*)d_out;

    float* pp;
    uint4 *whi, *wlo;
    unsigned *xih, *xil, *zih, *zil, *hih, *hil;
    int *cnti, *offp, *curp, *csrp;
    cudaGetSymbolAddress((void**)&pp, g_p);
    cudaGetSymbolAddress((void**)&whi, g_whi4);
    cudaGetSymbolAddress((void**)&wlo, g_wlo4);
    cudaGetSymbolAddress((void**)&xih, g_ximg_hi);
    cudaGetSymbolAddress((void**)&xil, g_ximg_lo);
    cudaGetSymbolAddress((void**)&zih, g_zimg_hi);
    cudaGetSymbolAddress((void**)&zil, g_zimg_lo);
    cudaGetSymbolAddress((void**)&hih, g_himg_hi);
    cudaGetSymbolAddress((void**)&hil, g_himg_lo);
    cudaGetSymbolAddress((void**)&cnti, g_cnti);
    cudaGetSymbolAddress((void**)&offp, g_off);
    cudaGetSymbolAddress((void**)&curp, g_cur);
    cudaGetSymbolAddress((void**)&csrp, g_csr);

    cudaFuncSetAttribute(fused_layer, cudaFuncAttributeMaxDynamicSharedMemorySize, FSMEM);
    cudaFuncSetAttribute(mma_gemm, cudaFuncAttributeMaxDynamicSharedMemorySize, SMEM_SZ);

    const float bnscale = rsqrtf(1.0f + 1e-5f);
    const int* src = ei;
    const int* dst = ei + EE;

    // 1: setup (weights + x image)
    setup_kernel<<<31400, 256>>>(lin_l_W, lin_r_W, mlp_W1, blk_Wa, blk_Wb, mlp_W2, post_W1,
                                 x_in, (unsigned short*)whi, (unsigned short*)wlo, xih, xil);
    // 2: CSR (count+scan+fill, one persistent kernel)
    csr_kernel<<<CSRB, 256>>>(src, dst, cnti, offp, curp, csrp);

    for (int i = 0; i < NLAYER; i++) {
        // 3: gather
        gather_img<<<(NN + 1) / 2, 256>>>(xih, xil, offp, csrp, zih, zil);

        SlotTab tab;
        int s = 0;
        auto push2 = [&](int base, int n) {
            for (int c = 0; c < n; c++) {
                tab.p[s++] = whi + (size_t)(base + c) * 2048;
                tab.p[s++] = wlo + (size_t)(base + c) * 2048;
            }
        };
        auto push1 = [&](int base, int n) {
            for (int c = 0; c < n; c++) tab.p[s++] = whi + (size_t)(base + c) * 2048;
        };
        push1(i * 8, 4);                 // cat-x (lin_l)           slots 0-3
        push1(i * 8 + 4, 4);             // cat-z (lin_r)           slots 4-7
        push1(24 + i * 4, 4);            // w1                      slots 8-11
        push1(36 + (2 * i) * 4, 4);      // wa0                     slots 12-15
        push1(60 + (2 * i) * 4, 4);      // wb0                     slots 16-19
        push1(36 + (2 * i + 1) * 4, 4);  // wa1                     slots 20-23
        push1(60 + (2 * i + 1) * 4, 4);  // wb1                     slots 24-27
        push2(84 + i * 4, 4);            // w2 (3-term)             slots 28-35

        size_t bo0 = ((size_t)i * 2) * 256, bo1 = ((size_t)i * 2 + 1) * 256;
        // 4: fused layer  <-- profiled launch
        fused_layer<<<NB, 512, FSMEM>>>(
            xih, xil, zih, tab,
            lin_l_b + (size_t)i * 256, lin_r_b + (size_t)i * 256,
            mlp_b1 + (size_t)i * 256,
            blk_ba + bo0, blk_gamma + bo0, blk_beta + bo0, blk_bb + bo0,
            blk_ba + bo1, blk_gamma + bo1, blk_beta + bo1, blk_bb + bo1,
            mlp_b2 + (size_t)i * 256, bnscale,
            hih, hil);
    }

    mma_gemm<<<NB, 512, SMEM_SZ>>>(xih, xil, whi + (size_t)96 * 2048,
                                   wlo + (size_t)96 * 2048, post_b1, pp, NN);
    head_kernel<<<(NN + 7) / 8, 256>>>(pp, post_W2, post_b2, out);
}

// round 10
// speedup vs baseline: 3.8470x; 1.1597x over previous
#include <cuda_runtime.h>
#include <cuda_bf16.h>
#include <math.h>

#define NN 50000
#define ROWSP 50048
#define DD 256
#define EE 800000
#define NCLS 47
#define NLAYER 3
#define NB 391
#define CSRB 148

#define SWZ(x) ((x) ^ (((x) >> 3) & 0x70))

// ---- standalone (post) gemm smem layout ----
#define ABUF 32768
#define BBASE 65536
#define BBUF 65536
#define PBASE 196608
#define SMEM_SZ 201728

// ---- fused kernel smem layout ----
#define FS_B 131072
#define FSMEM 229376   // 128KB A-image + 3x32KB B ring

// ---------------- device scratch ----------------
__device__ float g_p[ROWSP * DD];
__device__ uint4 g_whi4[100 * 2048];
__device__ uint4 g_wlo4[100 * 2048];
__device__ unsigned g_ximg_hi[4 * ROWSP * 32];
__device__ unsigned g_ximg_lo[4 * ROWSP * 32];
__device__ unsigned g_zimg_hi[4 * ROWSP * 32];
__device__ unsigned g_himg_hi[4 * ROWSP * 32];
__device__ unsigned g_himg_lo[4 * ROWSP * 32];
__device__ int g_cnti[NN];          // static zero-init; self-zeroed each run
__device__ int g_off[NN + 1];
__device__ int g_cur[NN];
__device__ int g_csr[EE];
__device__ int g_partial[CSRB];
__device__ int g_pscan[CSRB];
__device__ unsigned g_bar;

struct SlotTab { const uint4* p[32]; };

static __device__ __forceinline__ unsigned smem_u32(const void* p) {
    unsigned a;
    asm("{ .reg .u64 t; cvta.to.shared.u64 t, %1; cvt.u32.u64 %0, t; }" : "=r"(a) : "l"(p));
    return a;
}
static __device__ __forceinline__ void ldsm4(unsigned r[4], unsigned addr) {
    asm volatile("ldmatrix.sync.aligned.m8n8.x4.shared.b16 {%0,%1,%2,%3}, [%4];"
                 : "=r"(r[0]), "=r"(r[1]), "=r"(r[2]), "=r"(r[3]) : "r"(addr));
}
static __device__ __forceinline__ void mma16816(float d[4], const unsigned a[4],
                                                unsigned b0, unsigned b1) {
    asm volatile(
        "mma.sync.aligned.m16n8k16.row.col.f32.bf16.bf16.f32 "
        "{%0,%1,%2,%3}, {%4,%5,%6,%7}, {%8,%9}, {%0,%1,%2,%3};"
        : "+f"(d[0]), "+f"(d[1]), "+f"(d[2]), "+f"(d[3])
        : "r"(a[0]), "r"(a[1]), "r"(a[2]), "r"(a[3]), "r"(b0), "r"(b1));
}
#define CPA(dst, src) \
    asm volatile("cp.async.cg.shared.global [%0], [%1], 16;" :: "r"(dst), "l"(src) : "memory")
#define CP_COMMIT() asm volatile("cp.async.commit_group;" ::: "memory")
template <int N>
static __device__ __forceinline__ void cp_wait() {
    asm volatile("cp.async.wait_group %0;" :: "n"(N) : "memory");
}

static __device__ __forceinline__ void bsplit(float v, unsigned& h, unsigned& l) {
    __nv_bfloat16 hb = __float2bfloat16(v);
    h = __bfloat16_as_ushort(hb);
    l = __bfloat16_as_ushort(__float2bfloat16(v - __bfloat162float(hb)));
}
static __device__ __forceinline__ unsigned bhi(float v) {
    return (unsigned)__bfloat16_as_ushort(__float2bfloat16(v));
}
static __device__ __forceinline__ unsigned img_idx(int chunk, int row, int lc) {
    return ((unsigned)chunk * ROWSP + (unsigned)row) * 32u +
           ((((unsigned)(lc * 2)) ^ (((unsigned)row & 7u) << 4)) >> 2);
}
static __device__ __forceinline__ void img_write(unsigned* __restrict__ hi,
                                                 unsigned* __restrict__ lo, int chunk,
                                                 int row, int lc, float v0, float v1) {
    unsigned h0, l0, h1, l1;
    bsplit(v0, h0, l0);
    bsplit(v1, h1, l1);
    unsigned idx = img_idx(chunk, row, lc);
    hi[idx] = h0 | (h1 << 16);
    lo[idx] = l0 | (l1 << 16);
}
static __device__ __forceinline__ void img_write_hi(unsigned* __restrict__ hi, int chunk,
                                                    int row, int lc, float v0, float v1) {
    hi[img_idx(chunk, row, lc)] = bhi(v0) | (bhi(v1) << 16);
}
static __device__ __forceinline__ float2 img_read(const unsigned* __restrict__ hi,
                                                  const unsigned* __restrict__ lo, int chunk,
                                                  int row, int lc) {
    unsigned idx = img_idx(chunk, row, lc);
    unsigned h = hi[idx], l = lo[idx];
    float x0 = __bfloat162float(__ushort_as_bfloat16((unsigned short)(h & 0xffff))) +
               __bfloat162float(__ushort_as_bfloat16((unsigned short)(l & 0xffff)));
    float x1 = __bfloat162float(__ushort_as_bfloat16((unsigned short)(h >> 16))) +
               __bfloat162float(__ushort_as_bfloat16((unsigned short)(l >> 16)));
    return make_float2(x0, x1);
}
static __device__ __forceinline__ float2 img_read_hi(const unsigned* __restrict__ hi,
                                                     int chunk, int row, int lc) {
    unsigned h = hi[img_idx(chunk, row, lc)];
    return make_float2(
        __bfloat162float(__ushort_as_bfloat16((unsigned short)(h & 0xffff))),
        __bfloat162float(__ushort_as_bfloat16((unsigned short)(h >> 16))));
}

// ---------------- setup: weight prep + x image (ONE launch) ----------------
__global__ void setup_kernel(const float* __restrict__ linl, const float* __restrict__ linr,
                             const float* __restrict__ w1, const float* __restrict__ wa,
                             const float* __restrict__ wb, const float* __restrict__ w2,
                             const float* __restrict__ post, const float* __restrict__ X,
                             unsigned short* __restrict__ dhi, unsigned short* __restrict__ dlo,
                             unsigned* __restrict__ xih, unsigned* __restrict__ xil) {
    int b = blockIdx.x;
    if (b < 6400) {
        int idx = b * 256 + threadIdx.x;
        int m = idx >> 16;
        int rem = idx & 65535;
        int n = rem & 255, k = rem >> 8;
        const float* W;
        int chunk;
        if (m < 3)       { W = linl + (size_t)m * 65536;       chunk = 0  + m * 8 + (k >> 6); }
        else if (m < 6)  { W = linr + (size_t)(m - 3) * 65536; chunk = 4  + (m - 3) * 8 + (k >> 6); }
        else if (m < 9)  { W = w1 + (size_t)(m - 6) * 65536;   chunk = 24 + (m - 6) * 4 + (k >> 6); }
        else if (m < 15) { W = wa + (size_t)(m - 9) * 65536;   chunk = 36 + (m - 9) * 4 + (k >> 6); }
        else if (m < 21) { W = wb + (size_t)(m - 15) * 65536;  chunk = 60 + (m - 15) * 4 + (k >> 6); }
        else if (m < 24) { W = w2 + (size_t)(m - 21) * 65536;  chunk = 84 + (m - 21) * 4 + (k >> 6); }
        else             { W = post;                           chunk = 96 + (k >> 6); }
        float v = W[(size_t)k * 256 + n];
        unsigned h, l;
        bsplit(v, h, l);
        unsigned off = (unsigned)chunk * 32768u + SWZ((unsigned)(n * 128 + (k & 63) * 2));
        dhi[off >> 1] = (unsigned short)h;
        dlo[off >> 1] = (unsigned short)l;
    } else {
        int idx = (b - 6400) * 256 + threadIdx.x;   // < NN*128 exactly
        int row = idx >> 7, p = idx & 127;
        float v0 = X[(size_t)row * 256 + p * 2];
        float v1 = X[(size_t)row * 256 + p * 2 + 1];
        img_write(xih, xil, (p * 2) >> 6, row, (p * 2) & 63, v0, v1);
    }
}

// ---------------- single-kernel CSR build (persistent grid + sw barrier) ----------------
static __device__ __forceinline__ void gridbar() {
    __syncthreads();
    __threadfence();
    if (threadIdx.x == 0) {
        unsigned arr = atomicAdd(&g_bar, 1u);
        unsigned target = (arr / CSRB + 1u) * CSRB;
        while (*(volatile unsigned*)&g_bar < target) { }
    }
    __syncthreads();
}

__global__ void csr_kernel(const int* __restrict__ src, const int* __restrict__ dst,
                           int* __restrict__ cnt, int* __restrict__ off,
                           int* __restrict__ cur, int* __restrict__ csr) {
    __shared__ int sdata[256];
    const int b = blockIdx.x, t = threadIdx.x;
    for (int e = b * 256 + t; e < EE; e += CSRB * 256)
        atomicAdd(&cnt[dst[e]], 1);
    gridbar();
    int n0 = (b * 256 + t) * 2;
    int c0 = (n0 < NN) ? cnt[n0] : 0;
    int c1 = (n0 + 1 < NN) ? cnt[n0 + 1] : 0;
    if (n0 < NN) cnt[n0] = 0;
    if (n0 + 1 < NN) cnt[n0 + 1] = 0;
    int ts = c0 + c1;
    sdata[t] = ts;
    __syncthreads();
#pragma unroll
    for (int o = 1; o < 256; o <<= 1) {
        int v = (t >= o) ? sdata[t - o] : 0;
        __syncthreads();
        sdata[t] += v;
        __syncthreads();
    }
    int bexcl = sdata[t] - ts;
    if (t == 255) g_partial[b] = sdata[t];
    gridbar();
    if (b == 0) {
        int v = (t < CSRB) ? g_partial[t] : 0;
        sdata[t] = v;
        __syncthreads();
#pragma unroll
        for (int o = 1; o < 256; o <<= 1) {
            int w = (t >= o) ? sdata[t - o] : 0;
            __syncthreads();
            sdata[t] += w;
            __syncthreads();
        }
        if (t < CSRB) g_pscan[t] = sdata[t] - v;
        if (t == 0) off[0] = 0;
    }
    gridbar();
    int base = g_pscan[b] + bexcl;
    if (n0 < NN) {
        cur[n0] = base;
        off[n0 + 1] = base + c0;
        if (n0 + 1 < NN) {
            cur[n0 + 1] = base + c0;
            if (n0 + 2 <= NN) off[n0 + 2] = base + c0 + c1;
        }
    }
    gridbar();
    for (int e = b * 256 + t; e < EE; e += CSRB * 256) {
        int p = atomicAdd(&cur[dst[e]], 1);
        csr[p] = src[e];
    }
}

// ---------------- gather (hi-only): zimg_hi[d] = mean of ximg_hi[src] ----------------
__global__ void gather_img(const unsigned* __restrict__ xih,
                           const int* __restrict__ off, const int* __restrict__ csr,
                           unsigned* __restrict__ zih) {
    int w = (blockIdx.x * 256 + threadIdx.x) >> 5;
    int d = w >> 2, c = w & 3;
    if (d >= NN) return;
    int lane = threadIdx.x & 31;
    int lc = lane * 2;
    int b = off[d], e = off[d + 1];
    float s0 = 0.f, s1 = 0.f;
    int j = b;
    for (; j + 1 < e; j += 2) {
        int r0 = csr[j], r1 = csr[j + 1];
        float2 v0 = img_read_hi(xih, c, r0, lc);
        float2 v1 = img_read_hi(xih, c, r1, lc);
        s0 += v0.x + v1.x;
        s1 += v0.y + v1.y;
    }
    if (j < e) {
        float2 v = img_read_hi(xih, c, csr[j], lc);
        s0 += v.x;
        s1 += v.y;
    }
    float iv = 1.f / fmaxf((float)(e - b), 1.f);
    img_write_hi(zih, c, d, lc, s0 * iv, s1 * iv);
}

// ---- fused-layer helpers ----
template <bool ALO>
static __device__ __forceinline__ void mma_slot(unsigned abase, unsigned bbase,
                                                float (&acc)[2][8][4], int wm0, int wn0,
                                                int lane) {
    const int lrow = lane & 15;
    const int lk = (lane >> 4) * 8;
#pragma unroll
    for (int ks = 0; ks < 4; ks++) {
        const int k0 = ks * 16;
        unsigned ahi[2][4], alo[2][4];
#pragma unroll
        for (int mi = 0; mi < 2; mi++) {
            unsigned off = SWZ((unsigned)((wm0 + mi * 16 + lrow) * 128 + (k0 + lk) * 2));
            ldsm4(ahi[mi], abase + off);
            if (ALO) ldsm4(alo[mi], abase + 16384 + off);
        }
#pragma unroll
        for (int h = 0; h < 2; h++) {
            unsigned bb[2][4];
#pragma unroll
            for (int nb = 0; nb < 2; nb++) {
                unsigned off = SWZ((unsigned)((wn0 + (h * 2 + nb) * 16 + lrow) * 128 + (k0 + lk) * 2));
                ldsm4(bb[nb], bbase + off);
            }
#pragma unroll
            for (int mi = 0; mi < 2; mi++)
#pragma unroll
                for (int f = 0; f < 4; f++) {
                    int nb = f >> 1, r0 = f & 1;
                    float* d = acc[mi][h * 4 + f];
                    mma16816(d, ahi[mi], bb[nb][r0], bb[nb][r0 + 2]);
                    if (ALO) mma16816(d, alo[mi], bb[nb][r0], bb[nb][r0 + 2]);
                }
        }
    }
}

// ---------------- fused layer kernel ----------------
// Stage slot map (32 B-slots, all 1-term, strict consume order, ring of 3):
//   cat-x 0-3, cat-z 4-7, w1 8-11, wa0 12-15, wb0 16-19, wa1 20-23, wb1 24-27, w2 28-31
__global__ void __launch_bounds__(512, 1)
fused_layer(unsigned* __restrict__ ximg_hi, unsigned* __restrict__ ximg_lo,
            const unsigned* __restrict__ zimg_hi, SlotTab tab,
            const float* __restrict__ bl, const float* __restrict__ br,
            const float* __restrict__ b1,
            const float* __restrict__ ba0, const float* __restrict__ g0,
            const float* __restrict__ be0, const float* __restrict__ bb0,
            const float* __restrict__ ba1, const float* __restrict__ g1,
            const float* __restrict__ be1, const float* __restrict__ bb1,
            const float* __restrict__ b2, float bnscale,
            unsigned* __restrict__ himg_hi, unsigned* __restrict__ himg_lo) {
    extern __shared__ char smem[];
    const unsigned sb = smem_u32(smem);
    const int tid = threadIdx.x, wid = tid >> 5, lane = tid & 31;
    const int bm0 = blockIdx.x * 128;
    const int wm0 = (wid >> 2) * 32;
    const int wn0 = (wid & 3) * 64;
    const int tr = lane >> 2;
    const int tc2 = (lane & 3) * 2;

    float acc[2][8][4];
    auto zero_acc = [&]() {
#pragma unroll
        for (int a = 0; a < 2; a++)
#pragma unroll
            for (int b = 0; b < 8; b++)
#pragma unroll
                for (int c = 0; c < 4; c++) acc[a][b][c] = 0.f;
    };
    zero_acc();

    auto issue_B = [&](int s) {   // no commit
        if (s >= 32) return;
        const char* src = (const char*)tab.p[s];
        unsigned dstb = sb + FS_B + (unsigned)(s % 3) * 32768u;
#pragma unroll
        for (int i = 0; i < 4; i++) {
            int u = tid + i * 512;
            CPA(dstb + u * 16, src + u * 16);
        }
    };
    auto issue_z = [&](int c) {   // hi only
        const char* gh = (const char*)(zimg_hi + ((size_t)c * ROWSP + bm0) * 32);
        unsigned cb = sb + (unsigned)c * 32768u;
#pragma unroll
        for (int i = 0; i < 2; i++) {
            int u = tid + i * 512;
            CPA(cb + u * 16, gh + u * 16);
        }
    };
    // 1-term stage: 4 slots, one per A chunk
    auto run1 = [&](int s0, bool loadz) {
#pragma unroll 1
        for (int c = 0; c < 4; c++) {
            int s = s0 + c;
            unsigned abase = sb + (unsigned)c * 32768u;
            cp_wait<2>();
            __syncthreads();
            mma_slot<false>(abase, sb + FS_B + (unsigned)(s % 3) * 32768u, acc, wm0, wn0, lane);
            __syncthreads();
            issue_B(s + 3);
            if (loadz) issue_z(c);
            CP_COMMIT();
        }
    };
    auto conv_img = [&]() {   // acc -> smem A image (hi only)
        unsigned cb = (unsigned)(wn0 >> 6) * 32768u;
#pragma unroll
        for (int mi = 0; mi < 2; mi++)
#pragma unroll
            for (int ni = 0; ni < 8; ni++) {
                int lc = ni * 8 + tc2;
                float* d = acc[mi][ni];
                unsigned off = SWZ((unsigned)((wm0 + mi * 16 + tr) * 128 + lc * 2));
                *(unsigned*)(smem + cb + off) = bhi(d[0]) | (bhi(d[1]) << 16);
                off = SWZ((unsigned)((wm0 + mi * 16 + 8 + tr) * 128 + lc * 2));
                *(unsigned*)(smem + cb + off) = bhi(d[2]) | (bhi(d[3]) << 16);
            }
    };

    // ---- prologue: x image (hi only) + first 3 B slots ----
#pragma unroll
    for (int c = 0; c < 4; c++) {
        const char* gh = (const char*)(ximg_hi + ((size_t)c * ROWSP + bm0) * 32);
        unsigned cb = sb + (unsigned)c * 32768u;
#pragma unroll
        for (int i = 0; i < 2; i++) {
            int u = tid + i * 512;
            CPA(cb + u * 16, gh + u * 16);
        }
    }
    CP_COMMIT();
    issue_B(0); CP_COMMIT();
    issue_B(1); CP_COMMIT();
    issue_B(2); CP_COMMIT();

    // ---- cat: x half slots 0-3 (z prefetch), z half slots 4-7 ----
    run1(0, true);
    run1(4, false);
#pragma unroll
    for (int mi = 0; mi < 2; mi++)
#pragma unroll
        for (int ni = 0; ni < 8; ni++) {
            int cg = wn0 + ni * 8 + tc2;
            float* d = acc[mi][ni];
            float a0 = bl[cg] + br[cg], a1 = bl[cg + 1] + br[cg + 1];
            d[0] += a0; d[1] += a1; d[2] += a0; d[3] += a1;
        }
    conv_img(); zero_acc(); __syncthreads();

    // ---- w1: slots 8-11 -> h0 (write himg) ----
    run1(8, false);
#pragma unroll
    for (int mi = 0; mi < 2; mi++)
#pragma unroll
        for (int ni = 0; ni < 8; ni++) {
            int cg = wn0 + ni * 8 + tc2;
            float* d = acc[mi][ni];
            d[0] += b1[cg]; d[1] += b1[cg + 1]; d[2] += b1[cg]; d[3] += b1[cg + 1];
            int ra = bm0 + wm0 + mi * 16 + tr;
            img_write(himg_hi, himg_lo, cg >> 6, ra, cg & 63, d[0], d[1]);
            img_write(himg_hi, himg_lo, cg >> 6, ra + 8, cg & 63, d[2], d[3]);
        }
    conv_img(); zero_acc(); __syncthreads();

    // ---- blocks: wa j: 12+8j, wb j: 16+8j ----
#pragma unroll 1
    for (int j = 0; j < 2; j++) {
        const float* ba = j ? ba1 : ba0;
        const float* gg = j ? g1 : g0;
        const float* be = j ? be1 : be0;
        const float* bb = j ? bb1 : bb0;
        run1(12 + j * 8, false);
#pragma unroll
        for (int mi = 0; mi < 2; mi++)
#pragma unroll
            for (int ni = 0; ni < 8; ni++) {
                int cg = wn0 + ni * 8 + tc2;
                float* d = acc[mi][ni];
                float ga = gg[cg], gb = gg[cg + 1], ea = be[cg], eb = be[cg + 1];
                float a0 = ba[cg], a1 = ba[cg + 1];
                d[0] = fmaf(ga, fmaxf(d[0] + a0, 0.f) * bnscale, ea);
                d[1] = fmaf(gb, fmaxf(d[1] + a1, 0.f) * bnscale, eb);
                d[2] = fmaf(ga, fmaxf(d[2] + a0, 0.f) * bnscale, ea);
                d[3] = fmaf(gb, fmaxf(d[3] + a1, 0.f) * bnscale, eb);
            }
        conv_img(); zero_acc(); __syncthreads();
        run1(16 + j * 8, false);
#pragma unroll
        for (int mi = 0; mi < 2; mi++)
#pragma unroll
            for (int ni = 0; ni < 8; ni++) {
                int cg = wn0 + ni * 8 + tc2;
                float* d = acc[mi][ni];
                int ra = bm0 + wm0 + mi * 16 + tr;
                float2 ha = img_read(himg_hi, himg_lo, cg >> 6, ra, cg & 63);
                float2 hb = img_read(himg_hi, himg_lo, cg >> 6, ra + 8, cg & 63);
                d[0] += bb[cg] + ha.x; d[1] += bb[cg + 1] + ha.y;
                d[2] += bb[cg] + hb.x; d[3] += bb[cg + 1] + hb.y;
                if (j == 0) {
                    img_write(himg_hi, himg_lo, cg >> 6, ra, cg & 63, d[0], d[1]);
                    img_write(himg_hi, himg_lo, cg >> 6, ra + 8, cg & 63, d[2], d[3]);
                }
            }
        conv_img(); zero_acc(); __syncthreads();
    }

    // ---- w2 (1-term): slots 28-31, normalize + relu -> ximg ----
    run1(28, false);
#pragma unroll
    for (int mi = 0; mi < 2; mi++)
#pragma unroll
        for (int ni = 0; ni < 8; ni++) {
            int cg = wn0 + ni * 8 + tc2;
            float* d = acc[mi][ni];
            d[0] += b2[cg]; d[1] += b2[cg + 1]; d[2] += b2[cg]; d[3] += b2[cg + 1];
        }
    {
        float* rsum = (float*)(smem + FS_B);
        float ps[2][2] = {{0.f, 0.f}, {0.f, 0.f}};
#pragma unroll
        for (int mi = 0; mi < 2; mi++)
#pragma unroll
            for (int ni = 0; ni < 8; ni++) {
                float* d = acc[mi][ni];
                ps[mi][0] = fmaf(d[0], d[0], fmaf(d[1], d[1], ps[mi][0]));
                ps[mi][1] = fmaf(d[2], d[2], fmaf(d[3], d[3], ps[mi][1]));
            }
#pragma unroll
        for (int mi = 0; mi < 2; mi++)
#pragma unroll
            for (int q = 0; q < 2; q++) {
                ps[mi][q] += __shfl_xor_sync(0xffffffffu, ps[mi][q], 1);
                ps[mi][q] += __shfl_xor_sync(0xffffffffu, ps[mi][q], 2);
            }
        __syncthreads();
        if ((lane & 3) == 0) {
            int cw = wn0 >> 6;
#pragma unroll
            for (int mi = 0; mi < 2; mi++) {
                rsum[(wm0 + mi * 16 + tr) * 4 + cw] = ps[mi][0];
                rsum[(wm0 + mi * 16 + 8 + tr) * 4 + cw] = ps[mi][1];
            }
        }
        __syncthreads();
#pragma unroll
        for (int mi = 0; mi < 2; mi++) {
            int r0 = wm0 + mi * 16 + tr;
            int r1 = r0 + 8;
            float s0 = rsum[r0 * 4] + rsum[r0 * 4 + 1] + rsum[r0 * 4 + 2] + rsum[r0 * 4 + 3];
            float s1 = rsum[r1 * 4] + rsum[r1 * 4 + 1] + rsum[r1 * 4 + 2] + rsum[r1 * 4 + 3];
            float c0 = 1.f / fmaxf(sqrtf(s0), 1e-12f);
            float c1 = 1.f / fmaxf(sqrtf(s1), 1e-12f);
#pragma unroll
            for (int ni = 0; ni < 8; ni++) {
                float* d = acc[mi][ni];
                d[0] = fmaxf(d[0] * c0, 0.f); d[1] = fmaxf(d[1] * c0, 0.f);
                d[2] = fmaxf(d[2] * c1, 0.f); d[3] = fmaxf(d[3] * c1, 0.f);
            }
        }
    }
#pragma unroll
    for (int mi = 0; mi < 2; mi++)
#pragma unroll
        for (int ni = 0; ni < 8; ni++) {
            int cg = wn0 + ni * 8 + tc2;
            int ra = bm0 + wm0 + mi * 16 + tr;
            float* d = acc[mi][ni];
            img_write(ximg_hi, ximg_lo, cg >> 6, ra, cg & 63, d[0], d[1]);
            img_write(ximg_hi, ximg_lo, cg >> 6, ra + 8, cg & 63, d[2], d[3]);
        }
}

// ---------------- standalone GEMM (post layer, 3-term) ----------------
__global__ void __launch_bounds__(512, 1)
mma_gemm(const unsigned* __restrict__ Aimg_hi, const unsigned* __restrict__ Aimg_lo,
         const uint4* __restrict__ Whi, const uint4* __restrict__ Wlo,
         const float* __restrict__ bias, float* __restrict__ Of32, int M) {
    extern __shared__ char smem[];
    const unsigned sb = smem_u32(smem);
    const int tid = threadIdx.x, wid = tid >> 5, lane = tid & 31;
    const int bm0 = blockIdx.x * 128;

    if (tid < 256) ((float*)(smem + PBASE))[tid] = bias[tid];

    const int wm0 = (wid >> 2) * 32;
    const int wn0 = (wid & 3) * 64;
    const int lrow = lane & 15;
    const int lk = (lane >> 4) * 8;

    float acc[2][8][4];
#pragma unroll
    for (int a = 0; a < 2; a++)
#pragma unroll
        for (int b = 0; b < 8; b++)
#pragma unroll
            for (int c = 0; c < 4; c++) acc[a][b][c] = 0.f;

    auto issue = [&](int c, int st) {
        unsigned ab = sb + st * ABUF;
        unsigned bb = sb + BBASE + st * BBUF;
        const char* wh = (const char*)(Whi + (size_t)c * 2048);
        const char* wl = (const char*)(Wlo + (size_t)c * 2048);
#pragma unroll
        for (int i = 0; i < 4; i++) {
            int u = tid + i * 512;
            CPA(bb + u * 16, wh + u * 16);
            CPA(bb + 32768 + u * 16, wl + u * 16);
        }
        const char* ih = (const char*)(Aimg_hi + ((size_t)c * ROWSP + bm0) * 32);
        const char* il = (const char*)(Aimg_lo + ((size_t)c * ROWSP + bm0) * 32);
#pragma unroll
        for (int i = 0; i < 2; i++) {
            int u = tid + i * 512;
            CPA(ab + u * 16, ih + u * 16);
            CPA(ab + 16384 + u * 16, il + u * 16);
        }
    };

    issue(0, 0);
    CP_COMMIT();
    for (int c = 0; c < 4; c++) {
        int st = c & 1;
        if (c + 1 < 4) { issue(c + 1, st ^ 1); CP_COMMIT(); cp_wait<1>(); }
        else cp_wait<0>();
        __syncthreads();
        unsigned abase = sb + st * ABUF;
        unsigned bbase = sb + BBASE + st * BBUF;
#pragma unroll
        for (int ks = 0; ks < 4; ks++) {
            const int k0 = ks * 16;
            unsigned ahi[2][4], alo[2][4];
#pragma unroll
            for (int mi = 0; mi < 2; mi++) {
                unsigned off = SWZ((unsigned)((wm0 + mi * 16 + lrow) * 128 + (k0 + lk) * 2));
                ldsm4(ahi[mi], abase + off);
                ldsm4(alo[mi], abase + 16384 + off);
            }
#pragma unroll
            for (int h = 0; h < 2; h++) {
                unsigned bhi2[2][4], blo2[2][4];
#pragma unroll
                for (int nb = 0; nb < 2; nb++) {
                    unsigned off = SWZ((unsigned)((wn0 + (h * 2 + nb) * 16 + lrow) * 128 + (k0 + lk) * 2));
                    ldsm4(bhi2[nb], bbase + off);
                    ldsm4(blo2[nb], bbase + 32768 + off);
                }
#pragma unroll
                for (int mi = 0; mi < 2; mi++)
#pragma unroll
                    for (int f = 0; f < 4; f++) {
                        int nb = f >> 1, r0 = f & 1;
                        float* d = acc[mi][h * 4 + f];
                        mma16816(d, ahi[mi], bhi2[nb][r0], bhi2[nb][r0 + 2]);
                        mma16816(d, ahi[mi], blo2[nb][r0], blo2[nb][r0 + 2]);
                        mma16816(d, alo[mi], bhi2[nb][r0], bhi2[nb][r0 + 2]);
                    }
            }
        }
        __syncthreads();
    }

    const float* sbias = (const float*)(smem + PBASE);
    const int tr = lane >> 2;
    const int tc2 = (lane & 3) * 2;
#pragma unroll
    for (int mi = 0; mi < 2; mi++)
#pragma unroll
        for (int ni = 0; ni < 8; ni++) {
            int cg = wn0 + ni * 8 + tc2;
            int ra = bm0 + wm0 + mi * 16 + tr;
            int rb = ra + 8;
            float* d = acc[mi][ni];
            float v0 = d[0] + sbias[cg], v1 = d[1] + sbias[cg + 1];
            float v2 = d[2] + sbias[cg], v3 = d[3] + sbias[cg + 1];
            if (ra < M) *(float2*)(Of32 + (size_t)ra * 256 + cg) = make_float2(v0, v1);
            if (rb < M) *(float2*)(Of32 + (size_t)rb * 256 + cg) = make_float2(v2, v3);
        }
}

// ---------------- head ----------------
__global__ void head_kernel(const float* __restrict__ h, const float* __restrict__ W2,
                            const float* __restrict__ b2, float* __restrict__ out) {
    __shared__ float sW[256 * NCLS];
    __shared__ float sb[NCLS];
    int tid = threadIdx.x;
    for (int i = tid; i < 256 * NCLS; i += 256) sW[i] = W2[i];
    if (tid < NCLS) sb[tid] = b2[tid];
    __syncthreads();

    int wid = tid >> 5, lane = tid & 31;
    int r = blockIdx.x * 8 + wid;
    if (r >= NN) return;

    const float4* rp = (const float4*)(h + (size_t)r * DD);
    float4 q0 = rp[lane * 2];
    float4 q1 = rp[lane * 2 + 1];
    float hreg[8] = {q0.x, q0.y, q0.z, q0.w, q1.x, q1.y, q1.z, q1.w};

    int c0 = lane;
    int c1 = lane + 32;
    int c1m = (c1 < NCLS) ? c1 : (NCLS - 1);
    float acc0 = sb[c0];
    float acc1 = sb[c1m];
#pragma unroll
    for (int e = 0; e < 8; e++) {
        for (int l = 0; l < 32; l++) {
            float hv = __shfl_sync(0xffffffffu, hreg[e], l);
            int k = l * 8 + e;
            acc0 = fmaf(hv, sW[k * NCLS + c0], acc0);
            acc1 = fmaf(hv, sW[k * NCLS + c1m], acc1);
        }
    }
    float m = fmaxf(acc0, (c1 < NCLS) ? acc1 : -3.4e38f);
#pragma unroll
    for (int o = 16; o > 0; o >>= 1) m = fmaxf(m, __shfl_xor_sync(0xffffffffu, m, o));
    float es = expf(acc0 - m) + ((c1 < NCLS) ? expf(acc1 - m) : 0.f);
#pragma unroll
    for (int o = 16; o > 0; o >>= 1) es += __shfl_xor_sync(0xffffffffu, es, o);
    float lse = m + logf(es);
    out[(size_t)r * NCLS + c0] = acc0 - lse;
    if (c1 < NCLS) out[(size_t)r * NCLS + c1] = acc1 - lse;
}

// ---------------- host orchestration ----------------
extern "C" void kernel_launch(void* const* d_in, const int* in_sizes, int n_in,
                              void* d_out, int out_size) {
    const float* x_in      = (const float*)d_in[0];
    const int* ei          = (const int*)d_in[1];
    const float* lin_l_W   = (const float*)d_in[2];
    const float* lin_l_b   = (const float*)d_in[3];
    const float* lin_r_W   = (const float*)d_in[4];
    const float* lin_r_b   = (const float*)d_in[5];
    const float* mlp_W1    = (const float*)d_in[6];
    const float* mlp_b1    = (const float*)d_in[7];
    const float* blk_Wa    = (const float*)d_in[8];
    const float* blk_ba    = (const float*)d_in[9];
    const float* blk_gamma = (const float*)d_in[10];
    const float* blk_beta  = (const float*)d_in[11];
    const float* blk_Wb    = (const float*)d_in[12];
    const float* blk_bb    = (const float*)d_in[13];
    const float* mlp_W2    = (const float*)d_in[14];
    const float* mlp_b2    = (const float*)d_in[15];
    const float* post_W1   = (const float*)d_in[16];
    const float* post_b1   = (const float*)d_in[17];
    const float* post_W2   = (const float*)d_in[18];
    const float* post_b2   = (const float*)d_in[19];
    float* out = (float*)d_out;

    float* pp;
    uint4 *whi, *wlo;
    unsigned *xih, *xil, *zih, *hih, *hil;
    int *cnti, *offp, *curp, *csrp;
    cudaGetSymbolAddress((void**)&pp, g_p);
    cudaGetSymbolAddress((void**)&whi, g_whi4);
    cudaGetSymbolAddress((void**)&wlo, g_wlo4);
    cudaGetSymbolAddress((void**)&xih, g_ximg_hi);
    cudaGetSymbolAddress((void**)&xil, g_ximg_lo);
    cudaGetSymbolAddress((void**)&zih, g_zimg_hi);
    cudaGetSymbolAddress((void**)&hih, g_himg_hi);
    cudaGetSymbolAddress((void**)&hil, g_himg_lo);
    cudaGetSymbolAddress((void**)&cnti, g_cnti);
    cudaGetSymbolAddress((void**)&offp, g_off);
    cudaGetSymbolAddress((void**)&curp, g_cur);
    cudaGetSymbolAddress((void**)&csrp, g_csr);

    cudaFuncSetAttribute(fused_layer, cudaFuncAttributeMaxDynamicSharedMemorySize, FSMEM);
    cudaFuncSetAttribute(mma_gemm, cudaFuncAttributeMaxDynamicSharedMemorySize, SMEM_SZ);

    const float bnscale = rsqrtf(1.0f + 1e-5f);
    const int* src = ei;
    const int* dst = ei + EE;

    // 1: setup (weights + x image)
    setup_kernel<<<31400, 256>>>(lin_l_W, lin_r_W, mlp_W1, blk_Wa, blk_Wb, mlp_W2, post_W1,
                                 x_in, (unsigned short*)whi, (unsigned short*)wlo, xih, xil);
    // 2: CSR (count+scan+fill, one persistent kernel)
    csr_kernel<<<CSRB, 256>>>(src, dst, cnti, offp, curp, csrp);

    for (int i = 0; i < NLAYER; i++) {
        // 3: gather (hi only)
        gather_img<<<(NN + 1) / 2, 256>>>(xih, offp, csrp, zih);

        SlotTab tab;
        int s = 0;
        auto push1 = [&](int base, int n) {
            for (int c = 0; c < n; c++) tab.p[s++] = whi + (size_t)(base + c) * 2048;
        };
        push1(i * 8, 4);                 // cat-x (lin_l)           slots 0-3
        push1(i * 8 + 4, 4);             // cat-z (lin_r)           slots 4-7
        push1(24 + i * 4, 4);            // w1                      slots 8-11
        push1(36 + (2 * i) * 4, 4);      // wa0                     slots 12-15
        push1(60 + (2 * i) * 4, 4);      // wb0                     slots 16-19
        push1(36 + (2 * i + 1) * 4, 4);  // wa1                     slots 20-23
        push1(60 + (2 * i + 1) * 4, 4);  // wb1                     slots 24-27
        push1(84 + i * 4, 4);            // w2                      slots 28-31

        size_t bo0 = ((size_t)i * 2) * 256, bo1 = ((size_t)i * 2 + 1) * 256;
        // 4: fused layer  <-- profiled launch
        fused_layer<<<NB, 512, FSMEM>>>(
            xih, xil, zih, tab,
            lin_l_b + (size_t)i * 256, lin_r_b + (size_t)i * 256,
            mlp_b1 + (size_t)i * 256,
            blk_ba + bo0, blk_gamma + bo0, blk_beta + bo0, blk_bb + bo0,
            blk_ba + bo1, blk_gamma + bo1, blk_beta + bo1, blk_bb + bo1,
            mlp_b2 + (size_t)i * 256, bnscale,
            hih, hil);
    }

    mma_gemm<<<NB, 512, SMEM_SZ>>>(xih, xil, whi + (size_t)96 * 2048,
                                   wlo + (size_t)96 * 2048, post_b1, pp, NN);
    head_kernel<<<(NN + 7) / 8, 256>>>(pp, post_W2, post_b2, out);
}

// round 11
// speedup vs baseline: 4.1837x; 1.0875x over previous
#include <cuda_runtime.h>
#include <cuda_bf16.h>
#include <math.h>

#define NN 50000
#define ROWSP 50048
#define DD 256
#define EE 800000
#define NCLS 47
#define NLAYER 3
#define NB 391
#define CSRB 148

#define SWZ(x) ((x) ^ (((x) >> 3) & 0x70))

// ---- standalone (post) gemm smem layout ----
#define ABUF 32768
#define BBASE 65536
#define BBUF 65536
#define PBASE 196608
#define SMEM_SZ 201728

// ---- fused kernel smem layout ----
// A image: 4 chunks x 16KB (hi only) @ 0..65536
// B ring:  4 slots x 32KB @ 65536..196608
// rsum:    2KB @ 196608
#define FS_B 65536
#define RSUM_OFF 196608
#define FSMEM 198656

// ---------------- device scratch ----------------
__device__ float g_p[ROWSP * DD];
__device__ uint4 g_whi4[100 * 2048];
__device__ uint4 g_wlo4[100 * 2048];
__device__ unsigned g_ximg_hi[4 * ROWSP * 32];
__device__ unsigned g_ximg_lo[4 * ROWSP * 32];
__device__ unsigned g_zimg_hi[4 * ROWSP * 32];
__device__ unsigned g_himg_hi[4 * ROWSP * 32];
__device__ unsigned g_himg_lo[4 * ROWSP * 32];
__device__ int g_cnti[NN];          // static zero-init; self-zeroed each run
__device__ int g_off[NN + 1];
__device__ int g_cur[NN];
__device__ int g_csr[EE];
__device__ int g_partial[CSRB];
__device__ int g_pscan[CSRB];
__device__ unsigned g_bar;

struct SlotTab { const uint4* p[32]; };

static __device__ __forceinline__ unsigned smem_u32(const void* p) {
    unsigned a;
    asm("{ .reg .u64 t; cvta.to.shared.u64 t, %1; cvt.u32.u64 %0, t; }" : "=r"(a) : "l"(p));
    return a;
}
static __device__ __forceinline__ void ldsm4(unsigned r[4], unsigned addr) {
    asm volatile("ldmatrix.sync.aligned.m8n8.x4.shared.b16 {%0,%1,%2,%3}, [%4];"
                 : "=r"(r[0]), "=r"(r[1]), "=r"(r[2]), "=r"(r[3]) : "r"(addr));
}
static __device__ __forceinline__ void mma16816(float d[4], const unsigned a[4],
                                                unsigned b0, unsigned b1) {
    asm volatile(
        "mma.sync.aligned.m16n8k16.row.col.f32.bf16.bf16.f32 "
        "{%0,%1,%2,%3}, {%4,%5,%6,%7}, {%8,%9}, {%0,%1,%2,%3};"
        : "+f"(d[0]), "+f"(d[1]), "+f"(d[2]), "+f"(d[3])
        : "r"(a[0]), "r"(a[1]), "r"(a[2]), "r"(a[3]), "r"(b0), "r"(b1));
}
#define CPA(dst, src) \
    asm volatile("cp.async.cg.shared.global [%0], [%1], 16;" :: "r"(dst), "l"(src) : "memory")
#define CP_COMMIT() asm volatile("cp.async.commit_group;" ::: "memory")
template <int N>
static __device__ __forceinline__ void cp_wait() {
    asm volatile("cp.async.wait_group %0;" :: "n"(N) : "memory");
}

static __device__ __forceinline__ void bsplit(float v, unsigned& h, unsigned& l) {
    __nv_bfloat16 hb = __float2bfloat16(v);
    h = __bfloat16_as_ushort(hb);
    l = __bfloat16_as_ushort(__float2bfloat16(v - __bfloat162float(hb)));
}
static __device__ __forceinline__ unsigned bhi(float v) {
    return (unsigned)__bfloat16_as_ushort(__float2bfloat16(v));
}
static __device__ __forceinline__ unsigned img_idx(int chunk, int row, int lc) {
    return ((unsigned)chunk * ROWSP + (unsigned)row) * 32u +
           ((((unsigned)(lc * 2)) ^ (((unsigned)row & 7u) << 4)) >> 2);
}
static __device__ __forceinline__ void img_write(unsigned* __restrict__ hi,
                                                 unsigned* __restrict__ lo, int chunk,
                                                 int row, int lc, float v0, float v1) {
    unsigned h0, l0, h1, l1;
    bsplit(v0, h0, l0);
    bsplit(v1, h1, l1);
    unsigned idx = img_idx(chunk, row, lc);
    hi[idx] = h0 | (h1 << 16);
    lo[idx] = l0 | (l1 << 16);
}
static __device__ __forceinline__ void img_write_hi(unsigned* __restrict__ hi, int chunk,
                                                    int row, int lc, float v0, float v1) {
    hi[img_idx(chunk, row, lc)] = bhi(v0) | (bhi(v1) << 16);
}
static __device__ __forceinline__ float2 img_read(const unsigned* __restrict__ hi,
                                                  const unsigned* __restrict__ lo, int chunk,
                                                  int row, int lc) {
    unsigned idx = img_idx(chunk, row, lc);
    unsigned h = hi[idx], l = lo[idx];
    float x0 = __bfloat162float(__ushort_as_bfloat16((unsigned short)(h & 0xffff))) +
               __bfloat162float(__ushort_as_bfloat16((unsigned short)(l & 0xffff)));
    float x1 = __bfloat162float(__ushort_as_bfloat16((unsigned short)(h >> 16))) +
               __bfloat162float(__ushort_as_bfloat16((unsigned short)(l >> 16)));
    return make_float2(x0, x1);
}
static __device__ __forceinline__ float2 img_read_hi(const unsigned* __restrict__ hi,
                                                     int chunk, int row, int lc) {
    unsigned h = hi[img_idx(chunk, row, lc)];
    return make_float2(
        __bfloat162float(__ushort_as_bfloat16((unsigned short)(h & 0xffff))),
        __bfloat162float(__ushort_as_bfloat16((unsigned short)(h >> 16))));
}

// ---------------- setup: weight prep + x image (ONE launch) ----------------
__global__ void setup_kernel(const float* __restrict__ linl, const float* __restrict__ linr,
                             const float* __restrict__ w1, const float* __restrict__ wa,
                             const float* __restrict__ wb, const float* __restrict__ w2,
                             const float* __restrict__ post, const float* __restrict__ X,
                             unsigned short* __restrict__ dhi, unsigned short* __restrict__ dlo,
                             unsigned* __restrict__ xih, unsigned* __restrict__ xil) {
    int b = blockIdx.x;
    if (b < 6400) {
        int idx = b * 256 + threadIdx.x;
        int m = idx >> 16;
        int rem = idx & 65535;
        int n = rem & 255, k = rem >> 8;
        const float* W;
        int chunk;
        if (m < 3)       { W = linl + (size_t)m * 65536;       chunk = 0  + m * 8 + (k >> 6); }
        else if (m < 6)  { W = linr + (size_t)(m - 3) * 65536; chunk = 4  + (m - 3) * 8 + (k >> 6); }
        else if (m < 9)  { W = w1 + (size_t)(m - 6) * 65536;   chunk = 24 + (m - 6) * 4 + (k >> 6); }
        else if (m < 15) { W = wa + (size_t)(m - 9) * 65536;   chunk = 36 + (m - 9) * 4 + (k >> 6); }
        else if (m < 21) { W = wb + (size_t)(m - 15) * 65536;  chunk = 60 + (m - 15) * 4 + (k >> 6); }
        else if (m < 24) { W = w2 + (size_t)(m - 21) * 65536;  chunk = 84 + (m - 21) * 4 + (k >> 6); }
        else             { W = post;                           chunk = 96 + (k >> 6); }
        float v = W[(size_t)k * 256 + n];
        unsigned h, l;
        bsplit(v, h, l);
        unsigned off = (unsigned)chunk * 32768u + SWZ((unsigned)(n * 128 + (k & 63) * 2));
        dhi[off >> 1] = (unsigned short)h;
        dlo[off >> 1] = (unsigned short)l;
    } else {
        int idx = (b - 6400) * 256 + threadIdx.x;   // < NN*128 exactly
        int row = idx >> 7, p = idx & 127;
        float v0 = X[(size_t)row * 256 + p * 2];
        float v1 = X[(size_t)row * 256 + p * 2 + 1];
        img_write(xih, xil, (p * 2) >> 6, row, (p * 2) & 63, v0, v1);
    }
}

// ---------------- single-kernel CSR build (persistent grid + sw barrier) ----------------
static __device__ __forceinline__ void gridbar() {
    __syncthreads();
    __threadfence();
    if (threadIdx.x == 0) {
        unsigned arr = atomicAdd(&g_bar, 1u);
        unsigned target = (arr / CSRB + 1u) * CSRB;
        while (*(volatile unsigned*)&g_bar < target) { }
    }
    __syncthreads();
}

__global__ void csr_kernel(const int* __restrict__ src, const int* __restrict__ dst,
                           int* __restrict__ cnt, int* __restrict__ off,
                           int* __restrict__ cur, int* __restrict__ csr) {
    __shared__ int sdata[256];
    const int b = blockIdx.x, t = threadIdx.x;
    for (int e = b * 256 + t; e < EE; e += CSRB * 256)
        atomicAdd(&cnt[dst[e]], 1);
    gridbar();
    int n0 = (b * 256 + t) * 2;
    int c0 = (n0 < NN) ? cnt[n0] : 0;
    int c1 = (n0 + 1 < NN) ? cnt[n0 + 1] : 0;
    if (n0 < NN) cnt[n0] = 0;
    if (n0 + 1 < NN) cnt[n0 + 1] = 0;
    int ts = c0 + c1;
    sdata[t] = ts;
    __syncthreads();
#pragma unroll
    for (int o = 1; o < 256; o <<= 1) {
        int v = (t >= o) ? sdata[t - o] : 0;
        __syncthreads();
        sdata[t] += v;
        __syncthreads();
    }
    int bexcl = sdata[t] - ts;
    if (t == 255) g_partial[b] = sdata[t];
    gridbar();
    if (b == 0) {
        int v = (t < CSRB) ? g_partial[t] : 0;
        sdata[t] = v;
        __syncthreads();
#pragma unroll
        for (int o = 1; o < 256; o <<= 1) {
            int w = (t >= o) ? sdata[t - o] : 0;
            __syncthreads();
            sdata[t] += w;
            __syncthreads();
        }
        if (t < CSRB) g_pscan[t] = sdata[t] - v;
        if (t == 0) off[0] = 0;
    }
    gridbar();
    int base = g_pscan[b] + bexcl;
    if (n0 < NN) {
        cur[n0] = base;
        off[n0 + 1] = base + c0;
        if (n0 + 1 < NN) {
            cur[n0 + 1] = base + c0;
            if (n0 + 2 <= NN) off[n0 + 2] = base + c0 + c1;
        }
    }
    gridbar();
    for (int e = b * 256 + t; e < EE; e += CSRB * 256) {
        int p = atomicAdd(&cur[dst[e]], 1);
        csr[p] = src[e];
    }
}

// ---------------- gather (hi-only, unroll-4) ----------------
__global__ void gather_img(const unsigned* __restrict__ xih,
                           const int* __restrict__ off, const int* __restrict__ csr,
                           unsigned* __restrict__ zih) {
    int w = (blockIdx.x * 256 + threadIdx.x) >> 5;
    int d = w >> 2, c = w & 3;
    if (d >= NN) return;
    int lane = threadIdx.x & 31;
    int lc = lane * 2;
    int b = off[d], e = off[d + 1];
    float s0 = 0.f, s1 = 0.f;
    int j = b;
    for (; j + 3 < e; j += 4) {
        float2 v0 = img_read_hi(xih, c, csr[j], lc);
        float2 v1 = img_read_hi(xih, c, csr[j + 1], lc);
        float2 v2 = img_read_hi(xih, c, csr[j + 2], lc);
        float2 v3 = img_read_hi(xih, c, csr[j + 3], lc);
        s0 += (v0.x + v1.x) + (v2.x + v3.x);
        s1 += (v0.y + v1.y) + (v2.y + v3.y);
    }
    for (; j < e; j++) {
        float2 v = img_read_hi(xih, c, csr[j], lc);
        s0 += v.x;
        s1 += v.y;
    }
    float iv = 1.f / fmaxf((float)(e - b), 1.f);
    img_write_hi(zih, c, d, lc, s0 * iv, s1 * iv);
}

// ---- fused-layer MMA micro-kernel (hi-only A) ----
static __device__ __forceinline__ void mma_slot(unsigned abase, unsigned bbase,
                                                float (&acc)[2][8][4], int wm0, int wn0,
                                                int lane) {
    const int lrow = lane & 15;
    const int lk = (lane >> 4) * 8;
#pragma unroll
    for (int ks = 0; ks < 4; ks++) {
        const int k0 = ks * 16;
        unsigned ahi[2][4];
#pragma unroll
        for (int mi = 0; mi < 2; mi++) {
            unsigned off = SWZ((unsigned)((wm0 + mi * 16 + lrow) * 128 + (k0 + lk) * 2));
            ldsm4(ahi[mi], abase + off);
        }
#pragma unroll
        for (int h = 0; h < 2; h++) {
            unsigned bb[2][4];
#pragma unroll
            for (int nb = 0; nb < 2; nb++) {
                unsigned off = SWZ((unsigned)((wn0 + (h * 2 + nb) * 16 + lrow) * 128 + (k0 + lk) * 2));
                ldsm4(bb[nb], bbase + off);
            }
#pragma unroll
            for (int mi = 0; mi < 2; mi++)
#pragma unroll
                for (int f = 0; f < 4; f++) {
                    int nb = f >> 1, r0 = f & 1;
                    mma16816(acc[mi][h * 4 + f], ahi[mi], bb[nb][r0], bb[nb][r0 + 2]);
                }
        }
    }
}

// ---------------- fused layer kernel ----------------
// 32 B-slots all 1-term; B ring of 4; ONE barrier per slot.
// Slot map: cat-x 0-3, cat-z 4-7, w1 8-11, wa0 12-15, wb0 16-19, wa1 20-23, wb1 24-27, w2 28-31
__global__ void __launch_bounds__(512, 1)
fused_layer(unsigned* __restrict__ ximg_hi, unsigned* __restrict__ ximg_lo,
            const unsigned* __restrict__ zimg_hi, SlotTab tab,
            const float* __restrict__ bl, const float* __restrict__ br,
            const float* __restrict__ b1,
            const float* __restrict__ ba0, const float* __restrict__ g0,
            const float* __restrict__ be0, const float* __restrict__ bb0,
            const float* __restrict__ ba1, const float* __restrict__ g1,
            const float* __restrict__ be1, const float* __restrict__ bb1,
            const float* __restrict__ b2, float bnscale,
            unsigned* __restrict__ himg_hi, unsigned* __restrict__ himg_lo) {
    extern __shared__ char smem[];
    const unsigned sb = smem_u32(smem);
    const int tid = threadIdx.x, wid = tid >> 5, lane = tid & 31;
    const int bm0 = blockIdx.x * 128;
    const int wm0 = (wid >> 2) * 32;
    const int wn0 = (wid & 3) * 64;
    const int tr = lane >> 2;
    const int tc2 = (lane & 3) * 2;

    float acc[2][8][4];
    auto zero_acc = [&]() {
#pragma unroll
        for (int a = 0; a < 2; a++)
#pragma unroll
            for (int b = 0; b < 8; b++)
#pragma unroll
                for (int c = 0; c < 4; c++) acc[a][b][c] = 0.f;
    };
    zero_acc();

    auto issue_B = [&](int s) {   // no commit
        if (s >= 32) return;
        const char* src = (const char*)tab.p[s];
        unsigned dstb = sb + FS_B + (unsigned)(s & 3) * 32768u;
#pragma unroll
        for (int i = 0; i < 4; i++) {
            int u = tid + i * 512;
            CPA(dstb + u * 16, src + u * 16);
        }
    };
    auto issue_z = [&](int c) {   // 16KB hi-only into A chunk c
        const char* gh = (const char*)(zimg_hi + ((size_t)c * ROWSP + bm0) * 32);
        unsigned cb = sb + (unsigned)c * 16384u;
#pragma unroll
        for (int i = 0; i < 2; i++) {
            int u = tid + i * 512;
            CPA(cb + u * 16, gh + u * 16);
        }
    };
    // one barrier per slot; issue before consume (ring slot (s+3)&3 == (s-1)&3, drained)
    auto slot = [&](int s, int achunk, int zc) {
        cp_wait<2>();
        __syncthreads();
        issue_B(s + 3);
        if (zc >= 0) issue_z(zc);
        CP_COMMIT();
        mma_slot(sb + (unsigned)achunk * 16384u, sb + FS_B + (unsigned)(s & 3) * 32768u,
                 acc, wm0, wn0, lane);
    };
    auto run1 = [&](int s0) {
#pragma unroll 1
        for (int c = 0; c < 4; c++) slot(s0 + c, c, -1);
    };
    auto conv_img = [&]() {   // acc -> smem A image (hi only); caller syncs BEFORE
        unsigned cb = (unsigned)(wn0 >> 6) * 16384u;
#pragma unroll
        for (int mi = 0; mi < 2; mi++)
#pragma unroll
            for (int ni = 0; ni < 8; ni++) {
                int lc = ni * 8 + tc2;
                float* d = acc[mi][ni];
                unsigned off = SWZ((unsigned)((wm0 + mi * 16 + tr) * 128 + lc * 2));
                *(unsigned*)(smem + cb + off) = bhi(d[0]) | (bhi(d[1]) << 16);
                off = SWZ((unsigned)((wm0 + mi * 16 + 8 + tr) * 128 + lc * 2));
                *(unsigned*)(smem + cb + off) = bhi(d[2]) | (bhi(d[3]) << 16);
            }
    };

    // ---- prologue: x image (hi only, 4x16KB) + first 3 B slots ----
#pragma unroll
    for (int c = 0; c < 4; c++) {
        const char* gh = (const char*)(ximg_hi + ((size_t)c * ROWSP + bm0) * 32);
        unsigned cb = sb + (unsigned)c * 16384u;
#pragma unroll
        for (int i = 0; i < 2; i++) {
            int u = tid + i * 512;
            CPA(cb + u * 16, gh + u * 16);
        }
    }
    CP_COMMIT();
    issue_B(0); CP_COMMIT();
    issue_B(1); CP_COMMIT();
    issue_B(2); CP_COMMIT();

    // ---- cat super-stage: slots 0-7; z chunk s-1 prefetched at slots 1..4 ----
#pragma unroll 1
    for (int s = 0; s < 8; s++)
        slot(s, s & 3, (s >= 1 && s <= 4) ? (s - 1) : -1);
    __syncthreads();
#pragma unroll
    for (int mi = 0; mi < 2; mi++)
#pragma unroll
        for (int ni = 0; ni < 8; ni++) {
            int cg = wn0 + ni * 8 + tc2;
            float* d = acc[mi][ni];
            float a0 = bl[cg] + br[cg], a1 = bl[cg + 1] + br[cg + 1];
            d[0] += a0; d[1] += a1; d[2] += a0; d[3] += a1;
        }
    conv_img(); zero_acc();

    // ---- w1: slots 8-11 -> h0 (write himg) ----
    run1(8);
    __syncthreads();
#pragma unroll
    for (int mi = 0; mi < 2; mi++)
#pragma unroll
        for (int ni = 0; ni < 8; ni++) {
            int cg = wn0 + ni * 8 + tc2;
            float* d = acc[mi][ni];
            d[0] += b1[cg]; d[1] += b1[cg + 1]; d[2] += b1[cg]; d[3] += b1[cg + 1];
            int ra = bm0 + wm0 + mi * 16 + tr;
            img_write(himg_hi, himg_lo, cg >> 6, ra, cg & 63, d[0], d[1]);
            img_write(himg_hi, himg_lo, cg >> 6, ra + 8, cg & 63, d[2], d[3]);
        }
    conv_img(); zero_acc();

    // ---- blocks: wa j: 12+8j, wb j: 16+8j ----
#pragma unroll 1
    for (int j = 0; j < 2; j++) {
        const float* ba = j ? ba1 : ba0;
        const float* gg = j ? g1 : g0;
        const float* be = j ? be1 : be0;
        const float* bb = j ? bb1 : bb0;
        run1(12 + j * 8);
        __syncthreads();
#pragma unroll
        for (int mi = 0; mi < 2; mi++)
#pragma unroll
            for (int ni = 0; ni < 8; ni++) {
                int cg = wn0 + ni * 8 + tc2;
                float* d = acc[mi][ni];
                float ga = gg[cg], gb = gg[cg + 1], ea = be[cg], eb = be[cg + 1];
                float a0 = ba[cg], a1 = ba[cg + 1];
                d[0] = fmaf(ga, fmaxf(d[0] + a0, 0.f) * bnscale, ea);
                d[1] = fmaf(gb, fmaxf(d[1] + a1, 0.f) * bnscale, eb);
                d[2] = fmaf(ga, fmaxf(d[2] + a0, 0.f) * bnscale, ea);
                d[3] = fmaf(gb, fmaxf(d[3] + a1, 0.f) * bnscale, eb);
            }
        conv_img(); zero_acc();
        run1(16 + j * 8);
        __syncthreads();
#pragma unroll
        for (int mi = 0; mi < 2; mi++)
#pragma unroll
            for (int ni = 0; ni < 8; ni++) {
                int cg = wn0 + ni * 8 + tc2;
                float* d = acc[mi][ni];
                int ra = bm0 + wm0 + mi * 16 + tr;
                float2 ha = img_read(himg_hi, himg_lo, cg >> 6, ra, cg & 63);
                float2 hb = img_read(himg_hi, himg_lo, cg >> 6, ra + 8, cg & 63);
                d[0] += bb[cg] + ha.x; d[1] += bb[cg + 1] + ha.y;
                d[2] += bb[cg] + hb.x; d[3] += bb[cg + 1] + hb.y;
                if (j == 0) {
                    img_write(himg_hi, himg_lo, cg >> 6, ra, cg & 63, d[0], d[1]);
                    img_write(himg_hi, himg_lo, cg >> 6, ra + 8, cg & 63, d[2], d[3]);
                }
            }
        conv_img(); zero_acc();
    }

    // ---- w2: slots 28-31, normalize + relu -> ximg ----
    run1(28);
    __syncthreads();
#pragma unroll
    for (int mi = 0; mi < 2; mi++)
#pragma unroll
        for (int ni = 0; ni < 8; ni++) {
            int cg = wn0 + ni * 8 + tc2;
            float* d = acc[mi][ni];
            d[0] += b2[cg]; d[1] += b2[cg + 1]; d[2] += b2[cg]; d[3] += b2[cg + 1];
        }
    {
        float* rsum = (float*)(smem + RSUM_OFF);
        float ps[2][2] = {{0.f, 0.f}, {0.f, 0.f}};
#pragma unroll
        for (int mi = 0; mi < 2; mi++)
#pragma unroll
            for (int ni = 0; ni < 8; ni++) {
                float* d = acc[mi][ni];
                ps[mi][0] = fmaf(d[0], d[0], fmaf(d[1], d[1], ps[mi][0]));
                ps[mi][1] = fmaf(d[2], d[2], fmaf(d[3], d[3], ps[mi][1]));
            }
#pragma unroll
        for (int mi = 0; mi < 2; mi++)
#pragma unroll
            for (int q = 0; q < 2; q++) {
                ps[mi][q] += __shfl_xor_sync(0xffffffffu, ps[mi][q], 1);
                ps[mi][q] += __shfl_xor_sync(0xffffffffu, ps[mi][q], 2);
            }
        if ((lane & 3) == 0) {
            int cw = wn0 >> 6;
#pragma unroll
            for (int mi = 0; mi < 2; mi++) {
                rsum[(wm0 + mi * 16 + tr) * 4 + cw] = ps[mi][0];
                rsum[(wm0 + mi * 16 + 8 + tr) * 4 + cw] = ps[mi][1];
            }
        }
        __syncthreads();
#pragma unroll
        for (int mi = 0; mi < 2; mi++) {
            int r0 = wm0 + mi * 16 + tr;
            int r1 = r0 + 8;
            float s0 = rsum[r0 * 4] + rsum[r0 * 4 + 1] + rsum[r0 * 4 + 2] + rsum[r0 * 4 + 3];
            float s1 = rsum[r1 * 4] + rsum[r1 * 4 + 1] + rsum[r1 * 4 + 2] + rsum[r1 * 4 + 3];
            float c0 = 1.f / fmaxf(sqrtf(s0), 1e-12f);
            float c1 = 1.f / fmaxf(sqrtf(s1), 1e-12f);
#pragma unroll
            for (int ni = 0; ni < 8; ni++) {
                float* d = acc[mi][ni];
                d[0] = fmaxf(d[0] * c0, 0.f); d[1] = fmaxf(d[1] * c0, 0.f);
                d[2] = fmaxf(d[2] * c1, 0.f); d[3] = fmaxf(d[3] * c1, 0.f);
            }
        }
    }
#pragma unroll
    for (int mi = 0; mi < 2; mi++)
#pragma unroll
        for (int ni = 0; ni < 8; ni++) {
            int cg = wn0 + ni * 8 + tc2;
            int ra = bm0 + wm0 + mi * 16 + tr;
            float* d = acc[mi][ni];
            img_write(ximg_hi, ximg_lo, cg >> 6, ra, cg & 63, d[0], d[1]);
            img_write(ximg_hi, ximg_lo, cg >> 6, ra + 8, cg & 63, d[2], d[3]);
        }
}

// ---------------- standalone GEMM (post layer, 3-term) ----------------
__global__ void __launch_bounds__(512, 1)
mma_gemm(const unsigned* __restrict__ Aimg_hi, const unsigned* __restrict__ Aimg_lo,
         const uint4* __restrict__ Whi, const uint4* __restrict__ Wlo,
         const float* __restrict__ bias, float* __restrict__ Of32, int M) {
    extern __shared__ char smem[];
    const unsigned sb = smem_u32(smem);
    const int tid = threadIdx.x, wid = tid >> 5, lane = tid & 31;
    const int bm0 = blockIdx.x * 128;

    if (tid < 256) ((float*)(smem + PBASE))[tid] = bias[tid];

    const int wm0 = (wid >> 2) * 32;
    const int wn0 = (wid & 3) * 64;
    const int lrow = lane & 15;
    const int lk = (lane >> 4) * 8;

    float acc[2][8][4];
#pragma unroll
    for (int a = 0; a < 2; a++)
#pragma unroll
        for (int b = 0; b < 8; b++)
#pragma unroll
            for (int c = 0; c < 4; c++) acc[a][b][c] = 0.f;

    auto issue = [&](int c, int st) {
        unsigned ab = sb + st * ABUF;
        unsigned bb = sb + BBASE + st * BBUF;
        const char* wh = (const char*)(Whi + (size_t)c * 2048);
        const char* wl = (const char*)(Wlo + (size_t)c * 2048);
#pragma unroll
        for (int i = 0; i < 4; i++) {
            int u = tid + i * 512;
            CPA(bb + u * 16, wh + u * 16);
            CPA(bb + 32768 + u * 16, wl + u * 16);
        }
        const char* ih = (const char*)(Aimg_hi + ((size_t)c * ROWSP + bm0) * 32);
        const char* il = (const char*)(Aimg_lo + ((size_t)c * ROWSP + bm0) * 32);
#pragma unroll
        for (int i = 0; i < 2; i++) {
            int u = tid + i * 512;
            CPA(ab + u * 16, ih + u * 16);
            CPA(ab + 16384 + u * 16, il + u * 16);
        }
    };

    issue(0, 0);
    CP_COMMIT();
    for (int c = 0; c < 4; c++) {
        int st = c & 1;
        if (c + 1 < 4) { issue(c + 1, st ^ 1); CP_COMMIT(); cp_wait<1>(); }
        else cp_wait<0>();
        __syncthreads();
        unsigned abase = sb + st * ABUF;
        unsigned bbase = sb + BBASE + st * BBUF;
#pragma unroll
        for (int ks = 0; ks < 4; ks++) {
            const int k0 = ks * 16;
            unsigned ahi[2][4], alo[2][4];
#pragma unroll
            for (int mi = 0; mi < 2; mi++) {
                unsigned off = SWZ((unsigned)((wm0 + mi * 16 + lrow) * 128 + (k0 + lk) * 2));
                ldsm4(ahi[mi], abase + off);
                ldsm4(alo[mi], abase + 16384 + off);
            }
#pragma unroll
            for (int h = 0; h < 2; h++) {
                unsigned bhi2[2][4], blo2[2][4];
#pragma unroll
                for (int nb = 0; nb < 2; nb++) {
                    unsigned off = SWZ((unsigned)((wn0 + (h * 2 + nb) * 16 + lrow) * 128 + (k0 + lk) * 2));
                    ldsm4(bhi2[nb], bbase + off);
                    ldsm4(blo2[nb], bbase + 32768 + off);
                }
#pragma unroll
                for (int mi = 0; mi < 2; mi++)
#pragma unroll
                    for (int f = 0; f < 4; f++) {
                        int nb = f >> 1, r0 = f & 1;
                        float* d = acc[mi][h * 4 + f];
                        mma16816(d, ahi[mi], bhi2[nb][r0], bhi2[nb][r0 + 2]);
                        mma16816(d, ahi[mi], blo2[nb][r0], blo2[nb][r0 + 2]);
                        mma16816(d, alo[mi], bhi2[nb][r0], bhi2[nb][r0 + 2]);
                    }
            }
        }
        __syncthreads();
    }

    const float* sbias = (const float*)(smem + PBASE);
    const int tr = lane >> 2;
    const int tc2 = (lane & 3) * 2;
#pragma unroll
    for (int mi = 0; mi < 2; mi++)
#pragma unroll
        for (int ni = 0; ni < 8; ni++) {
            int cg = wn0 + ni * 8 + tc2;
            int ra = bm0 + wm0 + mi * 16 + tr;
            int rb = ra + 8;
            float* d = acc[mi][ni];
            float v0 = d[0] + sbias[cg], v1 = d[1] + sbias[cg + 1];
            float v2 = d[2] + sbias[cg], v3 = d[3] + sbias[cg + 1];
            if (ra < M) *(float2*)(Of32 + (size_t)ra * 256 + cg) = make_float2(v0, v1);
            if (rb < M) *(float2*)(Of32 + (size_t)rb * 256 + cg) = make_float2(v2, v3);
        }
}

// ---------------- head ----------------
__global__ void head_kernel(const float* __restrict__ h, const float* __restrict__ W2,
                            const float* __restrict__ b2, float* __restrict__ out) {
    __shared__ float sW[256 * NCLS];
    __shared__ float sb[NCLS];
    int tid = threadIdx.x;
    for (int i = tid; i < 256 * NCLS; i += 256) sW[i] = W2[i];
    if (tid < NCLS) sb[tid] = b2[tid];
    __syncthreads();

    int wid = tid >> 5, lane = tid & 31;
    int r = blockIdx.x * 8 + wid;
    if (r >= NN) return;

    const float4* rp = (const float4*)(h + (size_t)r * DD);
    float4 q0 = rp[lane * 2];
    float4 q1 = rp[lane * 2 + 1];
    float hreg[8] = {q0.x, q0.y, q0.z, q0.w, q1.x, q1.y, q1.z, q1.w};

    int c0 = lane;
    int c1 = lane + 32;
    int c1m = (c1 < NCLS) ? c1 : (NCLS - 1);
    float acc0 = sb[c0];
    float acc1 = sb[c1m];
#pragma unroll
    for (int e = 0; e < 8; e++) {
        for (int l = 0; l < 32; l++) {
            float hv = __shfl_sync(0xffffffffu, hreg[e], l);
            int k = l * 8 + e;
            acc0 = fmaf(hv, sW[k * NCLS + c0], acc0);
            acc1 = fmaf(hv, sW[k * NCLS + c1m], acc1);
        }
    }
    float m = fmaxf(acc0, (c1 < NCLS) ? acc1 : -3.4e38f);
#pragma unroll
    for (int o = 16; o > 0; o >>= 1) m = fmaxf(m, __shfl_xor_sync(0xffffffffu, m, o));
    float es = expf(acc0 - m) + ((c1 < NCLS) ? expf(acc1 - m) : 0.f);
#pragma unroll
    for (int o = 16; o > 0; o >>= 1) es += __shfl_xor_sync(0xffffffffu, es, o);
    float lse = m + logf(es);
    out[(size_t)r * NCLS + c0] = acc0 - lse;
    if (c1 < NCLS) out[(size_t)r * NCLS + c1] = acc1 - lse;
}

// ---------------- host orchestration ----------------
extern "C" void kernel_launch(void* const* d_in, const int* in_sizes, int n_in,
                              void* d_out, int out_size) {
    const float* x_in      = (const float*)d_in[0];
    const int* ei          = (const int*)d_in[1];
    const float* lin_l_W   = (const float*)d_in[2];
    const float* lin_l_b   = (const float*)d_in[3];
    const float* lin_r_W   = (const float*)d_in[4];
    const float* lin_r_b   = (const float*)d_in[5];
    const float* mlp_W1    = (const float*)d_in[6];
    const float* mlp_b1    = (const float*)d_in[7];
    const float* blk_Wa    = (const float*)d_in[8];
    const float* blk_ba    = (const float*)d_in[9];
    const float* blk_gamma = (const float*)d_in[10];
    const float* blk_beta  = (const float*)d_in[11];
    const float* blk_Wb    = (const float*)d_in[12];
    const float* blk_bb    = (const float*)d_in[13];
    const float* mlp_W2    = (const float*)d_in[14];
    const float* mlp_b2    = (const float*)d_in[15];
    const float* post_W1   = (const float*)d_in[16];
    const float* post_b1   = (const float*)d_in[17];
    const float* post_W2   = (const float*)d_in[18];
    const float* post_b2   = (const float*)d_in[19];
    float* out = (float*)d_out;

    float* pp;
    uint4 *whi, *wlo;
    unsigned *xih, *xil, *zih, *hih, *hil;
    int *cnti, *offp, *curp, *csrp;
    cudaGetSymbolAddress((void**)&pp, g_p);
    cudaGetSymbolAddress((void**)&whi, g_whi4);
    cudaGetSymbolAddress((void**)&wlo, g_wlo4);
    cudaGetSymbolAddress((void**)&xih, g_ximg_hi);
    cudaGetSymbolAddress((void**)&xil, g_ximg_lo);
    cudaGetSymbolAddress((void**)&zih, g_zimg_hi);
    cudaGetSymbolAddress((void**)&hih, g_himg_hi);
    cudaGetSymbolAddress((void**)&hil, g_himg_lo);
    cudaGetSymbolAddress((void**)&cnti, g_cnti);
    cudaGetSymbolAddress((void**)&offp, g_off);
    cudaGetSymbolAddress((void**)&curp, g_cur);
    cudaGetSymbolAddress((void**)&csrp, g_csr);

    cudaFuncSetAttribute(fused_layer, cudaFuncAttributeMaxDynamicSharedMemorySize, FSMEM);
    cudaFuncSetAttribute(mma_gemm, cudaFuncAttributeMaxDynamicSharedMemorySize, SMEM_SZ);

    const float bnscale = rsqrtf(1.0f + 1e-5f);
    const int* src = ei;
    const int* dst = ei + EE;

    // 1: setup (weights + x image)
    setup_kernel<<<31400, 256>>>(lin_l_W, lin_r_W, mlp_W1, blk_Wa, blk_Wb, mlp_W2, post_W1,
                                 x_in, (unsigned short*)whi, (unsigned short*)wlo, xih, xil);
    // 2: CSR (count+scan+fill, one persistent kernel)
    csr_kernel<<<CSRB, 256>>>(src, dst, cnti, offp, curp, csrp);

    for (int i = 0; i < NLAYER; i++) {
        // 3: gather (hi only)
        gather_img<<<(NN + 1) / 2, 256>>>(xih, offp, csrp, zih);

        SlotTab tab;
        int s = 0;
        auto push1 = [&](int base, int n) {
            for (int c = 0; c < n; c++) tab.p[s++] = whi + (size_t)(base + c) * 2048;
        };
        push1(i * 8, 4);                 // cat-x (lin_l)           slots 0-3
        push1(i * 8 + 4, 4);             // cat-z (lin_r)           slots 4-7
        push1(24 + i * 4, 4);            // w1                      slots 8-11
        push1(36 + (2 * i) * 4, 4);      // wa0                     slots 12-15
        push1(60 + (2 * i) * 4, 4);      // wb0                     slots 16-19
        push1(36 + (2 * i + 1) * 4, 4);  // wa1                     slots 20-23
        push1(60 + (2 * i + 1) * 4, 4);  // wb1                     slots 24-27
        push1(84 + i * 4, 4);            // w2                      slots 28-31

        size_t bo0 = ((size_t)i * 2) * 256, bo1 = ((size_t)i * 2 + 1) * 256;
        // 4: fused layer  <-- profiled launch
        fused_layer<<<NB, 512, FSMEM>>>(
            xih, xil, zih, tab,
            lin_l_b + (size_t)i * 256, lin_r_b + (size_t)i * 256,
            mlp_b1 + (size_t)i * 256,
            blk_ba + bo0, blk_gamma + bo0, blk_beta + bo0, blk_bb + bo0,
            blk_ba + bo1, blk_gamma + bo1, blk_beta + bo1, blk_bb + bo1,
            mlp_b2 + (size_t)i * 256, bnscale,
            hih, hil);
    }

    mma_gemm<<<NB, 512, SMEM_SZ>>>(xih, xil, whi + (size_t)96 * 2048,
                                   wlo + (size_t)96 * 2048, post_b1, pp, NN);
    head_kernel<<<(NN + 7) / 8, 256>>>(pp, post_W2, post_b2, out);
}

// round 12
// speedup vs baseline: 4.4634x; 1.0669x over previous
#include <cuda_runtime.h>
#include <cuda_bf16.h>
#include <math.h>

#define NN 50000
#define ROWSP 50048
#define DD 256
#define EE 800000
#define NCLS 47
#define NLAYER 3
#define NB 391
#define CSRB 148

#define SWZ(x) ((x) ^ (((x) >> 3) & 0x70))

// ---- fused kernel smem layout ----
// A image: 4 chunks x 16KB (hi only) @ 0..65536
// B ring:  2 slots x 64KB @ 65536..196608
// rsum:    2KB @ 196608
#define FS_B 65536
#define RSUM_OFF 196608
#define FSMEM 198656

// ---------------- device scratch ----------------
__device__ float g_p[ROWSP * DD];
__device__ uint4 g_whi4[100 * 2048];
__device__ uint4 g_wlo4[100 * 2048];   // kept for layout compat (unused now)
__device__ unsigned g_ximg_hi[4 * ROWSP * 32];
__device__ unsigned g_zimg_hi[4 * ROWSP * 32];
__device__ unsigned g_himg_hi[4 * ROWSP * 32];
__device__ unsigned g_himg_lo[4 * ROWSP * 32];
__device__ int g_cnti[NN];          // static zero-init; self-zeroed each run
__device__ int g_off[NN + 1];
__device__ int g_cur[NN];
__device__ int g_csr[EE];
__device__ int g_partial[CSRB];
__device__ int g_pscan[CSRB];
__device__ unsigned g_bar;

struct SlotTab { const uint4* p[18]; };

static __device__ __forceinline__ unsigned smem_u32(const void* p) {
    unsigned a;
    asm("{ .reg .u64 t; cvta.to.shared.u64 t, %1; cvt.u32.u64 %0, t; }" : "=r"(a) : "l"(p));
    return a;
}
static __device__ __forceinline__ void ldsm4(unsigned r[4], unsigned addr) {
    asm volatile("ldmatrix.sync.aligned.m8n8.x4.shared.b16 {%0,%1,%2,%3}, [%4];"
                 : "=r"(r[0]), "=r"(r[1]), "=r"(r[2]), "=r"(r[3]) : "r"(addr));
}
static __device__ __forceinline__ void mma16816(float d[4], const unsigned a[4],
                                                unsigned b0, unsigned b1) {
    asm volatile(
        "mma.sync.aligned.m16n8k16.row.col.f32.bf16.bf16.f32 "
        "{%0,%1,%2,%3}, {%4,%5,%6,%7}, {%8,%9}, {%0,%1,%2,%3};"
        : "+f"(d[0]), "+f"(d[1]), "+f"(d[2]), "+f"(d[3])
        : "r"(a[0]), "r"(a[1]), "r"(a[2]), "r"(a[3]), "r"(b0), "r"(b1));
}
#define CPA(dst, src) \
    asm volatile("cp.async.cg.shared.global [%0], [%1], 16;" :: "r"(dst), "l"(src) : "memory")
#define CP_COMMIT() asm volatile("cp.async.commit_group;" ::: "memory")
template <int N>
static __device__ __forceinline__ void cp_wait() {
    asm volatile("cp.async.wait_group %0;" :: "n"(N) : "memory");
}

static __device__ __forceinline__ void bsplit(float v, unsigned& h, unsigned& l) {
    __nv_bfloat16 hb = __float2bfloat16(v);
    h = __bfloat16_as_ushort(hb);
    l = __bfloat16_as_ushort(__float2bfloat16(v - __bfloat162float(hb)));
}
static __device__ __forceinline__ unsigned bhi(float v) {
    return (unsigned)__bfloat16_as_ushort(__float2bfloat16(v));
}
static __device__ __forceinline__ unsigned img_idx(int chunk, int row, int lc) {
    return ((unsigned)chunk * ROWSP + (unsigned)row) * 32u +
           ((((unsigned)(lc * 2)) ^ (((unsigned)row & 7u) << 4)) >> 2);
}
static __device__ __forceinline__ void img_write2(unsigned* __restrict__ hi,
                                                  unsigned* __restrict__ lo, int chunk,
                                                  int row, int lc, float v0, float v1) {
    unsigned h0, l0, h1, l1;
    bsplit(v0, h0, l0);
    bsplit(v1, h1, l1);
    unsigned idx = img_idx(chunk, row, lc);
    hi[idx] = h0 | (h1 << 16);
    lo[idx] = l0 | (l1 << 16);
}
static __device__ __forceinline__ void img_write_hi(unsigned* __restrict__ hi, int chunk,
                                                    int row, int lc, float v0, float v1) {
    hi[img_idx(chunk, row, lc)] = bhi(v0) | (bhi(v1) << 16);
}
static __device__ __forceinline__ float2 img_read2(const unsigned* __restrict__ hi,
                                                   const unsigned* __restrict__ lo, int chunk,
                                                   int row, int lc) {
    unsigned idx = img_idx(chunk, row, lc);
    unsigned h = hi[idx], l = lo[idx];
    float x0 = __bfloat162float(__ushort_as_bfloat16((unsigned short)(h & 0xffff))) +
               __bfloat162float(__ushort_as_bfloat16((unsigned short)(l & 0xffff)));
    float x1 = __bfloat162float(__ushort_as_bfloat16((unsigned short)(h >> 16))) +
               __bfloat162float(__ushort_as_bfloat16((unsigned short)(l >> 16)));
    return make_float2(x0, x1);
}
static __device__ __forceinline__ float2 img_read_hi(const unsigned* __restrict__ hi,
                                                     int chunk, int row, int lc) {
    unsigned h = hi[img_idx(chunk, row, lc)];
    return make_float2(
        __bfloat162float(__ushort_as_bfloat16((unsigned short)(h & 0xffff))),
        __bfloat162float(__ushort_as_bfloat16((unsigned short)(h >> 16))));
}

// ---------------- setup: weight prep + x image (ONE launch) ----------------
__global__ void setup_kernel(const float* __restrict__ linl, const float* __restrict__ linr,
                             const float* __restrict__ w1, const float* __restrict__ wa,
                             const float* __restrict__ wb, const float* __restrict__ w2,
                             const float* __restrict__ post, const float* __restrict__ X,
                             unsigned short* __restrict__ dhi,
                             unsigned* __restrict__ xih) {
    int b = blockIdx.x;
    if (b < 6400) {
        int idx = b * 256 + threadIdx.x;
        int m = idx >> 16;
        int rem = idx & 65535;
        int n = rem & 255, k = rem >> 8;
        const float* W;
        int chunk;
        if (m < 3)       { W = linl + (size_t)m * 65536;       chunk = 0  + m * 8 + (k >> 6); }
        else if (m < 6)  { W = linr + (size_t)(m - 3) * 65536; chunk = 4  + (m - 3) * 8 + (k >> 6); }
        else if (m < 9)  { W = w1 + (size_t)(m - 6) * 65536;   chunk = 24 + (m - 6) * 4 + (k >> 6); }
        else if (m < 15) { W = wa + (size_t)(m - 9) * 65536;   chunk = 36 + (m - 9) * 4 + (k >> 6); }
        else if (m < 21) { W = wb + (size_t)(m - 15) * 65536;  chunk = 60 + (m - 15) * 4 + (k >> 6); }
        else if (m < 24) { W = w2 + (size_t)(m - 21) * 65536;  chunk = 84 + (m - 21) * 4 + (k >> 6); }
        else             { W = post;                           chunk = 96 + (k >> 6); }
        float v = W[(size_t)k * 256 + n];
        unsigned off = (unsigned)chunk * 32768u + SWZ((unsigned)(n * 128 + (k & 63) * 2));
        dhi[off >> 1] = (unsigned short)bhi(v);
    } else {
        int idx = (b - 6400) * 256 + threadIdx.x;   // < NN*128 exactly
        int row = idx >> 7, p = idx & 127;
        float v0 = X[(size_t)row * 256 + p * 2];
        float v1 = X[(size_t)row * 256 + p * 2 + 1];
        img_write_hi(xih, (p * 2) >> 6, row, (p * 2) & 63, v0, v1);
    }
}

// ---------------- single-kernel CSR build (persistent grid + sw barrier) ----------------
static __device__ __forceinline__ void gridbar() {
    __syncthreads();
    __threadfence();
    if (threadIdx.x == 0) {
        unsigned arr = atomicAdd(&g_bar, 1u);
        unsigned target = (arr / CSRB + 1u) * CSRB;
        while (*(volatile unsigned*)&g_bar < target) { }
    }
    __syncthreads();
}

__global__ void csr_kernel(const int* __restrict__ src, const int* __restrict__ dst,
                           int* __restrict__ cnt, int* __restrict__ off,
                           int* __restrict__ cur, int* __restrict__ csr) {
    __shared__ int sdata[256];
    const int b = blockIdx.x, t = threadIdx.x;
    for (int e = b * 256 + t; e < EE; e += CSRB * 256)
        atomicAdd(&cnt[dst[e]], 1);
    gridbar();
    int n0 = (b * 256 + t) * 2;
    int c0 = (n0 < NN) ? cnt[n0] : 0;
    int c1 = (n0 + 1 < NN) ? cnt[n0 + 1] : 0;
    if (n0 < NN) cnt[n0] = 0;
    if (n0 + 1 < NN) cnt[n0 + 1] = 0;
    int ts = c0 + c1;
    sdata[t] = ts;
    __syncthreads();
#pragma unroll
    for (int o = 1; o < 256; o <<= 1) {
        int v = (t >= o) ? sdata[t - o] : 0;
        __syncthreads();
        sdata[t] += v;
        __syncthreads();
    }
    int bexcl = sdata[t] - ts;
    if (t == 255) g_partial[b] = sdata[t];
    gridbar();
    if (b == 0) {
        int v = (t < CSRB) ? g_partial[t] : 0;
        sdata[t] = v;
        __syncthreads();
#pragma unroll
        for (int o = 1; o < 256; o <<= 1) {
            int w = (t >= o) ? sdata[t - o] : 0;
            __syncthreads();
            sdata[t] += w;
            __syncthreads();
        }
        if (t < CSRB) g_pscan[t] = sdata[t] - v;
        if (t == 0) off[0] = 0;
    }
    gridbar();
    int base = g_pscan[b] + bexcl;
    if (n0 < NN) {
        cur[n0] = base;
        off[n0 + 1] = base + c0;
        if (n0 + 1 < NN) {
            cur[n0 + 1] = base + c0;
            if (n0 + 2 <= NN) off[n0 + 2] = base + c0 + c1;
        }
    }
    gridbar();
    for (int e = b * 256 + t; e < EE; e += CSRB * 256) {
        int p = atomicAdd(&cur[dst[e]], 1);
        csr[p] = src[e];
    }
}

// ---------------- gather (hi-only, unroll-4) ----------------
__global__ void gather_img(const unsigned* __restrict__ xih,
                           const int* __restrict__ off, const int* __restrict__ csr,
                           unsigned* __restrict__ zih) {
    int w = (blockIdx.x * 256 + threadIdx.x) >> 5;
    int d = w >> 2, c = w & 3;
    if (d >= NN) return;
    int lane = threadIdx.x & 31;
    int lc = lane * 2;
    int b = off[d], e = off[d + 1];
    float s0 = 0.f, s1 = 0.f;
    int j = b;
    for (; j + 3 < e; j += 4) {
        float2 v0 = img_read_hi(xih, c, csr[j], lc);
        float2 v1 = img_read_hi(xih, c, csr[j + 1], lc);
        float2 v2 = img_read_hi(xih, c, csr[j + 2], lc);
        float2 v3 = img_read_hi(xih, c, csr[j + 3], lc);
        s0 += (v0.x + v1.x) + (v2.x + v3.x);
        s1 += (v0.y + v1.y) + (v2.y + v3.y);
    }
    for (; j < e; j++) {
        float2 v = img_read_hi(xih, c, csr[j], lc);
        s0 += v.x;
        s1 += v.y;
    }
    float iv = 1.f / fmaxf((float)(e - b), 1.f);
    img_write_hi(zih, c, d, lc, s0 * iv, s1 * iv);
}

// ---- fused-layer MMA micro-kernel: one 32KB B chunk (k=64) vs one 16KB A chunk ----
static __device__ __forceinline__ void mma_chunk(unsigned abase, unsigned bbase,
                                                 float (&acc)[2][8][4], int wm0, int wn0,
                                                 int lane) {
    const int lrow = lane & 15;
    const int lk = (lane >> 4) * 8;
#pragma unroll
    for (int ks = 0; ks < 4; ks++) {
        const int k0 = ks * 16;
        unsigned ahi[2][4];
#pragma unroll
        for (int mi = 0; mi < 2; mi++) {
            unsigned off = SWZ((unsigned)((wm0 + mi * 16 + lrow) * 128 + (k0 + lk) * 2));
            ldsm4(ahi[mi], abase + off);
        }
#pragma unroll
        for (int h = 0; h < 2; h++) {
            unsigned bb[2][4];
#pragma unroll
            for (int nb = 0; nb < 2; nb++) {
                unsigned off = SWZ((unsigned)((wn0 + (h * 2 + nb) * 16 + lrow) * 128 + (k0 + lk) * 2));
                ldsm4(bb[nb], bbase + off);
            }
#pragma unroll
            for (int mi = 0; mi < 2; mi++)
#pragma unroll
                for (int f = 0; f < 4; f++) {
                    int nb = f >> 1, r0 = f & 1;
                    mma16816(acc[mi][h * 4 + f], ahi[mi], bb[nb][r0], bb[nb][r0 + 2]);
                }
        }
    }
}

// ---------------- fused layer kernel ----------------
// K-chunk 128 slots: each slot = 64KB B block (2 weight chunks) vs 2 A chunks.
// Slot map: cat-x 0-1, cat-z 2-3, w1 4-5, wa0 6-7, wb0 8-9, wa1 10-11, wb1 12-13,
//           w2 14-15, [post 16-17 if haspost]
__global__ void __launch_bounds__(512, 1)
fused_layer(unsigned* __restrict__ ximg_hi, const unsigned* __restrict__ zimg_hi,
            SlotTab tab, int nslots,
            const float* __restrict__ bl, const float* __restrict__ br,
            const float* __restrict__ b1,
            const float* __restrict__ ba0, const float* __restrict__ g0,
            const float* __restrict__ be0, const float* __restrict__ bb0,
            const float* __restrict__ ba1, const float* __restrict__ g1,
            const float* __restrict__ be1, const float* __restrict__ bb1,
            const float* __restrict__ b2, const float* __restrict__ postb, float bnscale,
            unsigned* __restrict__ himg_hi, unsigned* __restrict__ himg_lo,
            float* __restrict__ pp) {
    extern __shared__ char smem[];
    const unsigned sb = smem_u32(smem);
    const int tid = threadIdx.x, wid = tid >> 5, lane = tid & 31;
    const int bm0 = blockIdx.x * 128;
    const int wm0 = (wid >> 2) * 32;
    const int wn0 = (wid & 3) * 64;
    const int tr = lane >> 2;
    const int tc2 = (lane & 3) * 2;
    const bool haspost = (nslots > 16);

    float acc[2][8][4];
    auto zero_acc = [&]() {
#pragma unroll
        for (int a = 0; a < 2; a++)
#pragma unroll
            for (int b = 0; b < 8; b++)
#pragma unroll
                for (int c = 0; c < 4; c++) acc[a][b][c] = 0.f;
    };
    zero_acc();

    auto issue_B = [&](int s) {   // 64KB, no commit
        if (s >= nslots) return;
        const char* src = (const char*)tab.p[s];
        unsigned dstb = sb + FS_B + (unsigned)(s & 1) * 65536u;
#pragma unroll
        for (int i = 0; i < 8; i++) {
            int u = tid + i * 512;
            CPA(dstb + u * 16, src + u * 16);
        }
    };
    auto issue_z = [&](int c) {   // 16KB hi-only into A chunk c
        const char* gh = (const char*)(zimg_hi + ((size_t)c * ROWSP + bm0) * 32);
        unsigned cb = sb + (unsigned)c * 16384u;
#pragma unroll
        for (int i = 0; i < 2; i++) {
            int u = tid + i * 512;
            CPA(cb + u * 16, gh + u * 16);
        }
    };
    // one barrier per slot; issue next slot's B (ring slot (s+1)&1 was drained at s-1)
    auto slot = [&](int s, int ah, int zpair) {
        cp_wait<0>();
        __syncthreads();
        issue_B(s + 1);
        if (zpair >= 0) { issue_z(zpair * 2); issue_z(zpair * 2 + 1); }
        CP_COMMIT();
        unsigned bb = sb + FS_B + (unsigned)(s & 1) * 65536u;
        mma_chunk(sb + (unsigned)(ah * 2) * 16384u, bb, acc, wm0, wn0, lane);
        mma_chunk(sb + (unsigned)(ah * 2 + 1) * 16384u, bb + 32768u, acc, wm0, wn0, lane);
    };
    auto run2 = [&](int s0) { slot(s0, 0, -1); slot(s0 + 1, 1, -1); };
    auto conv_img = [&]() {   // acc -> smem A image (hi only); caller syncs BEFORE
        unsigned cb = (unsigned)(wn0 >> 6) * 16384u;
#pragma unroll
        for (int mi = 0; mi < 2; mi++)
#pragma unroll
            for (int ni = 0; ni < 8; ni++) {
                int lc = ni * 8 + tc2;
                float* d = acc[mi][ni];
                unsigned off = SWZ((unsigned)((wm0 + mi * 16 + tr) * 128 + lc * 2));
                *(unsigned*)(smem + cb + off) = bhi(d[0]) | (bhi(d[1]) << 16);
                off = SWZ((unsigned)((wm0 + mi * 16 + 8 + tr) * 128 + lc * 2));
                *(unsigned*)(smem + cb + off) = bhi(d[2]) | (bhi(d[3]) << 16);
            }
    };

    // ---- prologue: x image (hi only, 4x16KB) + B slot 0 ----
#pragma unroll
    for (int c = 0; c < 4; c++) {
        const char* gh = (const char*)(ximg_hi + ((size_t)c * ROWSP + bm0) * 32);
        unsigned cb = sb + (unsigned)c * 16384u;
#pragma unroll
        for (int i = 0; i < 2; i++) {
            int u = tid + i * 512;
            CPA(cb + u * 16, gh + u * 16);
        }
    }
    CP_COMMIT();
    issue_B(0);
    CP_COMMIT();

    // ---- cat: slots 0-1 (x), 2-3 (z); z pairs prefetched into drained A chunks ----
    slot(0, 0, -1);
    slot(1, 1, 0);
    slot(2, 0, 1);
    slot(3, 1, -1);
    __syncthreads();
#pragma unroll
    for (int mi = 0; mi < 2; mi++)
#pragma unroll
        for (int ni = 0; ni < 8; ni++) {
            int cg = wn0 + ni * 8 + tc2;
            float* d = acc[mi][ni];
            float a0 = bl[cg] + br[cg], a1 = bl[cg + 1] + br[cg + 1];
            d[0] += a0; d[1] += a1; d[2] += a0; d[3] += a1;
        }
    conv_img(); zero_acc();

    // ---- w1: slots 4-5 -> h0 (write himg) ----
    run2(4);
    __syncthreads();
#pragma unroll
    for (int mi = 0; mi < 2; mi++)
#pragma unroll
        for (int ni = 0; ni < 8; ni++) {
            int cg = wn0 + ni * 8 + tc2;
            float* d = acc[mi][ni];
            d[0] += b1[cg]; d[1] += b1[cg + 1]; d[2] += b1[cg]; d[3] += b1[cg + 1];
            int ra = bm0 + wm0 + mi * 16 + tr;
            img_write2(himg_hi, himg_lo, cg >> 6, ra, cg & 63, d[0], d[1]);
            img_write2(himg_hi, himg_lo, cg >> 6, ra + 8, cg & 63, d[2], d[3]);
        }
    conv_img(); zero_acc();

    // ---- blocks: wa j: 6+4j, wb j: 8+4j ----
#pragma unroll 1
    for (int j = 0; j < 2; j++) {
        const float* ba = j ? ba1 : ba0;
        const float* gg = j ? g1 : g0;
        const float* be = j ? be1 : be0;
        const float* bb = j ? bb1 : bb0;
        run2(6 + j * 4);
        __syncthreads();
#pragma unroll
        for (int mi = 0; mi < 2; mi++)
#pragma unroll
            for (int ni = 0; ni < 8; ni++) {
                int cg = wn0 + ni * 8 + tc2;
                float* d = acc[mi][ni];
                float ga = gg[cg], gb = gg[cg + 1], ea = be[cg], eb = be[cg + 1];
                float a0 = ba[cg], a1 = ba[cg + 1];
                d[0] = fmaf(ga, fmaxf(d[0] + a0, 0.f) * bnscale, ea);
                d[1] = fmaf(gb, fmaxf(d[1] + a1, 0.f) * bnscale, eb);
                d[2] = fmaf(ga, fmaxf(d[2] + a0, 0.f) * bnscale, ea);
                d[3] = fmaf(gb, fmaxf(d[3] + a1, 0.f) * bnscale, eb);
            }
        conv_img(); zero_acc();
        run2(8 + j * 4);
        __syncthreads();
#pragma unroll
        for (int mi = 0; mi < 2; mi++)
#pragma unroll
            for (int ni = 0; ni < 8; ni++) {
                int cg = wn0 + ni * 8 + tc2;
                float* d = acc[mi][ni];
                int ra = bm0 + wm0 + mi * 16 + tr;
                float2 ha = img_read2(himg_hi, himg_lo, cg >> 6, ra, cg & 63);
                float2 hb = img_read2(himg_hi, himg_lo, cg >> 6, ra + 8, cg & 63);
                d[0] += bb[cg] + ha.x; d[1] += bb[cg + 1] + ha.y;
                d[2] += bb[cg] + hb.x; d[3] += bb[cg + 1] + hb.y;
                if (j == 0) {
                    img_write2(himg_hi, himg_lo, cg >> 6, ra, cg & 63, d[0], d[1]);
                    img_write2(himg_hi, himg_lo, cg >> 6, ra + 8, cg & 63, d[2], d[3]);
                }
            }
        conv_img(); zero_acc();
    }

    // ---- w2: slots 14-15, normalize + relu ----
    run2(14);
    __syncthreads();
#pragma unroll
    for (int mi = 0; mi < 2; mi++)
#pragma unroll
        for (int ni = 0; ni < 8; ni++) {
            int cg = wn0 + ni * 8 + tc2;
            float* d = acc[mi][ni];
            d[0] += b2[cg]; d[1] += b2[cg + 1]; d[2] += b2[cg]; d[3] += b2[cg + 1];
        }
    {
        float* rsum = (float*)(smem + RSUM_OFF);
        float ps[2][2] = {{0.f, 0.f}, {0.f, 0.f}};
#pragma unroll
        for (int mi = 0; mi < 2; mi++)
#pragma unroll
            for (int ni = 0; ni < 8; ni++) {
                float* d = acc[mi][ni];
                ps[mi][0] = fmaf(d[0], d[0], fmaf(d[1], d[1], ps[mi][0]));
                ps[mi][1] = fmaf(d[2], d[2], fmaf(d[3], d[3], ps[mi][1]));
            }
#pragma unroll
        for (int mi = 0; mi < 2; mi++)
#pragma unroll
            for (int q = 0; q < 2; q++) {
                ps[mi][q] += __shfl_xor_sync(0xffffffffu, ps[mi][q], 1);
                ps[mi][q] += __shfl_xor_sync(0xffffffffu, ps[mi][q], 2);
            }
        if ((lane & 3) == 0) {
            int cw = wn0 >> 6;
#pragma unroll
            for (int mi = 0; mi < 2; mi++) {
                rsum[(wm0 + mi * 16 + tr) * 4 + cw] = ps[mi][0];
                rsum[(wm0 + mi * 16 + 8 + tr) * 4 + cw] = ps[mi][1];
            }
        }
        __syncthreads();
#pragma unroll
        for (int mi = 0; mi < 2; mi++) {
            int r0 = wm0 + mi * 16 + tr;
            int r1 = r0 + 8;
            float s0 = rsum[r0 * 4] + rsum[r0 * 4 + 1] + rsum[r0 * 4 + 2] + rsum[r0 * 4 + 3];
            float s1 = rsum[r1 * 4] + rsum[r1 * 4 + 1] + rsum[r1 * 4 + 2] + rsum[r1 * 4 + 3];
            float c0 = 1.f / fmaxf(sqrtf(s0), 1e-12f);
            float c1 = 1.f / fmaxf(sqrtf(s1), 1e-12f);
#pragma unroll
            for (int ni = 0; ni < 8; ni++) {
                float* d = acc[mi][ni];
                d[0] = fmaxf(d[0] * c0, 0.f); d[1] = fmaxf(d[1] * c0, 0.f);
                d[2] = fmaxf(d[2] * c1, 0.f); d[3] = fmaxf(d[3] * c1, 0.f);
            }
        }
    }
    if (!haspost) {
        // write x image for next layer's gather + prologue
#pragma unroll
        for (int mi = 0; mi < 2; mi++)
#pragma unroll
            for (int ni = 0; ni < 8; ni++) {
                int cg = wn0 + ni * 8 + tc2;
                int ra = bm0 + wm0 + mi * 16 + tr;
                float* d = acc[mi][ni];
                img_write_hi(ximg_hi, cg >> 6, ra, cg & 63, d[0], d[1]);
                img_write_hi(ximg_hi, cg >> 6, ra + 8, cg & 63, d[2], d[3]);
            }
        return;
    }
    // ---- post stage (layer 3 only): x -> A image, slots 16-17, pp = x@postW1 + b ----
    conv_img(); zero_acc();
    run2(16);
    __syncthreads();
#pragma unroll
    for (int mi = 0; mi < 2; mi++)
#pragma unroll
        for (int ni = 0; ni < 8; ni++) {
            int cg = wn0 + ni * 8 + tc2;
            int ra = bm0 + wm0 + mi * 16 + tr;
            int rb = ra + 8;
            float* d = acc[mi][ni];
            float v0 = d[0] + postb[cg], v1 = d[1] + postb[cg + 1];
            float v2 = d[2] + postb[cg], v3 = d[3] + postb[cg + 1];
            if (ra < NN) *(float2*)(pp + (size_t)ra * 256 + cg) = make_float2(v0, v1);
            if (rb < NN) *(float2*)(pp + (size_t)rb * 256 + cg) = make_float2(v2, v3);
        }
}

// ---------------- head: logits [256->47] + log_softmax ----------------
__global__ void head_kernel(const float* __restrict__ h, const float* __restrict__ W2,
                            const float* __restrict__ b2, float* __restrict__ out) {
    __shared__ float sW[256 * NCLS];
    __shared__ float sb[NCLS];
    int tid = threadIdx.x;
    for (int i = tid; i < 256 * NCLS; i += 256) sW[i] = W2[i];
    if (tid < NCLS) sb[tid] = b2[tid];
    __syncthreads();

    int wid = tid >> 5, lane = tid & 31;
    int r = blockIdx.x * 8 + wid;
    if (r >= NN) return;

    const float4* rp = (const float4*)(h + (size_t)r * DD);
    float4 q0 = rp[lane * 2];
    float4 q1 = rp[lane * 2 + 1];
    float hreg[8] = {q0.x, q0.y, q0.z, q0.w, q1.x, q1.y, q1.z, q1.w};

    int c0 = lane;
    int c1 = lane + 32;
    int c1m = (c1 < NCLS) ? c1 : (NCLS - 1);
    float acc0 = sb[c0];
    float acc1 = sb[c1m];
#pragma unroll
    for (int e = 0; e < 8; e++) {
        for (int l = 0; l < 32; l++) {
            float hv = __shfl_sync(0xffffffffu, hreg[e], l);
            int k = l * 8 + e;
            acc0 = fmaf(hv, sW[k * NCLS + c0], acc0);
            acc1 = fmaf(hv, sW[k * NCLS + c1m], acc1);
        }
    }
    float m = fmaxf(acc0, (c1 < NCLS) ? acc1 : -3.4e38f);
#pragma unroll
    for (int o = 16; o > 0; o >>= 1) m = fmaxf(m, __shfl_xor_sync(0xffffffffu, m, o));
    float es = expf(acc0 - m) + ((c1 < NCLS) ? expf(acc1 - m) : 0.f);
#pragma unroll
    for (int o = 16; o > 0; o >>= 1) es += __shfl_xor_sync(0xffffffffu, es, o);
    float lse = m + logf(es);
    out[(size_t)r * NCLS + c0] = acc0 - lse;
    if (c1 < NCLS) out[(size_t)r * NCLS + c1] = acc1 - lse;
}

// ---------------- host orchestration ----------------
extern "C" void kernel_launch(void* const* d_in, const int* in_sizes, int n_in,
                              void* d_out, int out_size) {
    const float* x_in      = (const float*)d_in[0];
    const int* ei          = (const int*)d_in[1];
    const float* lin_l_W   = (const float*)d_in[2];
    const float* lin_l_b   = (const float*)d_in[3];
    const float* lin_r_W   = (const float*)d_in[4];
    const float* lin_r_b   = (const float*)d_in[5];
    const float* mlp_W1    = (const float*)d_in[6];
    const float* mlp_b1    = (const float*)d_in[7];
    const float* blk_Wa    = (const float*)d_in[8];
    const float* blk_ba    = (const float*)d_in[9];
    const float* blk_gamma = (const float*)d_in[10];
    const float* blk_beta  = (const float*)d_in[11];
    const float* blk_Wb    = (const float*)d_in[12];
    const float* blk_bb    = (const float*)d_in[13];
    const float* mlp_W2    = (const float*)d_in[14];
    const float* mlp_b2    = (const float*)d_in[15];
    const float* post_W1   = (const float*)d_in[16];
    const float* post_b1   = (const float*)d_in[17];
    const float* post_W2   = (const float*)d_in[18];
    const float* post_b2   = (const float*)d_in[19];
    float* out = (float*)d_out;

    float* pp;
    uint4* whi;
    unsigned *xih, *zih, *hih, *hil;
    int *cnti, *offp, *curp, *csrp;
    cudaGetSymbolAddress((void**)&pp, g_p);
    cudaGetSymbolAddress((void**)&whi, g_whi4);
    cudaGetSymbolAddress((void**)&xih, g_ximg_hi);
    cudaGetSymbolAddress((void**)&zih, g_zimg_hi);
    cudaGetSymbolAddress((void**)&hih, g_himg_hi);
    cudaGetSymbolAddress((void**)&hil, g_himg_lo);
    cudaGetSymbolAddress((void**)&cnti, g_cnti);
    cudaGetSymbolAddress((void**)&offp, g_off);
    cudaGetSymbolAddress((void**)&curp, g_cur);
    cudaGetSymbolAddress((void**)&csrp, g_csr);

    cudaFuncSetAttribute(fused_layer, cudaFuncAttributeMaxDynamicSharedMemorySize, FSMEM);

    const float bnscale = rsqrtf(1.0f + 1e-5f);
    const int* src = ei;
    const int* dst = ei + EE;

    // 1: setup (weights + x image)
    setup_kernel<<<31400, 256>>>(lin_l_W, lin_r_W, mlp_W1, blk_Wa, blk_Wb, mlp_W2, post_W1,
                                 x_in, (unsigned short*)whi, xih);
    // 2: CSR (count+scan+fill, one persistent kernel)
    csr_kernel<<<CSRB, 256>>>(src, dst, cnti, offp, curp, csrp);

    for (int i = 0; i < NLAYER; i++) {
        // 3: gather (hi only)
        gather_img<<<(NN + 1) / 2, 256>>>(xih, offp, csrp, zih);

        SlotTab tab;
        int s = 0;
        auto push = [&](int base) {   // one 256x256 matrix = 2 slots of 64KB
            tab.p[s++] = whi + (size_t)base * 2048;
            tab.p[s++] = whi + (size_t)(base + 2) * 2048;
        };
        push(i * 8);                 // cat-x (lin_l)           slots 0-1
        push(i * 8 + 4);             // cat-z (lin_r)           slots 2-3
        push(24 + i * 4);            // w1                      slots 4-5
        push(36 + (2 * i) * 4);      // wa0                     slots 6-7
        push(60 + (2 * i) * 4);      // wb0                     slots 8-9
        push(36 + (2 * i + 1) * 4);  // wa1                     slots 10-11
        push(60 + (2 * i + 1) * 4);  // wb1                     slots 12-13
        push(84 + i * 4);            // w2                      slots 14-15
        int nslots = 16;
        if (i == NLAYER - 1) { push(96); nslots = 18; }  // post slots 16-17

        size_t bo0 = ((size_t)i * 2) * 256, bo1 = ((size_t)i * 2 + 1) * 256;
        // 4: fused layer  <-- profiled launch
        fused_layer<<<NB, 512, FSMEM>>>(
            xih, zih, tab, nslots,
            lin_l_b + (size_t)i * 256, lin_r_b + (size_t)i * 256,
            mlp_b1 + (size_t)i * 256,
            blk_ba + bo0, blk_gamma + bo0, blk_beta + bo0, blk_bb + bo0,
            blk_ba + bo1, blk_gamma + bo1, blk_beta + bo1, blk_bb + bo1,
            mlp_b2 + (size_t)i * 256, post_b1, bnscale,
            hih, hil, pp);
    }

    head_kernel<<<(NN + 7) / 8, 256>>>(pp, post_W2, post_b2, out);
}

// round 13
// speedup vs baseline: 4.4982x; 1.0078x over previous
#include <cuda_runtime.h>
#include <cuda_bf16.h>
#include <math.h>

#define NN 50000
#define ROWSP 50048
#define DD 256
#define EE 800000
#define NCLS 47
#define NLAYER 3
#define NB 391
#define CSRB 148

#define SWZ(x) ((x) ^ (((x) >> 3) & 0x70))

// ---- fused kernel smem layout ----
#define FS_B 65536
#define RSUM_OFF 196608
#define FSMEM 198656

// ---------------- device scratch ----------------
__device__ float g_p[ROWSP * DD];
__device__ uint4 g_whi4[100 * 2048];
__device__ unsigned g_ximg_hi[4 * ROWSP * 32];
__device__ unsigned g_zimg_hi[4 * ROWSP * 32];
__device__ unsigned g_himg_hi[4 * ROWSP * 32];
__device__ unsigned g_himg_lo[4 * ROWSP * 32];
__device__ int g_cnti[NN];          // static zero-init; self-zeroed each run
__device__ int g_off[NN + 1];
__device__ int g_cur[NN];
__device__ int g_csr[EE];
__device__ int g_partial[CSRB];
__device__ int g_pscan[CSRB];
__device__ unsigned g_bar;

struct SlotTab { const uint4* p[18]; };

static __device__ __forceinline__ unsigned smem_u32(const void* p) {
    unsigned a;
    asm("{ .reg .u64 t; cvta.to.shared.u64 t, %1; cvt.u32.u64 %0, t; }" : "=r"(a) : "l"(p));
    return a;
}
static __device__ __forceinline__ void ldsm4(unsigned r[4], unsigned addr) {
    asm volatile("ldmatrix.sync.aligned.m8n8.x4.shared.b16 {%0,%1,%2,%3}, [%4];"
                 : "=r"(r[0]), "=r"(r[1]), "=r"(r[2]), "=r"(r[3]) : "r"(addr));
}
static __device__ __forceinline__ void mma16816(float d[4], const unsigned a[4],
                                                unsigned b0, unsigned b1) {
    asm volatile(
        "mma.sync.aligned.m16n8k16.row.col.f32.bf16.bf16.f32 "
        "{%0,%1,%2,%3}, {%4,%5,%6,%7}, {%8,%9}, {%0,%1,%2,%3};"
        : "+f"(d[0]), "+f"(d[1]), "+f"(d[2]), "+f"(d[3])
        : "r"(a[0]), "r"(a[1]), "r"(a[2]), "r"(a[3]), "r"(b0), "r"(b1));
}
#define CPA(dst, src) \
    asm volatile("cp.async.cg.shared.global [%0], [%1], 16;" :: "r"(dst), "l"(src) : "memory")
#define CP_COMMIT() asm volatile("cp.async.commit_group;" ::: "memory")
template <int N>
static __device__ __forceinline__ void cp_wait() {
    asm volatile("cp.async.wait_group %0;" :: "n"(N) : "memory");
}

static __device__ __forceinline__ void bsplit(float v, unsigned& h, unsigned& l) {
    __nv_bfloat16 hb = __float2bfloat16(v);
    h = __bfloat16_as_ushort(hb);
    l = __bfloat16_as_ushort(__float2bfloat16(v - __bfloat162float(hb)));
}
static __device__ __forceinline__ unsigned bhi(float v) {
    return (unsigned)__bfloat16_as_ushort(__float2bfloat16(v));
}
static __device__ __forceinline__ unsigned img_idx(int chunk, int row, int lc) {
    return ((unsigned)chunk * ROWSP + (unsigned)row) * 32u +
           ((((unsigned)(lc * 2)) ^ (((unsigned)row & 7u) << 4)) >> 2);
}
static __device__ __forceinline__ void img_write2(unsigned* __restrict__ hi,
                                                  unsigned* __restrict__ lo, int chunk,
                                                  int row, int lc, float v0, float v1) {
    unsigned h0, l0, h1, l1;
    bsplit(v0, h0, l0);
    bsplit(v1, h1, l1);
    unsigned idx = img_idx(chunk, row, lc);
    hi[idx] = h0 | (h1 << 16);
    lo[idx] = l0 | (l1 << 16);
}
static __device__ __forceinline__ void img_write_hi(unsigned* __restrict__ hi, int chunk,
                                                    int row, int lc, float v0, float v1) {
    hi[img_idx(chunk, row, lc)] = bhi(v0) | (bhi(v1) << 16);
}
static __device__ __forceinline__ float2 img_read2(const unsigned* __restrict__ hi,
                                                   const unsigned* __restrict__ lo, int chunk,
                                                   int row, int lc) {
    unsigned idx = img_idx(chunk, row, lc);
    unsigned h = hi[idx], l = lo[idx];
    float x0 = __bfloat162float(__ushort_as_bfloat16((unsigned short)(h & 0xffff))) +
               __bfloat162float(__ushort_as_bfloat16((unsigned short)(l & 0xffff)));
    float x1 = __bfloat162float(__ushort_as_bfloat16((unsigned short)(h >> 16))) +
               __bfloat162float(__ushort_as_bfloat16((unsigned short)(l >> 16)));
    return make_float2(x0, x1);
}

// ---------------- setup: weight prep + x image (ONE launch) ----------------
__global__ void setup_kernel(const float* __restrict__ linl, const float* __restrict__ linr,
                             const float* __restrict__ w1, const float* __restrict__ wa,
                             const float* __restrict__ wb, const float* __restrict__ w2,
                             const float* __restrict__ post, const float* __restrict__ X,
                             unsigned short* __restrict__ dhi,
                             unsigned* __restrict__ xih) {
    int b = blockIdx.x;
    if (b < 6400) {
        int idx = b * 256 + threadIdx.x;
        int m = idx >> 16;
        int rem = idx & 65535;
        int n = rem & 255, k = rem >> 8;
        const float* W;
        int chunk;
        if (m < 3)       { W = linl + (size_t)m * 65536;       chunk = 0  + m * 8 + (k >> 6); }
        else if (m < 6)  { W = linr + (size_t)(m - 3) * 65536; chunk = 4  + (m - 3) * 8 + (k >> 6); }
        else if (m < 9)  { W = w1 + (size_t)(m - 6) * 65536;   chunk = 24 + (m - 6) * 4 + (k >> 6); }
        else if (m < 15) { W = wa + (size_t)(m - 9) * 65536;   chunk = 36 + (m - 9) * 4 + (k >> 6); }
        else if (m < 21) { W = wb + (size_t)(m - 15) * 65536;  chunk = 60 + (m - 15) * 4 + (k >> 6); }
        else if (m < 24) { W = w2 + (size_t)(m - 21) * 65536;  chunk = 84 + (m - 21) * 4 + (k >> 6); }
        else             { W = post;                           chunk = 96 + (k >> 6); }
        float v = W[(size_t)k * 256 + n];
        unsigned off = (unsigned)chunk * 32768u + SWZ((unsigned)(n * 128 + (k & 63) * 2));
        dhi[off >> 1] = (unsigned short)bhi(v);
    } else {
        int idx = (b - 6400) * 256 + threadIdx.x;   // < NN*128 exactly
        int row = idx >> 7, p = idx & 127;
        float v0 = X[(size_t)row * 256 + p * 2];
        float v1 = X[(size_t)row * 256 + p * 2 + 1];
        img_write_hi(xih, (p * 2) >> 6, row, (p * 2) & 63, v0, v1);
    }
}

// ---------------- single-kernel CSR build (persistent grid + sw barrier) ----------------
static __device__ __forceinline__ void gridbar() {
    __syncthreads();
    __threadfence();
    if (threadIdx.x == 0) {
        unsigned arr = atomicAdd(&g_bar, 1u);
        unsigned target = (arr / CSRB + 1u) * CSRB;
        while (*(volatile unsigned*)&g_bar < target) { }
    }
    __syncthreads();
}

__global__ void csr_kernel(const int* __restrict__ src, const int* __restrict__ dst,
                           int* __restrict__ cnt, int* __restrict__ off,
                           int* __restrict__ cur, int* __restrict__ csr) {
    __shared__ int sdata[256];
    const int b = blockIdx.x, t = threadIdx.x;
    for (int e = b * 256 + t; e < EE; e += CSRB * 256)
        atomicAdd(&cnt[dst[e]], 1);
    gridbar();
    int n0 = (b * 256 + t) * 2;
    int c0 = (n0 < NN) ? cnt[n0] : 0;
    int c1 = (n0 + 1 < NN) ? cnt[n0 + 1] : 0;
    if (n0 < NN) cnt[n0] = 0;
    if (n0 + 1 < NN) cnt[n0 + 1] = 0;
    int ts = c0 + c1;
    sdata[t] = ts;
    __syncthreads();
#pragma unroll
    for (int o = 1; o < 256; o <<= 1) {
        int v = (t >= o) ? sdata[t - o] : 0;
        __syncthreads();
        sdata[t] += v;
        __syncthreads();
    }
    int bexcl = sdata[t] - ts;
    if (t == 255) g_partial[b] = sdata[t];
    gridbar();
    if (b == 0) {
        int v = (t < CSRB) ? g_partial[t] : 0;
        sdata[t] = v;
        __syncthreads();
#pragma unroll
        for (int o = 1; o < 256; o <<= 1) {
            int w = (t >= o) ? sdata[t - o] : 0;
            __syncthreads();
            sdata[t] += w;
            __syncthreads();
        }
        if (t < CSRB) g_pscan[t] = sdata[t] - v;
        if (t == 0) off[0] = 0;
    }
    gridbar();
    int base = g_pscan[b] + bexcl;
    if (n0 < NN) {
        cur[n0] = base;
        off[n0 + 1] = base + c0;
        if (n0 + 1 < NN) {
            cur[n0 + 1] = base + c0;
            if (n0 + 2 <= NN) off[n0 + 2] = base + c0 + c1;
        }
    }
    gridbar();
    for (int e = b * 256 + t; e < EE; e += CSRB * 256) {
        int p = atomicAdd(&cur[dst[e]], 1);
        csr[p] = src[e];
    }
}

// ---------------- gather (hi-only, 8-wide MLP) ----------------
// warp per (node, 64-col chunk); per-lane word idx = row_base + (lane ^ ((row&7)<<2))
__global__ void gather_img(const unsigned* __restrict__ xih,
                           const int* __restrict__ off, const int* __restrict__ csr,
                           unsigned* __restrict__ zih) {
    int w = (blockIdx.x * 256 + threadIdx.x) >> 5;
    int d = w >> 2, c = w & 3;
    if (d >= NN) return;
    int lane = threadIdx.x & 31;
    int b = off[d], e = off[d + 1];
    const unsigned* __restrict__ base = xih + (size_t)c * ROWSP * 32u;
    float s0 = 0.f, s1 = 0.f;
    int j = b;
    for (; j + 8 <= e; j += 8) {
        int r[8];
#pragma unroll
        for (int q = 0; q < 8; q++) r[q] = __ldg(&csr[j + q]);
        unsigned v[8];
#pragma unroll
        for (int q = 0; q < 8; q++)
            v[q] = __ldg(&base[(unsigned)r[q] * 32u + ((unsigned)lane ^ (((unsigned)r[q] & 7u) << 2))]);
#pragma unroll
        for (int q = 0; q < 8; q++) {
            s0 += __bfloat162float(__ushort_as_bfloat16((unsigned short)(v[q] & 0xffff)));
            s1 += __bfloat162float(__ushort_as_bfloat16((unsigned short)(v[q] >> 16)));
        }
    }
    for (; j + 2 <= e; j += 2) {
        int r0 = __ldg(&csr[j]), r1 = __ldg(&csr[j + 1]);
        unsigned v0 = __ldg(&base[(unsigned)r0 * 32u + ((unsigned)lane ^ (((unsigned)r0 & 7u) << 2))]);
        unsigned v1 = __ldg(&base[(unsigned)r1 * 32u + ((unsigned)lane ^ (((unsigned)r1 & 7u) << 2))]);
        s0 += __bfloat162float(__ushort_as_bfloat16((unsigned short)(v0 & 0xffff))) +
              __bfloat162float(__ushort_as_bfloat16((unsigned short)(v1 & 0xffff)));
        s1 += __bfloat162float(__ushort_as_bfloat16((unsigned short)(v0 >> 16))) +
              __bfloat162float(__ushort_as_bfloat16((unsigned short)(v1 >> 16)));
    }
    if (j < e) {
        int r0 = __ldg(&csr[j]);
        unsigned v0 = __ldg(&base[(unsigned)r0 * 32u + ((unsigned)lane ^ (((unsigned)r0 & 7u) << 2))]);
        s0 += __bfloat162float(__ushort_as_bfloat16((unsigned short)(v0 & 0xffff)));
        s1 += __bfloat162float(__ushort_as_bfloat16((unsigned short)(v0 >> 16)));
    }
    float iv = 1.f / fmaxf((float)(e - b), 1.f);
    img_write_hi(zih, c, d, lane * 2, s0 * iv, s1 * iv);
}

// ---- fused-layer MMA micro-kernel: one 32KB B chunk (k=64) vs one 16KB A chunk ----
static __device__ __forceinline__ void mma_chunk(unsigned abase, unsigned bbase,
                                                 float (&acc)[2][8][4], int wm0, int wn0,
                                                 int lane) {
    const int lrow = lane & 15;
    const int lk = (lane >> 4) * 8;
#pragma unroll
    for (int ks = 0; ks < 4; ks++) {
        const int k0 = ks * 16;
        unsigned ahi[2][4];
#pragma unroll
        for (int mi = 0; mi < 2; mi++) {
            unsigned off = SWZ((unsigned)((wm0 + mi * 16 + lrow) * 128 + (k0 + lk) * 2));
            ldsm4(ahi[mi], abase + off);
        }
#pragma unroll
        for (int h = 0; h < 2; h++) {
            unsigned bb[2][4];
#pragma unroll
            for (int nb = 0; nb < 2; nb++) {
                unsigned off = SWZ((unsigned)((wn0 + (h * 2 + nb) * 16 + lrow) * 128 + (k0 + lk) * 2));
                ldsm4(bb[nb], bbase + off);
            }
#pragma unroll
            for (int mi = 0; mi < 2; mi++)
#pragma unroll
                for (int f = 0; f < 4; f++) {
                    int nb = f >> 1, r0 = f & 1;
                    mma16816(acc[mi][h * 4 + f], ahi[mi], bb[nb][r0], bb[nb][r0 + 2]);
                }
        }
    }
}

// ---------------- fused layer kernel ----------------
// Slot map: cat-x 0-1, cat-z 2-3, w1 4-5, wa0 6-7, wb0 8-9, wa1 10-11, wb1 12-13,
//           w2 14-15, [post 16-17 if haspost]
__global__ void __launch_bounds__(512, 1)
fused_layer(unsigned* __restrict__ ximg_hi, const unsigned* __restrict__ zimg_hi,
            SlotTab tab, int nslots,
            const float* __restrict__ bl, const float* __restrict__ br,
            const float* __restrict__ b1,
            const float* __restrict__ ba0, const float* __restrict__ g0,
            const float* __restrict__ be0, const float* __restrict__ bb0,
            const float* __restrict__ ba1, const float* __restrict__ g1,
            const float* __restrict__ be1, const float* __restrict__ bb1,
            const float* __restrict__ b2, const float* __restrict__ postb, float bnscale,
            unsigned* __restrict__ himg_hi, unsigned* __restrict__ himg_lo,
            float* __restrict__ pp) {
    extern __shared__ char smem[];
    const unsigned sb = smem_u32(smem);
    const int tid = threadIdx.x, wid = tid >> 5, lane = tid & 31;
    const int bm0 = blockIdx.x * 128;
    const int wm0 = (wid >> 2) * 32;
    const int wn0 = (wid & 3) * 64;
    const int tr = lane >> 2;
    const int tc2 = (lane & 3) * 2;
    const bool haspost = (nslots > 16);

    float acc[2][8][4];
    auto zero_acc = [&]() {
#pragma unroll
        for (int a = 0; a < 2; a++)
#pragma unroll
            for (int b = 0; b < 8; b++)
#pragma unroll
                for (int c = 0; c < 4; c++) acc[a][b][c] = 0.f;
    };
    zero_acc();

    auto issue_B = [&](int s) {   // 64KB, no commit
        if (s >= nslots) return;
        const char* src = (const char*)tab.p[s];
        unsigned dstb = sb + FS_B + (unsigned)(s & 1) * 65536u;
#pragma unroll
        for (int i = 0; i < 8; i++) {
            int u = tid + i * 512;
            CPA(dstb + u * 16, src + u * 16);
        }
    };
    auto issue_z = [&](int c) {   // 16KB hi-only into A chunk c
        const char* gh = (const char*)(zimg_hi + ((size_t)c * ROWSP + bm0) * 32);
        unsigned cb = sb + (unsigned)c * 16384u;
#pragma unroll
        for (int i = 0; i < 2; i++) {
            int u = tid + i * 512;
            CPA(cb + u * 16, gh + u * 16);
        }
    };
    auto slot = [&](int s, int ah, int zpair) {
        cp_wait<0>();
        __syncthreads();
        issue_B(s + 1);
        if (zpair >= 0) { issue_z(zpair * 2); issue_z(zpair * 2 + 1); }
        CP_COMMIT();
        unsigned bb = sb + FS_B + (unsigned)(s & 1) * 65536u;
        mma_chunk(sb + (unsigned)(ah * 2) * 16384u, bb, acc, wm0, wn0, lane);
        mma_chunk(sb + (unsigned)(ah * 2 + 1) * 16384u, bb + 32768u, acc, wm0, wn0, lane);
    };
    auto run2 = [&](int s0) { slot(s0, 0, -1); slot(s0 + 1, 1, -1); };
    auto conv_img = [&]() {   // acc -> smem A image (hi only); caller syncs BEFORE
        unsigned cb = (unsigned)(wn0 >> 6) * 16384u;
#pragma unroll
        for (int mi = 0; mi < 2; mi++)
#pragma unroll
            for (int ni = 0; ni < 8; ni++) {
                int lc = ni * 8 + tc2;
                float* d = acc[mi][ni];
                unsigned off = SWZ((unsigned)((wm0 + mi * 16 + tr) * 128 + lc * 2));
                *(unsigned*)(smem + cb + off) = bhi(d[0]) | (bhi(d[1]) << 16);
                off = SWZ((unsigned)((wm0 + mi * 16 + 8 + tr) * 128 + lc * 2));
                *(unsigned*)(smem + cb + off) = bhi(d[2]) | (bhi(d[3]) << 16);
            }
    };

    // ---- prologue: x image (hi only, 4x16KB) + B slot 0 ----
#pragma unroll
    for (int c = 0; c < 4; c++) {
        const char* gh = (const char*)(ximg_hi + ((size_t)c * ROWSP + bm0) * 32);
        unsigned cb = sb + (unsigned)c * 16384u;
#pragma unroll
        for (int i = 0; i < 2; i++) {
            int u = tid + i * 512;
            CPA(cb + u * 16, gh + u * 16);
        }
    }
    CP_COMMIT();
    issue_B(0);
    CP_COMMIT();

    // ---- cat: slots 0-1 (x), 2-3 (z); z pairs prefetched into drained A chunks ----
    slot(0, 0, -1);
    slot(1, 1, 0);
    slot(2, 0, 1);
    slot(3, 1, -1);
    __syncthreads();
#pragma unroll
    for (int mi = 0; mi < 2; mi++)
#pragma unroll
        for (int ni = 0; ni < 8; ni++) {
            int cg = wn0 + ni * 8 + tc2;
            float* d = acc[mi][ni];
            float a0 = bl[cg] + br[cg], a1 = bl[cg + 1] + br[cg + 1];
            d[0] += a0; d[1] += a1; d[2] += a0; d[3] += a1;
        }
    conv_img(); zero_acc();

    // ---- w1: slots 4-5 -> h0 (write himg) ----
    run2(4);
    __syncthreads();
#pragma unroll
    for (int mi = 0; mi < 2; mi++)
#pragma unroll
        for (int ni = 0; ni < 8; ni++) {
            int cg = wn0 + ni * 8 + tc2;
            float* d = acc[mi][ni];
            d[0] += b1[cg]; d[1] += b1[cg + 1]; d[2] += b1[cg]; d[3] += b1[cg + 1];
            int ra = bm0 + wm0 + mi * 16 + tr;
            img_write2(himg_hi, himg_lo, cg >> 6, ra, cg & 63, d[0], d[1]);
            img_write2(himg_hi, himg_lo, cg >> 6, ra + 8, cg & 63, d[2], d[3]);
        }
    conv_img(); zero_acc();

    // ---- blocks: wa j: 6+4j, wb j: 8+4j ----
#pragma unroll 1
    for (int j = 0; j < 2; j++) {
        const float* ba = j ? ba1 : ba0;
        const float* gg = j ? g1 : g0;
        const float* be = j ? be1 : be0;
        const float* bb = j ? bb1 : bb0;
        run2(6 + j * 4);
        __syncthreads();
#pragma unroll
        for (int mi = 0; mi < 2; mi++)
#pragma unroll
            for (int ni = 0; ni < 8; ni++) {
                int cg = wn0 + ni * 8 + tc2;
                float* d = acc[mi][ni];
                float ga = gg[cg], gb = gg[cg + 1], ea = be[cg], eb = be[cg + 1];
                float a0 = ba[cg], a1 = ba[cg + 1];
                d[0] = fmaf(ga, fmaxf(d[0] + a0, 0.f) * bnscale, ea);
                d[1] = fmaf(gb, fmaxf(d[1] + a1, 0.f) * bnscale, eb);
                d[2] = fmaf(ga, fmaxf(d[2] + a0, 0.f) * bnscale, ea);
                d[3] = fmaf(gb, fmaxf(d[3] + a1, 0.f) * bnscale, eb);
            }
        conv_img(); zero_acc();
        run2(8 + j * 4);
        __syncthreads();
#pragma unroll
        for (int mi = 0; mi < 2; mi++)
#pragma unroll
            for (int ni = 0; ni < 8; ni++) {
                int cg = wn0 + ni * 8 + tc2;
                float* d = acc[mi][ni];
                int ra = bm0 + wm0 + mi * 16 + tr;
                float2 ha = img_read2(himg_hi, himg_lo, cg >> 6, ra, cg & 63);
                float2 hb = img_read2(himg_hi, himg_lo, cg >> 6, ra + 8, cg & 63);
                d[0] += bb[cg] + ha.x; d[1] += bb[cg + 1] + ha.y;
                d[2] += bb[cg] + hb.x; d[3] += bb[cg + 1] + hb.y;
                if (j == 0) {
                    img_write2(himg_hi, himg_lo, cg >> 6, ra, cg & 63, d[0], d[1]);
                    img_write2(himg_hi, himg_lo, cg >> 6, ra + 8, cg & 63, d[2], d[3]);
                }
            }
        conv_img(); zero_acc();
    }

    // ---- w2: slots 14-15, normalize + relu ----
    run2(14);
    __syncthreads();
#pragma unroll
    for (int mi = 0; mi < 2; mi++)
#pragma unroll
        for (int ni = 0; ni < 8; ni++) {
            int cg = wn0 + ni * 8 + tc2;
            float* d = acc[mi][ni];
            d[0] += b2[cg]; d[1] += b2[cg + 1]; d[2] += b2[cg]; d[3] += b2[cg + 1];
        }
    {
        float* rsum = (float*)(smem + RSUM_OFF);
        float ps[2][2] = {{0.f, 0.f}, {0.f, 0.f}};
#pragma unroll
        for (int mi = 0; mi < 2; mi++)
#pragma unroll
            for (int ni = 0; ni < 8; ni++) {
                float* d = acc[mi][ni];
                ps[mi][0] = fmaf(d[0], d[0], fmaf(d[1], d[1], ps[mi][0]));
                ps[mi][1] = fmaf(d[2], d[2], fmaf(d[3], d[3], ps[mi][1]));
            }
#pragma unroll
        for (int mi = 0; mi < 2; mi++)
#pragma unroll
            for (int q = 0; q < 2; q++) {
                ps[mi][q] += __shfl_xor_sync(0xffffffffu, ps[mi][q], 1);
                ps[mi][q] += __shfl_xor_sync(0xffffffffu, ps[mi][q], 2);
            }
        if ((lane & 3) == 0) {
            int cw = wn0 >> 6;
#pragma unroll
            for (int mi = 0; mi < 2; mi++) {
                rsum[(wm0 + mi * 16 + tr) * 4 + cw] = ps[mi][0];
                rsum[(wm0 + mi * 16 + 8 + tr) * 4 + cw] = ps[mi][1];
            }
        }
        __syncthreads();
#pragma unroll
        for (int mi = 0; mi < 2; mi++) {
            int r0 = wm0 + mi * 16 + tr;
            int r1 = r0 + 8;
            float s0 = rsum[r0 * 4] + rsum[r0 * 4 + 1] + rsum[r0 * 4 + 2] + rsum[r0 * 4 + 3];
            float s1 = rsum[r1 * 4] + rsum[r1 * 4 + 1] + rsum[r1 * 4 + 2] + rsum[r1 * 4 + 3];
            float c0 = 1.f / fmaxf(sqrtf(s0), 1e-12f);
            float c1 = 1.f / fmaxf(sqrtf(s1), 1e-12f);
#pragma unroll
            for (int ni = 0; ni < 8; ni++) {
                float* d = acc[mi][ni];
                d[0] = fmaxf(d[0] * c0, 0.f); d[1] = fmaxf(d[1] * c0, 0.f);
                d[2] = fmaxf(d[2] * c1, 0.f); d[3] = fmaxf(d[3] * c1, 0.f);
            }
        }
    }
    if (!haspost) {
#pragma unroll
        for (int mi = 0; mi < 2; mi++)
#pragma unroll
            for (int ni = 0; ni < 8; ni++) {
                int cg = wn0 + ni * 8 + tc2;
                int ra = bm0 + wm0 + mi * 16 + tr;
                float* d = acc[mi][ni];
                img_write_hi(ximg_hi, cg >> 6, ra, cg & 63, d[0], d[1]);
                img_write_hi(ximg_hi, cg >> 6, ra + 8, cg & 63, d[2], d[3]);
            }
        return;
    }
    // ---- post stage (layer 3 only): x -> A image, slots 16-17, pp = x@postW1 + b ----
    conv_img(); zero_acc();
    run2(16);
    __syncthreads();
#pragma unroll
    for (int mi = 0; mi < 2; mi++)
#pragma unroll
        for (int ni = 0; ni < 8; ni++) {
            int cg = wn0 + ni * 8 + tc2;
            int ra = bm0 + wm0 + mi * 16 + tr;
            int rb = ra + 8;
            float* d = acc[mi][ni];
            float v0 = d[0] + postb[cg], v1 = d[1] + postb[cg + 1];
            float v2 = d[2] + postb[cg], v3 = d[3] + postb[cg + 1];
            if (ra < NN) *(float2*)(pp + (size_t)ra * 256 + cg) = make_float2(v0, v1);
            if (rb < NN) *(float2*)(pp + (size_t)rb * 256 + cg) = make_float2(v2, v3);
        }
}

// ---------------- head: logits [256->47] + log_softmax ----------------
__global__ void head_kernel(const float* __restrict__ h, const float* __restrict__ W2,
                            const float* __restrict__ b2, float* __restrict__ out) {
    __shared__ float sW[256 * NCLS];
    __shared__ float sb[NCLS];
    int tid = threadIdx.x;
    for (int i = tid; i < 256 * NCLS; i += 256) sW[i] = W2[i];
    if (tid < NCLS) sb[tid] = b2[tid];
    __syncthreads();

    int wid = tid >> 5, lane = tid & 31;
    int r = blockIdx.x * 8 + wid;
    if (r >= NN) return;

    const float4* rp = (const float4*)(h + (size_t)r * DD);
    float4 q0 = rp[lane * 2];
    float4 q1 = rp[lane * 2 + 1];
    float hreg[8] = {q0.x, q0.y, q0.z, q0.w, q1.x, q1.y, q1.z, q1.w};

    int c0 = lane;
    int c1 = lane + 32;
    int c1m = (c1 < NCLS) ? c1 : (NCLS - 1);
    float acc0 = sb[c0];
    float acc1 = sb[c1m];
#pragma unroll
    for (int e = 0; e < 8; e++) {
        for (int l = 0; l < 32; l++) {
            float hv = __shfl_sync(0xffffffffu, hreg[e], l);
            int k = l * 8 + e;
            acc0 = fmaf(hv, sW[k * NCLS + c0], acc0);
            acc1 = fmaf(hv, sW[k * NCLS + c1m], acc1);
        }
    }
    float m = fmaxf(acc0, (c1 < NCLS) ? acc1 : -3.4e38f);
#pragma unroll
    for (int o = 16; o > 0; o >>= 1) m = fmaxf(m, __shfl_xor_sync(0xffffffffu, m, o));
    float es = expf(acc0 - m) + ((c1 < NCLS) ? expf(acc1 - m) : 0.f);
#pragma unroll
    for (int o = 16; o > 0; o >>= 1) es += __shfl_xor_sync(0xffffffffu, es, o);
    float lse = m + logf(es);
    out[(size_t)r * NCLS + c0] = acc0 - lse;
    if (c1 < NCLS) out[(size_t)r * NCLS + c1] = acc1 - lse;
}

// ---------------- host orchestration ----------------
extern "C" void kernel_launch(void* const* d_in, const int* in_sizes, int n_in,
                              void* d_out, int out_size) {
    const float* x_in      = (const float*)d_in[0];
    const int* ei          = (const int*)d_in[1];
    const float* lin_l_W   = (const float*)d_in[2];
    const float* lin_l_b   = (const float*)d_in[3];
    const float* lin_r_W   = (const float*)d_in[4];
    const float* lin_r_b   = (const float*)d_in[5];
    const float* mlp_W1    = (const float*)d_in[6];
    const float* mlp_b1    = (const float*)d_in[7];
    const float* blk_Wa    = (const float*)d_in[8];
    const float* blk_ba    = (const float*)d_in[9];
    const float* blk_gamma = (const float*)d_in[10];
    const float* blk_beta  = (const float*)d_in[11];
    const float* blk_Wb    = (const float*)d_in[12];
    const float* blk_bb    = (const float*)d_in[13];
    const float* mlp_W2    = (const float*)d_in[14];
    const float* mlp_b2    = (const float*)d_in[15];
    const float* post_W1   = (const float*)d_in[16];
    const float* post_b1   = (const float*)d_in[17];
    const float* post_W2   = (const float*)d_in[18];
    const float* post_b2   = (const float*)d_in[19];
    float* out = (float*)d_out;

    float* pp;
    uint4* whi;
    unsigned *xih, *zih, *hih, *hil;
    int *cnti, *offp, *curp, *csrp;
    cudaGetSymbolAddress((void**)&pp, g_p);
    cudaGetSymbolAddress((void**)&whi, g_whi4);
    cudaGetSymbolAddress((void**)&xih, g_ximg_hi);
    cudaGetSymbolAddress((void**)&zih, g_zimg_hi);
    cudaGetSymbolAddress((void**)&hih, g_himg_hi);
    cudaGetSymbolAddress((void**)&hil, g_himg_lo);
    cudaGetSymbolAddress((void**)&cnti, g_cnti);
    cudaGetSymbolAddress((void**)&offp, g_off);
    cudaGetSymbolAddress((void**)&curp, g_cur);
    cudaGetSymbolAddress((void**)&csrp, g_csr);

    cudaFuncSetAttribute(fused_layer, cudaFuncAttributeMaxDynamicSharedMemorySize, FSMEM);

    const float bnscale = rsqrtf(1.0f + 1e-5f);
    const int* src = ei;
    const int* dst = ei + EE;

    // 1: setup (weights + x image)
    setup_kernel<<<31400, 256>>>(lin_l_W, lin_r_W, mlp_W1, blk_Wa, blk_Wb, mlp_W2, post_W1,
                                 x_in, (unsigned short*)whi, xih);
    // 2: CSR (count+scan+fill, one persistent kernel)
    csr_kernel<<<CSRB, 256>>>(src, dst, cnti, offp, curp, csrp);

    for (int i = 0; i < NLAYER; i++) {
        // 3: gather (hi only, 8-wide)
        gather_img<<<(NN + 1) / 2, 256>>>(xih, offp, csrp, zih);

        SlotTab tab;
        int s = 0;
        auto push = [&](int base) {   // one 256x256 matrix = 2 slots of 64KB
            tab.p[s++] = whi + (size_t)base * 2048;
            tab.p[s++] = whi + (size_t)(base + 2) * 2048;
        };
        push(i * 8);                 // cat-x (lin_l)           slots 0-1
        push(i * 8 + 4);             // cat-z (lin_r)           slots 2-3
        push(24 + i * 4);            // w1                      slots 4-5
        push(36 + (2 * i) * 4);      // wa0                     slots 6-7
        push(60 + (2 * i) * 4);      // wb0                     slots 8-9
        push(36 + (2 * i + 1) * 4);  // wa1                     slots 10-11
        push(60 + (2 * i + 1) * 4);  // wb1                     slots 12-13
        push(84 + i * 4);            // w2                      slots 14-15
        int nslots = 16;
        if (i == NLAYER - 1) { push(96); nslots = 18; }  // post slots 16-17

        size_t bo0 = ((size_t)i * 2) * 256, bo1 = ((size_t)i * 2 + 1) * 256;
        // 4: fused layer  <-- profiled launch
        fused_layer<<<NB, 512, FSMEM>>>(
            xih, zih, tab, nslots,
            lin_l_b + (size_t)i * 256, lin_r_b + (size_t)i * 256,
            mlp_b1 + (size_t)i * 256,
            blk_ba + bo0, blk_gamma + bo0, blk_beta + bo0, blk_bb + bo0,
            blk_ba + bo1, blk_gamma + bo1, blk_beta + bo1, blk_bb + bo1,
            mlp_b2 + (size_t)i * 256, post_b1, bnscale,
            hih, hil, pp);
    }

    head_kernel<<<(NN + 7) / 8, 256>>>(pp, post_W2, post_b2, out);
}

// round 14
// speedup vs baseline: 4.7537x; 1.0568x over previous
#include <cuda_runtime.h>
#include <cuda_bf16.h>
#include <math.h>

#define NN 50000
#define ROWSP 50048
#define DD 256
#define EE 800000
#define NCLS 47
#define NLAYER 3
#define NB2 782
#define CSRB 148

#define SWZ(x) ((x) ^ (((x) >> 3) & 0x70))

// ---- fused kernel smem layout (per CTA, 2 CTAs/SM) ----
// A image: 4 chunks x 8KB (M64, hi only) @ 0..32768
// B ring:  2 slots x 32KB @ 32768..98304
// rsum:    512B @ 98304
#define FS_B 32768
#define RSUM_OFF 98304
#define FSMEM 98816

// ---------------- device scratch ----------------
__device__ float g_p[ROWSP * DD];
__device__ uint4 g_whi4[100 * 2048];
__device__ unsigned g_ximg_hi[4 * ROWSP * 32];
__device__ unsigned g_zimg_hi[4 * ROWSP * 32];
__device__ unsigned g_himg_hi[4 * ROWSP * 32];
__device__ unsigned g_himg_lo[4 * ROWSP * 32];
__device__ int g_cnti[NN];          // static zero-init; self-zeroed each run
__device__ int g_off[NN + 1];
__device__ int g_cur[NN];
__device__ int g_csr[EE];
__device__ int g_partial[CSRB];
__device__ int g_pscan[CSRB];
__device__ unsigned g_bar;

struct SlotTab { const uint4* p[36]; };

static __device__ __forceinline__ unsigned smem_u32(const void* p) {
    unsigned a;
    asm("{ .reg .u64 t; cvta.to.shared.u64 t, %1; cvt.u32.u64 %0, t; }" : "=r"(a) : "l"(p));
    return a;
}
static __device__ __forceinline__ void ldsm4(unsigned r[4], unsigned addr) {
    asm volatile("ldmatrix.sync.aligned.m8n8.x4.shared.b16 {%0,%1,%2,%3}, [%4];"
                 : "=r"(r[0]), "=r"(r[1]), "=r"(r[2]), "=r"(r[3]) : "r"(addr));
}
static __device__ __forceinline__ void mma16816(float d[4], const unsigned a[4],
                                                unsigned b0, unsigned b1) {
    asm volatile(
        "mma.sync.aligned.m16n8k16.row.col.f32.bf16.bf16.f32 "
        "{%0,%1,%2,%3}, {%4,%5,%6,%7}, {%8,%9}, {%0,%1,%2,%3};"
        : "+f"(d[0]), "+f"(d[1]), "+f"(d[2]), "+f"(d[3])
        : "r"(a[0]), "r"(a[1]), "r"(a[2]), "r"(a[3]), "r"(b0), "r"(b1));
}
#define CPA(dst, src) \
    asm volatile("cp.async.cg.shared.global [%0], [%1], 16;" :: "r"(dst), "l"(src) : "memory")
#define CP_COMMIT() asm volatile("cp.async.commit_group;" ::: "memory")
template <int N>
static __device__ __forceinline__ void cp_wait() {
    asm volatile("cp.async.wait_group %0;" :: "n"(N) : "memory");
}

static __device__ __forceinline__ void bsplit(float v, unsigned& h, unsigned& l) {
    __nv_bfloat16 hb = __float2bfloat16(v);
    h = __bfloat16_as_ushort(hb);
    l = __bfloat16_as_ushort(__float2bfloat16(v - __bfloat162float(hb)));
}
static __device__ __forceinline__ unsigned bhi(float v) {
    return (unsigned)__bfloat16_as_ushort(__float2bfloat16(v));
}
static __device__ __forceinline__ unsigned img_idx(int chunk, int row, int lc) {
    return ((unsigned)chunk * ROWSP + (unsigned)row) * 32u +
           ((((unsigned)(lc * 2)) ^ (((unsigned)row & 7u) << 4)) >> 2);
}
static __device__ __forceinline__ void img_write2(unsigned* __restrict__ hi,
                                                  unsigned* __restrict__ lo, int chunk,
                                                  int row, int lc, float v0, float v1) {
    unsigned h0, l0, h1, l1;
    bsplit(v0, h0, l0);
    bsplit(v1, h1, l1);
    unsigned idx = img_idx(chunk, row, lc);
    hi[idx] = h0 | (h1 << 16);
    lo[idx] = l0 | (l1 << 16);
}
static __device__ __forceinline__ void img_write_hi(unsigned* __restrict__ hi, int chunk,
                                                    int row, int lc, float v0, float v1) {
    hi[img_idx(chunk, row, lc)] = bhi(v0) | (bhi(v1) << 16);
}
static __device__ __forceinline__ float2 img_read2(const unsigned* __restrict__ hi,
                                                   const unsigned* __restrict__ lo, int chunk,
                                                   int row, int lc) {
    unsigned idx = img_idx(chunk, row, lc);
    unsigned h = hi[idx], l = lo[idx];
    float x0 = __bfloat162float(__ushort_as_bfloat16((unsigned short)(h & 0xffff))) +
               __bfloat162float(__ushort_as_bfloat16((unsigned short)(l & 0xffff)));
    float x1 = __bfloat162float(__ushort_as_bfloat16((unsigned short)(h >> 16))) +
               __bfloat162float(__ushort_as_bfloat16((unsigned short)(l >> 16)));
    return make_float2(x0, x1);
}

// ---------------- setup: weight prep + x image (ONE launch) ----------------
__global__ void setup_kernel(const float* __restrict__ linl, const float* __restrict__ linr,
                             const float* __restrict__ w1, const float* __restrict__ wa,
                             const float* __restrict__ wb, const float* __restrict__ w2,
                             const float* __restrict__ post, const float* __restrict__ X,
                             unsigned short* __restrict__ dhi,
                             unsigned* __restrict__ xih) {
    int b = blockIdx.x;
    if (b < 6400) {
        int idx = b * 256 + threadIdx.x;
        int m = idx >> 16;
        int rem = idx & 65535;
        int n = rem & 255, k = rem >> 8;
        const float* W;
        int chunk;
        if (m < 3)       { W = linl + (size_t)m * 65536;       chunk = 0  + m * 8 + (k >> 6); }
        else if (m < 6)  { W = linr + (size_t)(m - 3) * 65536; chunk = 4  + (m - 3) * 8 + (k >> 6); }
        else if (m < 9)  { W = w1 + (size_t)(m - 6) * 65536;   chunk = 24 + (m - 6) * 4 + (k >> 6); }
        else if (m < 15) { W = wa + (size_t)(m - 9) * 65536;   chunk = 36 + (m - 9) * 4 + (k >> 6); }
        else if (m < 21) { W = wb + (size_t)(m - 15) * 65536;  chunk = 60 + (m - 15) * 4 + (k >> 6); }
        else if (m < 24) { W = w2 + (size_t)(m - 21) * 65536;  chunk = 84 + (m - 21) * 4 + (k >> 6); }
        else             { W = post;                           chunk = 96 + (k >> 6); }
        float v = W[(size_t)k * 256 + n];
        unsigned off = (unsigned)chunk * 32768u + SWZ((unsigned)(n * 128 + (k & 63) * 2));
        dhi[off >> 1] = (unsigned short)bhi(v);
    } else {
        int idx = (b - 6400) * 256 + threadIdx.x;   // < NN*128 exactly
        int row = idx >> 7, p = idx & 127;
        float v0 = X[(size_t)row * 256 + p * 2];
        float v1 = X[(size_t)row * 256 + p * 2 + 1];
        img_write_hi(xih, (p * 2) >> 6, row, (p * 2) & 63, v0, v1);
    }
}

// ---------------- single-kernel CSR build (persistent grid + sw barrier) ----------------
static __device__ __forceinline__ void gridbar() {
    __syncthreads();
    __threadfence();
    if (threadIdx.x == 0) {
        unsigned arr = atomicAdd(&g_bar, 1u);
        unsigned target = (arr / CSRB + 1u) * CSRB;
        while (*(volatile unsigned*)&g_bar < target) { }
    }
    __syncthreads();
}

__global__ void csr_kernel(const int* __restrict__ src, const int* __restrict__ dst,
                           int* __restrict__ cnt, int* __restrict__ off,
                           int* __restrict__ cur, int* __restrict__ csr) {
    __shared__ int sdata[256];
    const int b = blockIdx.x, t = threadIdx.x;
    for (int e = b * 256 + t; e < EE; e += CSRB * 256)
        atomicAdd(&cnt[dst[e]], 1);
    gridbar();
    int n0 = (b * 256 + t) * 2;
    int c0 = (n0 < NN) ? cnt[n0] : 0;
    int c1 = (n0 + 1 < NN) ? cnt[n0 + 1] : 0;
    if (n0 < NN) cnt[n0] = 0;
    if (n0 + 1 < NN) cnt[n0 + 1] = 0;
    int ts = c0 + c1;
    sdata[t] = ts;
    __syncthreads();
#pragma unroll
    for (int o = 1; o < 256; o <<= 1) {
        int v = (t >= o) ? sdata[t - o] : 0;
        __syncthreads();
        sdata[t] += v;
        __syncthreads();
    }
    int bexcl = sdata[t] - ts;
    if (t == 255) g_partial[b] = sdata[t];
    gridbar();
    if (b == 0) {
        int v = (t < CSRB) ? g_partial[t] : 0;
        sdata[t] = v;
        __syncthreads();
#pragma unroll
        for (int o = 1; o < 256; o <<= 1) {
            int w = (t >= o) ? sdata[t - o] : 0;
            __syncthreads();
            sdata[t] += w;
            __syncthreads();
        }
        if (t < CSRB) g_pscan[t] = sdata[t] - v;
        if (t == 0) off[0] = 0;
    }
    gridbar();
    int base = g_pscan[b] + bexcl;
    if (n0 < NN) {
        cur[n0] = base;
        off[n0 + 1] = base + c0;
        if (n0 + 1 < NN) {
            cur[n0 + 1] = base + c0;
            if (n0 + 2 <= NN) off[n0 + 2] = base + c0 + c1;
        }
    }
    gridbar();
    for (int e = b * 256 + t; e < EE; e += CSRB * 256) {
        int p = atomicAdd(&cur[dst[e]], 1);
        csr[p] = src[e];
    }
}

// ---------------- gather (hi-only, 8-wide MLP) ----------------
__global__ void gather_img(const unsigned* __restrict__ xih,
                           const int* __restrict__ off, const int* __restrict__ csr,
                           unsigned* __restrict__ zih) {
    int w = (blockIdx.x * 256 + threadIdx.x) >> 5;
    int d = w >> 2, c = w & 3;
    if (d >= NN) return;
    int lane = threadIdx.x & 31;
    int b = off[d], e = off[d + 1];
    const unsigned* __restrict__ base = xih + (size_t)c * ROWSP * 32u;
    float s0 = 0.f, s1 = 0.f;
    int j = b;
    for (; j + 8 <= e; j += 8) {
        int r[8];
#pragma unroll
        for (int q = 0; q < 8; q++) r[q] = __ldg(&csr[j + q]);
        unsigned v[8];
#pragma unroll
        for (int q = 0; q < 8; q++)
            v[q] = __ldg(&base[(unsigned)r[q] * 32u + ((unsigned)lane ^ (((unsigned)r[q] & 7u) << 2))]);
#pragma unroll
        for (int q = 0; q < 8; q++) {
            s0 += __bfloat162float(__ushort_as_bfloat16((unsigned short)(v[q] & 0xffff)));
            s1 += __bfloat162float(__ushort_as_bfloat16((unsigned short)(v[q] >> 16)));
        }
    }
    for (; j + 2 <= e; j += 2) {
        int r0 = __ldg(&csr[j]), r1 = __ldg(&csr[j + 1]);
        unsigned v0 = __ldg(&base[(unsigned)r0 * 32u + ((unsigned)lane ^ (((unsigned)r0 & 7u) << 2))]);
        unsigned v1 = __ldg(&base[(unsigned)r1 * 32u + ((unsigned)lane ^ (((unsigned)r1 & 7u) << 2))]);
        s0 += __bfloat162float(__ushort_as_bfloat16((unsigned short)(v0 & 0xffff))) +
              __bfloat162float(__ushort_as_bfloat16((unsigned short)(v1 & 0xffff)));
        s1 += __bfloat162float(__ushort_as_bfloat16((unsigned short)(v0 >> 16))) +
              __bfloat162float(__ushort_as_bfloat16((unsigned short)(v1 >> 16)));
    }
    if (j < e) {
        int r0 = __ldg(&csr[j]);
        unsigned v0 = __ldg(&base[(unsigned)r0 * 32u + ((unsigned)lane ^ (((unsigned)r0 & 7u) << 2))]);
        s0 += __bfloat162float(__ushort_as_bfloat16((unsigned short)(v0 & 0xffff)));
        s1 += __bfloat162float(__ushort_as_bfloat16((unsigned short)(v0 >> 16)));
    }
    float iv = 1.f / fmaxf((float)(e - b), 1.f);
    img_write_hi(zih, c, d, lane * 2, s0 * iv, s1 * iv);
}

// ---- M64 MMA micro-kernel: one 8KB A chunk (64 rows, k64) vs one 32KB B chunk ----
// warp tile 16(M) x 128(N): wm0 = (wid&3)*16, wn0 = (wid>>2)*128. acc[16][4].
static __device__ __forceinline__ void mma_chunk(unsigned abase, unsigned bbase,
                                                 float (&acc)[16][4], int wm0, int wn0,
                                                 int lane) {
    const int lrow = lane & 15;
    const int lk = (lane >> 4) * 8;
#pragma unroll
    for (int ks = 0; ks < 4; ks++) {
        const int k0 = ks * 16;
        unsigned ahi[4];
        {
            unsigned off = SWZ((unsigned)((wm0 + lrow) * 128 + (k0 + lk) * 2));
            ldsm4(ahi, abase + off);
        }
#pragma unroll
        for (int hp = 0; hp < 4; hp++) {
            unsigned bb[2][4];
#pragma unroll
            for (int q = 0; q < 2; q++) {
                int g = hp * 2 + q;
                unsigned off = SWZ((unsigned)((wn0 + g * 16 + lrow) * 128 + (k0 + lk) * 2));
                ldsm4(bb[q], bbase + off);
            }
#pragma unroll
            for (int q = 0; q < 2; q++)
#pragma unroll
                for (int r0 = 0; r0 < 2; r0++)
                    mma16816(acc[(hp * 2 + q) * 2 + r0], ahi, bb[q][r0], bb[q][r0 + 2]);
        }
    }
}

// ---------------- fused layer kernel (M64, 256 threads, 2 CTAs/SM) ----------------
// 32 K-64 slots (+4 post): stage st = s>>2, A chunk = s&3.
// Stage order: cat-x, cat-z, w1, wa0, wb0, wa1, wb1, w2 [, post]
__global__ void __launch_bounds__(256, 2)
fused_layer(unsigned* __restrict__ ximg_hi, const unsigned* __restrict__ zimg_hi,
            SlotTab tab, int nslots,
            const float* __restrict__ bl, const float* __restrict__ br,
            const float* __restrict__ b1,
            const float* __restrict__ ba0, const float* __restrict__ g0,
            const float* __restrict__ be0, const float* __restrict__ bb0,
            const float* __restrict__ ba1, const float* __restrict__ g1,
            const float* __restrict__ be1, const float* __restrict__ bb1,
            const float* __restrict__ b2, const float* __restrict__ postb, float bnscale,
            unsigned* __restrict__ himg_hi, unsigned* __restrict__ himg_lo,
            float* __restrict__ pp) {
    extern __shared__ char smem[];
    const unsigned sb = smem_u32(smem);
    const int tid = threadIdx.x, wid = tid >> 5, lane = tid & 31;
    const int bm0 = blockIdx.x * 64;
    const int wm0 = (wid & 3) * 16;
    const int wn0 = (wid >> 2) * 128;
    const int tr = lane >> 2;
    const int tc2 = (lane & 3) * 2;
    const bool haspost = (nslots > 32);

    float acc[16][4];
    auto zero_acc = [&]() {
#pragma unroll
        for (int a = 0; a < 16; a++)
#pragma unroll
            for (int c = 0; c < 4; c++) acc[a][c] = 0.f;
    };
    zero_acc();

    auto issue_B = [&](int s) {   // 32KB, no commit
        if (s >= nslots) return;
        const char* src = (const char*)tab.p[s];
        unsigned dstb = sb + FS_B + (unsigned)(s & 1) * 32768u;
#pragma unroll
        for (int i = 0; i < 8; i++) {
            int u = tid + i * 256;
            CPA(dstb + u * 16, src + u * 16);
        }
    };
    auto issue_z = [&](int c) {   // 8KB hi-only into A chunk c
        const char* gh = (const char*)(zimg_hi + ((size_t)c * ROWSP + bm0) * 32);
        unsigned cb = sb + (unsigned)c * 8192u;
#pragma unroll
        for (int i = 0; i < 2; i++) {
            int u = tid + i * 256;
            CPA(cb + u * 16, gh + u * 16);
        }
    };
    auto slot = [&](int s, int ah, int zc) {
        cp_wait<0>();
        __syncthreads();
        issue_B(s + 1);
        if (zc >= 0) issue_z(zc);
        CP_COMMIT();
        mma_chunk(sb + (unsigned)ah * 8192u, sb + FS_B + (unsigned)(s & 1) * 32768u,
                  acc, wm0, wn0, lane);
    };
    auto run4 = [&](int s0) {
#pragma unroll 1
        for (int c = 0; c < 4; c++) slot(s0 + c, c, -1);
    };
    auto conv_img = [&]() {   // acc -> smem A image (hi only); caller syncs BEFORE
#pragma unroll
        for (int ni = 0; ni < 16; ni++) {
            int cg = wn0 + ni * 8 + tc2;
            unsigned cb = (unsigned)(cg >> 6) * 8192u;
            int lc = cg & 63;
            float* d = acc[ni];
            unsigned off = SWZ((unsigned)((wm0 + tr) * 128 + lc * 2));
            *(unsigned*)(smem + cb + off) = bhi(d[0]) | (bhi(d[1]) << 16);
            off = SWZ((unsigned)((wm0 + 8 + tr) * 128 + lc * 2));
            *(unsigned*)(smem + cb + off) = bhi(d[2]) | (bhi(d[3]) << 16);
        }
    };

    // ---- prologue: x image (hi only, 4x8KB) + B slot 0 ----
#pragma unroll
    for (int c = 0; c < 4; c++) {
        const char* gh = (const char*)(ximg_hi + ((size_t)c * ROWSP + bm0) * 32);
        unsigned cb = sb + (unsigned)c * 8192u;
#pragma unroll
        for (int i = 0; i < 2; i++) {
            int u = tid + i * 256;
            CPA(cb + u * 16, gh + u * 16);
        }
    }
    CP_COMMIT();
    issue_B(0);
    CP_COMMIT();

    // ---- cat: slots 0-3 (x), 4-7 (z); z chunk s-1 prefetched at slots 1..4 ----
#pragma unroll 1
    for (int s = 0; s < 8; s++)
        slot(s, s & 3, (s >= 1 && s <= 4) ? (s - 1) : -1);
    __syncthreads();
#pragma unroll
    for (int ni = 0; ni < 16; ni++) {
        int cg = wn0 + ni * 8 + tc2;
        float* d = acc[ni];
        float a0 = bl[cg] + br[cg], a1 = bl[cg + 1] + br[cg + 1];
        d[0] += a0; d[1] += a1; d[2] += a0; d[3] += a1;
    }
    conv_img(); zero_acc();

    // ---- w1: slots 8-11 -> h0 (write himg) ----
    run4(8);
    __syncthreads();
#pragma unroll
    for (int ni = 0; ni < 16; ni++) {
        int cg = wn0 + ni * 8 + tc2;
        float* d = acc[ni];
        d[0] += b1[cg]; d[1] += b1[cg + 1]; d[2] += b1[cg]; d[3] += b1[cg + 1];
        int ra = bm0 + wm0 + tr;
        img_write2(himg_hi, himg_lo, cg >> 6, ra, cg & 63, d[0], d[1]);
        img_write2(himg_hi, himg_lo, cg >> 6, ra + 8, cg & 63, d[2], d[3]);
    }
    conv_img(); zero_acc();

    // ---- blocks: wa j: 12+8j, wb j: 16+8j ----
#pragma unroll 1
    for (int j = 0; j < 2; j++) {
        const float* ba = j ? ba1 : ba0;
        const float* gg = j ? g1 : g0;
        const float* be = j ? be1 : be0;
        const float* bb = j ? bb1 : bb0;
        run4(12 + j * 8);
        __syncthreads();
#pragma unroll
        for (int ni = 0; ni < 16; ni++) {
            int cg = wn0 + ni * 8 + tc2;
            float* d = acc[ni];
            float ga = gg[cg], gb = gg[cg + 1], ea = be[cg], eb = be[cg + 1];
            float a0 = ba[cg], a1 = ba[cg + 1];
            d[0] = fmaf(ga, fmaxf(d[0] + a0, 0.f) * bnscale, ea);
            d[1] = fmaf(gb, fmaxf(d[1] + a1, 0.f) * bnscale, eb);
            d[2] = fmaf(ga, fmaxf(d[2] + a0, 0.f) * bnscale, ea);
            d[3] = fmaf(gb, fmaxf(d[3] + a1, 0.f) * bnscale, eb);
        }
        conv_img(); zero_acc();
        run4(16 + j * 8);
        __syncthreads();
#pragma unroll
        for (int ni = 0; ni < 16; ni++) {
            int cg = wn0 + ni * 8 + tc2;
            float* d = acc[ni];
            int ra = bm0 + wm0 + tr;
            float2 ha = img_read2(himg_hi, himg_lo, cg >> 6, ra, cg & 63);
            float2 hb = img_read2(himg_hi, himg_lo, cg >> 6, ra + 8, cg & 63);
            d[0] += bb[cg] + ha.x; d[1] += bb[cg + 1] + ha.y;
            d[2] += bb[cg] + hb.x; d[3] += bb[cg + 1] + hb.y;
            if (j == 0) {
                img_write2(himg_hi, himg_lo, cg >> 6, ra, cg & 63, d[0], d[1]);
                img_write2(himg_hi, himg_lo, cg >> 6, ra + 8, cg & 63, d[2], d[3]);
            }
        }
        conv_img(); zero_acc();
    }

    // ---- w2: slots 28-31, normalize + relu ----
    run4(28);
    __syncthreads();
#pragma unroll
    for (int ni = 0; ni < 16; ni++) {
        int cg = wn0 + ni * 8 + tc2;
        float* d = acc[ni];
        d[0] += b2[cg]; d[1] += b2[cg + 1]; d[2] += b2[cg]; d[3] += b2[cg + 1];
    }
    {
        float* rsum = (float*)(smem + RSUM_OFF);   // [64 rows][2 halves]
        float ps0 = 0.f, ps1 = 0.f;
#pragma unroll
        for (int ni = 0; ni < 16; ni++) {
            float* d = acc[ni];
            ps0 = fmaf(d[0], d[0], fmaf(d[1], d[1], ps0));
            ps1 = fmaf(d[2], d[2], fmaf(d[3], d[3], ps1));
        }
#pragma unroll
        for (int o = 1; o <= 2; o <<= 1) {
            ps0 += __shfl_xor_sync(0xffffffffu, ps0, o);
            ps1 += __shfl_xor_sync(0xffffffffu, ps1, o);
        }
        int half = wn0 >> 7;
        if ((lane & 3) == 0) {
            rsum[(wm0 + tr) * 2 + half] = ps0;
            rsum[(wm0 + 8 + tr) * 2 + half] = ps1;
        }
        __syncthreads();
        int r0 = wm0 + tr, r1 = r0 + 8;
        float s0 = rsum[r0 * 2] + rsum[r0 * 2 + 1];
        float s1 = rsum[r1 * 2] + rsum[r1 * 2 + 1];
        float c0 = 1.f / fmaxf(sqrtf(s0), 1e-12f);
        float c1 = 1.f / fmaxf(sqrtf(s1), 1e-12f);
#pragma unroll
        for (int ni = 0; ni < 16; ni++) {
            float* d = acc[ni];
            d[0] = fmaxf(d[0] * c0, 0.f); d[1] = fmaxf(d[1] * c0, 0.f);
            d[2] = fmaxf(d[2] * c1, 0.f); d[3] = fmaxf(d[3] * c1, 0.f);
        }
    }
    if (!haspost) {
#pragma unroll
        for (int ni = 0; ni < 16; ni++) {
            int cg = wn0 + ni * 8 + tc2;
            int ra = bm0 + wm0 + tr;
            float* d = acc[ni];
            img_write_hi(ximg_hi, cg >> 6, ra, cg & 63, d[0], d[1]);
            img_write_hi(ximg_hi, cg >> 6, ra + 8, cg & 63, d[2], d[3]);
        }
        return;
    }
    // ---- post stage (layer 3): x -> A image, slots 32-35, pp = x@postW1 + b ----
    conv_img(); zero_acc();
    __syncthreads();
    run4(32);
    __syncthreads();
#pragma unroll
    for (int ni = 0; ni < 16; ni++) {
        int cg = wn0 + ni * 8 + tc2;
        int ra = bm0 + wm0 + tr;
        int rb = ra + 8;
        float* d = acc[ni];
        float v0 = d[0] + postb[cg], v1 = d[1] + postb[cg + 1];
        float v2 = d[2] + postb[cg], v3 = d[3] + postb[cg + 1];
        if (ra < NN) *(float2*)(pp + (size_t)ra * 256 + cg) = make_float2(v0, v1);
        if (rb < NN) *(float2*)(pp + (size_t)rb * 256 + cg) = make_float2(v2, v3);
    }
}

// ---------------- head: logits [256->47] + log_softmax ----------------
__global__ void head_kernel(const float* __restrict__ h, const float* __restrict__ W2,
                            const float* __restrict__ b2, float* __restrict__ out) {
    __shared__ float sW[256 * NCLS];
    __shared__ float sb[NCLS];
    int tid = threadIdx.x;
    for (int i = tid; i < 256 * NCLS; i += 256) sW[i] = W2[i];
    if (tid < NCLS) sb[tid] = b2[tid];
    __syncthreads();

    int wid = tid >> 5, lane = tid & 31;
    int r = blockIdx.x * 8 + wid;
    if (r >= NN) return;

    const float4* rp = (const float4*)(h + (size_t)r * DD);
    float4 q0 = rp[lane * 2];
    float4 q1 = rp[lane * 2 + 1];
    float hreg[8] = {q0.x, q0.y, q0.z, q0.w, q1.x, q1.y, q1.z, q1.w};

    int c0 = lane;
    int c1 = lane + 32;
    int c1m = (c1 < NCLS) ? c1 : (NCLS - 1);
    float acc0 = sb[c0];
    float acc1 = sb[c1m];
#pragma unroll
    for (int e = 0; e < 8; e++) {
        for (int l = 0; l < 32; l++) {
            float hv = __shfl_sync(0xffffffffu, hreg[e], l);
            int k = l * 8 + e;
            acc0 = fmaf(hv, sW[k * NCLS + c0], acc0);
            acc1 = fmaf(hv, sW[k * NCLS + c1m], acc1);
        }
    }
    float m = fmaxf(acc0, (c1 < NCLS) ? acc1 : -3.4e38f);
#pragma unroll
    for (int o = 16; o > 0; o >>= 1) m = fmaxf(m, __shfl_xor_sync(0xffffffffu, m, o));
    float es = expf(acc0 - m) + ((c1 < NCLS) ? expf(acc1 - m) : 0.f);
#pragma unroll
    for (int o = 16; o > 0; o >>= 1) es += __shfl_xor_sync(0xffffffffu, es, o);
    float lse = m + logf(es);
    out[(size_t)r * NCLS + c0] = acc0 - lse;
    if (c1 < NCLS) out[(size_t)r * NCLS + c1] = acc1 - lse;
}

// ---------------- host orchestration ----------------
extern "C" void kernel_launch(void* const* d_in, const int* in_sizes, int n_in,
                              void* d_out, int out_size) {
    const float* x_in      = (const float*)d_in[0];
    const int* ei          = (const int*)d_in[1];
    const float* lin_l_W   = (const float*)d_in[2];
    const float* lin_l_b   = (const float*)d_in[3];
    const float* lin_r_W   = (const float*)d_in[4];
    const float* lin_r_b   = (const float*)d_in[5];
    const float* mlp_W1    = (const float*)d_in[6];
    const float* mlp_b1    = (const float*)d_in[7];
    const float* blk_Wa    = (const float*)d_in[8];
    const float* blk_ba    = (const float*)d_in[9];
    const float* blk_gamma = (const float*)d_in[10];
    const float* blk_beta  = (const float*)d_in[11];
    const float* blk_Wb    = (const float*)d_in[12];
    const float* blk_bb    = (const float*)d_in[13];
    const float* mlp_W2    = (const float*)d_in[14];
    const float* mlp_b2    = (const float*)d_in[15];
    const float* post_W1   = (const float*)d_in[16];
    const float* post_b1   = (const float*)d_in[17];
    const float* post_W2   = (const float*)d_in[18];
    const float* post_b2   = (const float*)d_in[19];
    float* out = (float*)d_out;

    float* pp;
    uint4* whi;
    unsigned *xih, *zih, *hih, *hil;
    int *cnti, *offp, *curp, *csrp;
    cudaGetSymbolAddress((void**)&pp, g_p);
    cudaGetSymbolAddress((void**)&whi, g_whi4);
    cudaGetSymbolAddress((void**)&xih, g_ximg_hi);
    cudaGetSymbolAddress((void**)&zih, g_zimg_hi);
    cudaGetSymbolAddress((void**)&hih, g_himg_hi);
    cudaGetSymbolAddress((void**)&hil, g_himg_lo);
    cudaGetSymbolAddress((void**)&cnti, g_cnti);
    cudaGetSymbolAddress((void**)&offp, g_off);
    cudaGetSymbolAddress((void**)&curp, g_cur);
    cudaGetSymbolAddress((void**)&csrp, g_csr);

    cudaFuncSetAttribute(fused_layer, cudaFuncAttributeMaxDynamicSharedMemorySize, FSMEM);

    const float bnscale = rsqrtf(1.0f + 1e-5f);
    const int* src = ei;
    const int* dst = ei + EE;

    // 1: setup (weights + x image)
    setup_kernel<<<31400, 256>>>(lin_l_W, lin_r_W, mlp_W1, blk_Wa, blk_Wb, mlp_W2, post_W1,
                                 x_in, (unsigned short*)whi, xih);
    // 2: CSR (count+scan+fill, one persistent kernel)
    csr_kernel<<<CSRB, 256>>>(src, dst, cnti, offp, curp, csrp);

    for (int i = 0; i < NLAYER; i++) {
        // 3: gather (hi only, 8-wide)
        gather_img<<<(NN + 1) / 2, 256>>>(xih, offp, csrp, zih);

        SlotTab tab;
        int s = 0;
        auto push = [&](int base) {   // one 256x256 matrix = 4 slots of 32KB
            for (int c = 0; c < 4; c++) tab.p[s++] = whi + (size_t)(base + c) * 2048;
        };
        push(i * 8);                 // cat-x (lin_l)           slots 0-3
        push(i * 8 + 4);             // cat-z (lin_r)           slots 4-7
        push(24 + i * 4);            // w1                      slots 8-11
        push(36 + (2 * i) * 4);      // wa0                     slots 12-15
        push(60 + (2 * i) * 4);      // wb0                     slots 16-19
        push(36 + (2 * i + 1) * 4);  // wa1                     slots 20-23
        push(60 + (2 * i + 1) * 4);  // wb1                     slots 24-27
        push(84 + i * 4);            // w2                      slots 28-31
        int nslots = 32;
        if (i == NLAYER - 1) { push(96); nslots = 36; }  // post slots 32-35

        size_t bo0 = ((size_t)i * 2) * 256, bo1 = ((size_t)i * 2 + 1) * 256;
        // 4: fused layer  <-- profiled launch
        fused_layer<<<NB2, 256, FSMEM>>>(
            xih, zih, tab, nslots,
            lin_l_b + (size_t)i * 256, lin_r_b + (size_t)i * 256,
            mlp_b1 + (size_t)i * 256,
            blk_ba + bo0, blk_gamma + bo0, blk_beta + bo0, blk_bb + bo0,
            blk_ba + bo1, blk_gamma + bo1, blk_beta + bo1, blk_bb + bo1,
            mlp_b2 + (size_t)i * 256, post_b1, bnscale,
            hih, hil, pp);
    }

    head_kernel<<<(NN + 7) / 8, 256>>>(pp, post_W2, post_b2, out);
}